// round 1
// baseline (speedup 1.0000x reference)
#include <cuda_runtime.h>
#include <math.h>

#define BB 2
#define SS 2048
#define DD 768
#define HH 12
#define DKK 64
#define DFF 3072
#define MROWS (BB*SS)   // 4096

// ---------------- scratch (device globals; no allocation allowed) ----------
__device__ float g_Wq[DD*DD];
__device__ float g_Wk[DD*DD];
__device__ float g_Wv[DD*DD];
__device__ float g_q[BB*HH*SS*DKK];
__device__ float g_k[BB*HH*SS*DKK];
__device__ float g_v[BB*HH*SS*DKK];
__device__ float g_ctx[MROWS*DD];
__device__ float g_y[MROWS*DD];    // attn_out + src (pre-LN1)
__device__ float g_x[MROWS*DD];    // post-LN1
__device__ float g_ff[MROWS*DFF];  // relu(x@W1+b1)
__device__ float g_y2[MROWS*DD];   // x + ff (pre-LN2)

// ---------------- repack per-head weights [H,D,DK] -> [D, H*DK] ------------
__global__ void repack_qkv(const float* __restrict__ Wq,
                           const float* __restrict__ Wk,
                           const float* __restrict__ Wv) {
    int idx = blockIdx.x * blockDim.x + threadIdx.x;
    if (idx >= DD*DD) return;
    int d = idx / DD;
    int c = idx % DD;          // c = h*64 + dk
    int h = c >> 6, dk = c & 63;
    int s = (h*DD + d)*DKK + dk;
    g_Wq[idx] = Wq[s];
    g_Wk[idx] = Wk[s];
    g_Wv[idx] = Wv[s];
}

// ---------------- tiled fp32 GEMM: C = A[M,K] @ B[K,N] + epilogue ----------
// MODE 0: C = acc + bias[col]
// MODE 1: C = acc + bias[col] + res[row*N+col]
// MODE 2: C = relu(acc + bias[col])
// MODE 3: QKV scatter: write to [B,H,S,DK] layout with bias
template<int MODE>
__global__ __launch_bounds__(256)
void gemm_k(const float* __restrict__ A, const float* __restrict__ Bm,
            const float* __restrict__ bias, const float* __restrict__ res,
            float* __restrict__ C, int M, int N, int K)
{
    __shared__ float As[16][64];
    __shared__ float Bs[16][64];
    const int t = threadIdx.x;                 // 0..255
    const int rowBase = blockIdx.y * 64;
    const int colBase = blockIdx.x * 64;
    const int ty = t >> 4, tx = t & 15;

    // load mappings
    const int am = t >> 2;             // 0..63
    const int ak = (t & 3) * 4;        // 0,4,8,12
    const int bk = t >> 4;             // 0..15
    const int bn = (t & 15) * 4;       // 0..60

    float acc[4][4] = {};

    for (int k0 = 0; k0 < K; k0 += 16) {
        float4 a4 = *(const float4*)&A[(size_t)(rowBase + am) * K + k0 + ak];
        As[ak+0][am] = a4.x; As[ak+1][am] = a4.y;
        As[ak+2][am] = a4.z; As[ak+3][am] = a4.w;
        *(float4*)&Bs[bk][bn] = *(const float4*)&Bm[(size_t)(k0 + bk) * N + colBase + bn];
        __syncthreads();
        #pragma unroll
        for (int kk = 0; kk < 16; kk++) {
            float ar[4], br[4];
            #pragma unroll
            for (int i = 0; i < 4; i++) ar[i] = As[kk][ty*4 + i];
            #pragma unroll
            for (int j = 0; j < 4; j++) br[j] = Bs[kk][tx*4 + j];
            #pragma unroll
            for (int i = 0; i < 4; i++)
                #pragma unroll
                for (int j = 0; j < 4; j++)
                    acc[i][j] += ar[i] * br[j];
        }
        __syncthreads();
    }

    #pragma unroll
    for (int i = 0; i < 4; i++) {
        int row = rowBase + ty*4 + i;
        #pragma unroll
        for (int j = 0; j < 4; j++) {
            int col = colBase + tx*4 + j;
            float v = acc[i][j] + bias[col];
            if (MODE == 1) v += res[(size_t)row * N + col];
            if (MODE == 2) v = fmaxf(v, 0.0f);
            if (MODE == 3) {
                int b = row >> 11, s = row & 2047;
                int h = col >> 6,  dk = col & 63;
                C[((((size_t)b*HH + h)*SS) + s)*DKK + dk] = v;
            } else {
                C[(size_t)row * N + col] = v;
            }
        }
    }
}

// ---------------- flash attention -----------------------------------------
// grid = (S/64, H, B), block = 64 threads (1 query per thread)
__global__ __launch_bounds__(64)
void attn_k()
{
    const int qt = blockIdx.x, h = blockIdx.y, b = blockIdx.z;
    const int tid = threadIdx.x;
    const int TK = 32;

    __shared__ float Ksh[TK][DKK];
    __shared__ float Vsh[TK][DKK];
    __shared__ float Ssh[TK][64];

    const float* qp    = g_q + ((((size_t)b*HH + h)*SS) + qt*64 + tid)*DKK;
    const float* kbase = g_k + (((size_t)b*HH + h)*SS)*DKK;
    const float* vbase = g_v + (((size_t)b*HH + h)*SS)*DKK;

    float qreg[DKK], acc[DKK];
    #pragma unroll
    for (int d = 0; d < DKK; d++) { qreg[d] = qp[d] * 0.125f; acc[d] = 0.0f; }

    float m = -1e30f, l = 0.0f;

    const int lr = tid >> 1;          // 0..31 (key row)
    const int lc = (tid & 1) * 32;    // half-row offset

    for (int t0 = 0; t0 < SS; t0 += TK) {
        const float4* ksrc = (const float4*)(kbase + (size_t)(t0 + lr)*DKK + lc);
        const float4* vsrc = (const float4*)(vbase + (size_t)(t0 + lr)*DKK + lc);
        float4* kdst = (float4*)&Ksh[lr][lc];
        float4* vdst = (float4*)&Vsh[lr][lc];
        #pragma unroll
        for (int i = 0; i < 8; i++) { kdst[i] = ksrc[i]; vdst[i] = vsrc[i]; }
        __syncthreads();

        float tmax = -1e30f;
        #pragma unroll 4
        for (int j = 0; j < TK; j++) {
            float s = 0.0f;
            #pragma unroll
            for (int d = 0; d < DKK; d++) s += qreg[d] * Ksh[j][d];
            Ssh[j][tid] = s;
            tmax = fmaxf(tmax, s);
        }

        float mnew = fmaxf(m, tmax);
        float corr = __expf(m - mnew);
        l *= corr;
        #pragma unroll
        for (int d = 0; d < DKK; d++) acc[d] *= corr;

        #pragma unroll 4
        for (int j = 0; j < TK; j++) {
            float p = __expf(Ssh[j][tid] - mnew);
            l += p;
            #pragma unroll
            for (int d = 0; d < DKK; d++) acc[d] += p * Vsh[j][d];
        }
        m = mnew;
        __syncthreads();
    }

    const float inv = 1.0f / l;
    const size_t row = (size_t)b*SS + qt*64 + tid;
    #pragma unroll
    for (int d = 0; d < DKK; d++)
        g_ctx[row*DD + h*DKK + d] = acc[d] * inv;
}

// ---------------- LayerNorm -----------------------------------------------
// one block (256 threads) per row of D=768
__global__ __launch_bounds__(256)
void ln_k(const float* __restrict__ in, const float* __restrict__ w,
          const float* __restrict__ bsh, float* __restrict__ out)
{
    const size_t row = blockIdx.x;
    const float* x = in + row * DD;
    float s = 0.0f, s2 = 0.0f;
    for (int i = threadIdx.x; i < DD; i += 256) {
        float v = x[i]; s += v; s2 += v * v;
    }
    #pragma unroll
    for (int o = 16; o > 0; o >>= 1) {
        s  += __shfl_xor_sync(0xFFFFFFFFu, s,  o);
        s2 += __shfl_xor_sync(0xFFFFFFFFu, s2, o);
    }
    __shared__ float ws[8], ws2[8];
    const int wid = threadIdx.x >> 5, lane = threadIdx.x & 31;
    if (lane == 0) { ws[wid] = s; ws2[wid] = s2; }
    __syncthreads();
    float ts = 0.0f, ts2 = 0.0f;
    #pragma unroll
    for (int i = 0; i < 8; i++) { ts += ws[i]; ts2 += ws2[i]; }
    const float mu   = ts  * (1.0f / DD);
    const float var  = ts2 * (1.0f / DD) - mu * mu;
    const float rstd = rsqrtf(var + 1e-5f);
    for (int i = threadIdx.x; i < DD; i += 256)
        out[row * DD + i] = (x[i] - mu) * rstd * w[i] + bsh[i];
}

// ---------------- launch ----------------------------------------------------
template<typename T>
static float* sym_addr(T& sym) {
    void* p = nullptr;
    cudaGetSymbolAddress(&p, sym);
    return (float*)p;
}

extern "C" void kernel_launch(void* const* d_in, const int* in_sizes, int n_in,
                              void* d_out, int out_size)
{
    const float* src  = (const float*)d_in[0];
    const float* Wq   = (const float*)d_in[1];
    const float* bq   = (const float*)d_in[2];
    const float* Wk   = (const float*)d_in[3];
    const float* bk   = (const float*)d_in[4];
    const float* Wv   = (const float*)d_in[5];
    const float* bv   = (const float*)d_in[6];
    const float* Wo   = (const float*)d_in[7];
    const float* bo   = (const float*)d_in[8];
    const float* ln1w = (const float*)d_in[9];
    const float* ln1b = (const float*)d_in[10];
    const float* W1   = (const float*)d_in[11];
    const float* b1   = (const float*)d_in[12];
    const float* W2   = (const float*)d_in[13];
    const float* b2   = (const float*)d_in[14];
    const float* ln2w = (const float*)d_in[15];
    const float* ln2b = (const float*)d_in[16];
    float* out = (float*)d_out;

    float* pWq  = sym_addr(g_Wq);
    float* pWk  = sym_addr(g_Wk);
    float* pWv  = sym_addr(g_Wv);
    float* pq   = sym_addr(g_q);
    float* pk   = sym_addr(g_k);
    float* pv   = sym_addr(g_v);
    float* pctx = sym_addr(g_ctx);
    float* py   = sym_addr(g_y);
    float* px   = sym_addr(g_x);
    float* pff  = sym_addr(g_ff);
    float* py2  = sym_addr(g_y2);

    // 1) repack per-head projection weights
    repack_qkv<<<(DD*DD + 255)/256, 256>>>(Wq, Wk, Wv);

    // 2) QKV projections (scatter into [B,H,S,DK])
    dim3 gQKV(DD/64, MROWS/64);
    gemm_k<3><<<gQKV, 256>>>(src, pWq, bq, nullptr, pq, MROWS, DD, DD);
    gemm_k<3><<<gQKV, 256>>>(src, pWk, bk, nullptr, pk, MROWS, DD, DD);
    gemm_k<3><<<gQKV, 256>>>(src, pWv, bv, nullptr, pv, MROWS, DD, DD);

    // 3) attention -> ctx [B,S,H*DK]
    attn_k<<<dim3(SS/64, HH, BB), 64>>>();

    // 4) output projection + residual(src) -> y ; LN1 -> x
    gemm_k<1><<<gQKV, 256>>>(pctx, Wo, bo, src, py, MROWS, DD, DD);
    ln_k<<<MROWS, 256>>>(py, ln1w, ln1b, px);

    // 5) FFN
    gemm_k<2><<<dim3(DFF/64, MROWS/64), 256>>>(px, W1, b1, nullptr, pff, MROWS, DFF, DD);
    gemm_k<1><<<gQKV, 256>>>(pff, W2, b2, px, py2, MROWS, DD, DFF);

    // 6) LN2 -> output
    ln_k<<<MROWS, 256>>>(py2, ln2w, ln2b, out);
}

// round 4
// speedup vs baseline: 1.3959x; 1.3959x over previous
#include <cuda_runtime.h>
#include <cuda_bf16.h>
#include <cstdint>
#include <math.h>

#define BB 2
#define SS 2048
#define DD 768
#define HH 12
#define DKK 64
#define DFF 3072
#define MROWS (BB*SS)   // 4096

// ======================= device scratch (no allocs allowed) ================
__device__ float g_q[BB*HH*SS*DKK];
__device__ float g_k[BB*HH*SS*DKK];
__device__ float g_v[BB*HH*SS*DKK];
__device__ float g_ctx[MROWS*DD];
__device__ float g_y[MROWS*DD];
__device__ float g_x[MROWS*DD];
__device__ float g_y2[MROWS*DD];
// bf16 hi/lo pairs
__device__ __nv_bfloat16 s_srch[MROWS*DD],  s_srcl[MROWS*DD];
__device__ __nv_bfloat16 s_ctxh[MROWS*DD],  s_ctxl[MROWS*DD];
__device__ __nv_bfloat16 s_xh[MROWS*DD],    s_xl[MROWS*DD];
__device__ __nv_bfloat16 s_ffh[MROWS*DFF],  s_ffl[MROWS*DFF];
__device__ __nv_bfloat16 w_qh[DD*DD], w_ql[DD*DD];
__device__ __nv_bfloat16 w_kh[DD*DD], w_kl[DD*DD];
__device__ __nv_bfloat16 w_vh[DD*DD], w_vl[DD*DD];
__device__ __nv_bfloat16 w_oh[DD*DD], w_ol[DD*DD];
__device__ __nv_bfloat16 w_1h[DFF*DD], w_1l[DFF*DD];
__device__ __nv_bfloat16 w_2h[DD*DFF], w_2l[DD*DFF];

// ======================= PTX helpers (stable ISA only; no tcgen05) =========
__device__ __forceinline__ uint32_t smem_u32(const void* p) {
    uint32_t a;
    asm("{ .reg .u64 t; cvta.to.shared.u64 t, %1; cvt.u32.u64 %0, t; }" : "=r"(a) : "l"(p));
    return a;
}
#define CP_ASYNC16(dst, src) \
    asm volatile("cp.async.cg.shared.global [%0], [%1], 16;" :: "r"(dst), "l"(src) : "memory")
#define CP_COMMIT() asm volatile("cp.async.commit_group;" ::: "memory")
#define CP_WAIT(n)  asm volatile("cp.async.wait_group %0;" :: "n"(n) : "memory")

__device__ __forceinline__ void ldm_x4(uint32_t* r, uint32_t addr) {
    asm volatile("ldmatrix.sync.aligned.m8n8.x4.shared.b16 {%0,%1,%2,%3}, [%4];"
        : "=r"(r[0]), "=r"(r[1]), "=r"(r[2]), "=r"(r[3]) : "r"(addr));
}
__device__ __forceinline__ void mma_bf16(float* c, const uint32_t* a, const uint32_t* b) {
    asm volatile("mma.sync.aligned.m16n8k16.row.col.f32.bf16.bf16.f32 "
        "{%0,%1,%2,%3}, {%4,%5,%6,%7}, {%8,%9}, {%0,%1,%2,%3};"
        : "+f"(c[0]), "+f"(c[1]), "+f"(c[2]), "+f"(c[3])
        : "r"(a[0]), "r"(a[1]), "r"(a[2]), "r"(a[3]), "r"(b[0]), "r"(b[1]));
}

// ======================= split-bf16 helpers ================================
__device__ __forceinline__ void split_bf16(float v, __nv_bfloat16& h, __nv_bfloat16& l) {
    h = __float2bfloat16(v);
    l = __float2bfloat16(v - __bfloat162float(h));
}

// ======================= conversion / repack kernels =======================
__global__ void cvt_pair(const float* __restrict__ in,
                         __nv_bfloat16* __restrict__ oh, __nv_bfloat16* __restrict__ ol, int n) {
    int i = blockIdx.x * 256 + threadIdx.x;
    if (i >= n) return;
    __nv_bfloat16 h, l; split_bf16(in[i], h, l);
    oh[i] = h; ol[i] = l;
}

// Wq/Wk/Wv [H,D,DK] -> [768 rows (h*64+dk), 768 cols (d)] split hi/lo
__global__ void repack_headw(const float* __restrict__ Wq, const float* __restrict__ Wk,
                             const float* __restrict__ Wv) {
    int idx = blockIdx.x * 256 + threadIdx.x;
    if (idx >= DD * DD) return;
    int n = idx / DD, d = idx % DD;
    int h = n >> 6, dk = n & 63;
    int s = (h * DD + d) * DKK + dk;
    __nv_bfloat16 hh, ll;
    split_bf16(Wq[s], hh, ll); w_qh[idx] = hh; w_ql[idx] = ll;
    split_bf16(Wk[s], hh, ll); w_kh[idx] = hh; w_kl[idx] = ll;
    split_bf16(Wv[s], hh, ll); w_vh[idx] = hh; w_vl[idx] = ll;
}

// W [K, N] row-major -> [N, K] split hi/lo
__global__ void repack_T(const float* __restrict__ W,
                         __nv_bfloat16* __restrict__ oh, __nv_bfloat16* __restrict__ ol,
                         int N, int K) {
    int idx = blockIdx.x * 256 + threadIdx.x;
    if (idx >= N * K) return;
    int n = idx / K, k = idx % K;
    __nv_bfloat16 h, l; split_bf16(W[(size_t)k * N + n], h, l);
    oh[idx] = h; ol[idx] = l;
}

// ======================= mma.sync split-bf16 GEMM ==========================
// C[M,N] = (Ah+Al)[M,K] @ (Bh+Bl)[N,K]^T  (split product, Al*Bl dropped)
// MODE 0: QKV scatter [B,H,S,DK] + bias
// MODE 1: C = acc + bias + res (fp32)
// MODE 2: relu(acc+bias) -> (Ch, Cl) bf16 split pair
static constexpr int RS    = 80;            // smem row stride (bytes) for 32 bf16 + pad
static constexpr int MATB  = 128 * RS;      // 10240 bytes per matrix tile
static constexpr int STG   = 4 * MATB;      // 40960 per stage (Ah,Al,Bh,Bl)
static constexpr int GSMEM = 2 * STG;       // 81920 double-buffered

template<int MODE>
__global__ void __launch_bounds__(256, 1) gemm_mma(
    const __nv_bfloat16* __restrict__ Ah, const __nv_bfloat16* __restrict__ Al,
    const __nv_bfloat16* __restrict__ Bh, const __nv_bfloat16* __restrict__ Bl,
    const float* __restrict__ bias, const float* __restrict__ res,
    float* __restrict__ C, __nv_bfloat16* __restrict__ Ch, __nv_bfloat16* __restrict__ Cl,
    int M, int N, int K)
{
    extern __shared__ char sb[];
    const uint32_t sbu = smem_u32(sb);
    const int tid  = threadIdx.x;
    const int wid  = tid >> 5;
    const int lane = tid & 31;
    const int wm   = wid & 3;        // 4 warps over M (32 rows each)
    const int wn   = wid >> 2;       // 2 warps over N (64 cols each)

    const int rowBase = blockIdx.y << 7;
    const int colBase = blockIdx.x << 7;
    const __nv_bfloat16* gA[2] = { Ah + (size_t)rowBase * K, Al + (size_t)rowBase * K };
    const __nv_bfloat16* gB[2] = { Bh + (size_t)colBase * K, Bl + (size_t)colBase * K };

    // per-thread cp.async slots: 8 x 16B; slot -> (matrix, row, quad)
    int ld_mat[8], ld_r[8], ld_q[8];
    #pragma unroll
    for (int i = 0; i < 8; i++) {
        int slot = (i << 8) + tid;        // 0..2047
        ld_mat[i] = slot >> 9;            // 0:Ah 1:Al 2:Bh 3:Bl
        int rem = slot & 511;
        ld_r[i] = rem >> 2;
        ld_q[i] = rem & 3;
    }

    auto load_stage = [&](int kc, int buf) {
        const uint32_t base = sbu + buf * STG;
        #pragma unroll
        for (int i = 0; i < 8; i++) {
            const __nv_bfloat16* src = (ld_mat[i] < 2 ? gA[ld_mat[i]] : gB[ld_mat[i] - 2])
                                       + (size_t)ld_r[i] * K + kc + (ld_q[i] << 3);
            uint32_t dst = base + ld_mat[i] * MATB + ld_r[i] * RS + (ld_q[i] << 4);
            CP_ASYNC16(dst, src);
        }
        CP_COMMIT();
    };

    float acc[2][8][4];
    #pragma unroll
    for (int mt = 0; mt < 2; mt++)
        #pragma unroll
        for (int nt = 0; nt < 8; nt++)
            #pragma unroll
            for (int j = 0; j < 4; j++) acc[mt][nt][j] = 0.0f;

    // ldmatrix per-lane addresses (relative to matrix tile base, ks=0)
    const uint32_t aAddr = (uint32_t)((wm * 32 + (lane & 15)) * RS + (lane >> 4) * 16);
    const uint32_t bAddr = (uint32_t)((wn * 64 + ((lane >> 4) << 3) + (lane & 7)) * RS
                                      + ((lane >> 3) & 1) * 16);

    const int nStages = K >> 5;
    load_stage(0, 0);

    for (int c = 0; c < nStages; c++) {
        if (c + 1 < nStages) load_stage((c + 1) << 5, (c + 1) & 1);
        if (c + 1 < nStages) { CP_WAIT(1); } else { CP_WAIT(0); }
        __syncthreads();

        const uint32_t base = sbu + (c & 1) * STG;
        #pragma unroll
        for (int ks = 0; ks < 2; ks++) {
            const uint32_t ko = ks * 32;
            uint32_t bh[16], bl[16];
            #pragma unroll
            for (int np = 0; np < 4; np++) {
                ldm_x4(bh + np * 4, base + 2 * MATB + bAddr + np * 16 * RS + ko);
                ldm_x4(bl + np * 4, base + 3 * MATB + bAddr + np * 16 * RS + ko);
            }
            #pragma unroll
            for (int mt = 0; mt < 2; mt++) {
                uint32_t ah[4], al[4];
                ldm_x4(ah, base + 0 * MATB + aAddr + mt * 16 * RS + ko);
                ldm_x4(al, base + 1 * MATB + aAddr + mt * 16 * RS + ko);
                #pragma unroll
                for (int nt = 0; nt < 8; nt++) {
                    mma_bf16(acc[mt][nt], ah, bh + nt * 2);
                    mma_bf16(acc[mt][nt], ah, bl + nt * 2);
                    mma_bf16(acc[mt][nt], al, bh + nt * 2);
                }
            }
        }
        __syncthreads();
    }

    // ---------------- epilogue ----------------
    const int g  = lane >> 2;          // 0..7
    const int tc = (lane & 3) << 1;    // 0,2,4,6

    #pragma unroll
    for (int mt = 0; mt < 2; mt++) {
        #pragma unroll
        for (int half = 0; half < 2; half++) {     // c0c1 (row g) / c2c3 (row g+8)
            const int orow = rowBase + wm * 32 + mt * 16 + g + half * 8;
            #pragma unroll
            for (int nt = 0; nt < 8; nt++) {
                const int col = colBase + wn * 64 + nt * 8 + tc;
                float v0 = acc[mt][nt][half * 2 + 0] + bias[col];
                float v1 = acc[mt][nt][half * 2 + 1] + bias[col + 1];
                if (MODE == 0) {
                    const int b = orow >> 11, s = orow & 2047;
                    const int h = col >> 6, dk = col & 63;
                    float2 v = make_float2(v0, v1);
                    *(float2*)(C + ((((size_t)b * HH + h) * SS + s) * DKK + dk)) = v;
                } else if (MODE == 1) {
                    const float* rp = res + (size_t)orow * N + col;
                    float2 rv = *(const float2*)rp;
                    *(float2*)(C + (size_t)orow * N + col) = make_float2(v0 + rv.x, v1 + rv.y);
                } else {
                    v0 = fmaxf(v0, 0.0f); v1 = fmaxf(v1, 0.0f);
                    __nv_bfloat16 h0, l0, h1, l1;
                    split_bf16(v0, h0, l0); split_bf16(v1, h1, l1);
                    uint32_t hw = ((uint32_t)__bfloat16_as_ushort(h1) << 16) | __bfloat16_as_ushort(h0);
                    uint32_t lw = ((uint32_t)__bfloat16_as_ushort(l1) << 16) | __bfloat16_as_ushort(l0);
                    *(uint32_t*)(Ch + (size_t)orow * N + col) = hw;
                    *(uint32_t*)(Cl + (size_t)orow * N + col) = lw;
                }
            }
        }
    }
}

// ======================= flash attention (fp32) ============================
__global__ __launch_bounds__(64)
void attn_k()
{
    const int qt = blockIdx.x, h = blockIdx.y, b = blockIdx.z;
    const int tid = threadIdx.x;
    const int TK = 32;

    __shared__ float Ksh[TK][DKK];
    __shared__ float Vsh[TK][DKK];
    __shared__ float Ssh[TK][64];

    const float* qp    = g_q + ((((size_t)b*HH + h)*SS) + qt*64 + tid)*DKK;
    const float* kbase = g_k + (((size_t)b*HH + h)*SS)*DKK;
    const float* vbase = g_v + (((size_t)b*HH + h)*SS)*DKK;

    float qreg[DKK], acc[DKK];
    #pragma unroll
    for (int d = 0; d < DKK; d++) { qreg[d] = qp[d] * 0.125f; acc[d] = 0.0f; }

    float m = -1e30f, l = 0.0f;

    const int lr = tid >> 1;
    const int lc = (tid & 1) * 32;

    for (int t0 = 0; t0 < SS; t0 += TK) {
        const float4* ksrc = (const float4*)(kbase + (size_t)(t0 + lr)*DKK + lc);
        const float4* vsrc = (const float4*)(vbase + (size_t)(t0 + lr)*DKK + lc);
        float4* kdst = (float4*)&Ksh[lr][lc];
        float4* vdst = (float4*)&Vsh[lr][lc];
        #pragma unroll
        for (int i = 0; i < 8; i++) { kdst[i] = ksrc[i]; vdst[i] = vsrc[i]; }
        __syncthreads();

        float tmax = -1e30f;
        #pragma unroll 4
        for (int j = 0; j < TK; j++) {
            float s = 0.0f;
            #pragma unroll
            for (int d = 0; d < DKK; d++) s += qreg[d] * Ksh[j][d];
            Ssh[j][tid] = s;
            tmax = fmaxf(tmax, s);
        }

        float mnew = fmaxf(m, tmax);
        float corr = __expf(m - mnew);
        l *= corr;
        #pragma unroll
        for (int d = 0; d < DKK; d++) acc[d] *= corr;

        #pragma unroll 4
        for (int j = 0; j < TK; j++) {
            float p = __expf(Ssh[j][tid] - mnew);
            l += p;
            #pragma unroll
            for (int d = 0; d < DKK; d++) acc[d] += p * Vsh[j][d];
        }
        m = mnew;
        __syncthreads();
    }

    const float inv = 1.0f / l;
    const size_t row = (size_t)b*SS + qt*64 + tid;
    #pragma unroll
    for (int d = 0; d < DKK; d++)
        g_ctx[row*DD + h*DKK + d] = acc[d] * inv;
}

// ======================= LayerNorm (optionally emits bf16 pair) ============
template<int WB>
__global__ __launch_bounds__(256)
void ln_k(const float* __restrict__ in, const float* __restrict__ w,
          const float* __restrict__ bsh, float* __restrict__ out,
          __nv_bfloat16* __restrict__ oh, __nv_bfloat16* __restrict__ ol)
{
    const size_t row = blockIdx.x;
    const float* x = in + row * DD;
    float s = 0.0f, s2 = 0.0f;
    for (int i = threadIdx.x; i < DD; i += 256) {
        float v = x[i]; s += v; s2 += v * v;
    }
    #pragma unroll
    for (int o = 16; o > 0; o >>= 1) {
        s  += __shfl_xor_sync(0xFFFFFFFFu, s,  o);
        s2 += __shfl_xor_sync(0xFFFFFFFFu, s2, o);
    }
    __shared__ float ws[8], ws2[8];
    const int wid = threadIdx.x >> 5, lane = threadIdx.x & 31;
    if (lane == 0) { ws[wid] = s; ws2[wid] = s2; }
    __syncthreads();
    float ts = 0.0f, ts2 = 0.0f;
    #pragma unroll
    for (int i = 0; i < 8; i++) { ts += ws[i]; ts2 += ws2[i]; }
    const float mu   = ts  * (1.0f / DD);
    const float var  = ts2 * (1.0f / DD) - mu * mu;
    const float rstd = rsqrtf(var + 1e-5f);
    for (int i = threadIdx.x; i < DD; i += 256) {
        float r = (x[i] - mu) * rstd * w[i] + bsh[i];
        out[row * DD + i] = r;
        if (WB) {
            __nv_bfloat16 h, l; split_bf16(r, h, l);
            oh[row * DD + i] = h; ol[row * DD + i] = l;
        }
    }
}

// ======================= launch ============================================
template<typename T>
static void* sym_addr(T& sym) {
    void* p = nullptr;
    cudaGetSymbolAddress(&p, sym);
    return p;
}

extern "C" void kernel_launch(void* const* d_in, const int* in_sizes, int n_in,
                              void* d_out, int out_size)
{
    const float* src  = (const float*)d_in[0];
    const float* Wq   = (const float*)d_in[1];
    const float* bq   = (const float*)d_in[2];
    const float* Wk   = (const float*)d_in[3];
    const float* bk   = (const float*)d_in[4];
    const float* Wv   = (const float*)d_in[5];
    const float* bv   = (const float*)d_in[6];
    const float* Wo   = (const float*)d_in[7];
    const float* bo   = (const float*)d_in[8];
    const float* ln1w = (const float*)d_in[9];
    const float* ln1b = (const float*)d_in[10];
    const float* W1   = (const float*)d_in[11];
    const float* b1   = (const float*)d_in[12];
    const float* W2   = (const float*)d_in[13];
    const float* b2   = (const float*)d_in[14];
    const float* ln2w = (const float*)d_in[15];
    const float* ln2b = (const float*)d_in[16];
    float* out = (float*)d_out;

    float* pq   = (float*)sym_addr(g_q);
    float* pk   = (float*)sym_addr(g_k);
    float* pv   = (float*)sym_addr(g_v);
    float* pctx = (float*)sym_addr(g_ctx);
    float* py   = (float*)sym_addr(g_y);
    float* px   = (float*)sym_addr(g_x);
    float* py2  = (float*)sym_addr(g_y2);

    __nv_bfloat16* srch = (__nv_bfloat16*)sym_addr(s_srch);
    __nv_bfloat16* srcl = (__nv_bfloat16*)sym_addr(s_srcl);
    __nv_bfloat16* ctxh = (__nv_bfloat16*)sym_addr(s_ctxh);
    __nv_bfloat16* ctxl = (__nv_bfloat16*)sym_addr(s_ctxl);
    __nv_bfloat16* xh   = (__nv_bfloat16*)sym_addr(s_xh);
    __nv_bfloat16* xl   = (__nv_bfloat16*)sym_addr(s_xl);
    __nv_bfloat16* ffh  = (__nv_bfloat16*)sym_addr(s_ffh);
    __nv_bfloat16* ffl  = (__nv_bfloat16*)sym_addr(s_ffl);
    __nv_bfloat16* wqh  = (__nv_bfloat16*)sym_addr(w_qh);
    __nv_bfloat16* wql  = (__nv_bfloat16*)sym_addr(w_ql);
    __nv_bfloat16* wkh  = (__nv_bfloat16*)sym_addr(w_kh);
    __nv_bfloat16* wkl  = (__nv_bfloat16*)sym_addr(w_kl);
    __nv_bfloat16* wvh  = (__nv_bfloat16*)sym_addr(w_vh);
    __nv_bfloat16* wvl  = (__nv_bfloat16*)sym_addr(w_vl);
    __nv_bfloat16* woh  = (__nv_bfloat16*)sym_addr(w_oh);
    __nv_bfloat16* wol  = (__nv_bfloat16*)sym_addr(w_ol);
    __nv_bfloat16* w1h  = (__nv_bfloat16*)sym_addr(w_1h);
    __nv_bfloat16* w1l  = (__nv_bfloat16*)sym_addr(w_1l);
    __nv_bfloat16* w2h  = (__nv_bfloat16*)sym_addr(w_2h);
    __nv_bfloat16* w2l  = (__nv_bfloat16*)sym_addr(w_2l);

    // No static guard — identical host path on every call (harness rule).
    cudaFuncSetAttribute((const void*)gemm_mma<0>, cudaFuncAttributeMaxDynamicSharedMemorySize, GSMEM);
    cudaFuncSetAttribute((const void*)gemm_mma<1>, cudaFuncAttributeMaxDynamicSharedMemorySize, GSMEM);
    cudaFuncSetAttribute((const void*)gemm_mma<2>, cudaFuncAttributeMaxDynamicSharedMemorySize, GSMEM);

    // weight repack + activation split
    cvt_pair<<<(MROWS*DD + 255)/256, 256>>>(src, srch, srcl, MROWS*DD);
    repack_headw<<<(DD*DD + 255)/256, 256>>>(Wq, Wk, Wv);
    repack_T<<<(DD*DD + 255)/256, 256>>>(Wo, woh, wol, DD, DD);
    repack_T<<<(DFF*DD + 255)/256, 256>>>(W1, w1h, w1l, DFF, DD);
    repack_T<<<(DD*DFF + 255)/256, 256>>>(W2, w2h, w2l, DD, DFF);

    // QKV projections (split-bf16 mma.sync, scatter into [B,H,S,DK])
    dim3 g768(DD/128, MROWS/128);
    gemm_mma<0><<<g768, 256, GSMEM>>>(srch, srcl, wqh, wql, bq, nullptr, pq, nullptr, nullptr, MROWS, DD, DD);
    gemm_mma<0><<<g768, 256, GSMEM>>>(srch, srcl, wkh, wkl, bk, nullptr, pk, nullptr, nullptr, MROWS, DD, DD);
    gemm_mma<0><<<g768, 256, GSMEM>>>(srch, srcl, wvh, wvl, bv, nullptr, pv, nullptr, nullptr, MROWS, DD, DD);

    // attention (fp32)
    attn_k<<<dim3(SS/64, HH, BB), 64>>>();

    // out projection + residual -> y ; LN1 -> x (+ bf16 pair)
    cvt_pair<<<(MROWS*DD + 255)/256, 256>>>(pctx, ctxh, ctxl, MROWS*DD);
    gemm_mma<1><<<g768, 256, GSMEM>>>(ctxh, ctxl, woh, wol, bo, src, py, nullptr, nullptr, MROWS, DD, DD);
    ln_k<1><<<MROWS, 256>>>(py, ln1w, ln1b, px, xh, xl);

    // FFN
    gemm_mma<2><<<dim3(DFF/128, MROWS/128), 256, GSMEM>>>(xh, xl, w1h, w1l, b1, nullptr, nullptr, ffh, ffl, MROWS, DFF, DD);
    gemm_mma<1><<<g768, 256, GSMEM>>>(ffh, ffl, w2h, w2l, b2, px, py2, nullptr, nullptr, MROWS, DD, DFF);

    // LN2 -> output
    ln_k<0><<<MROWS, 256>>>(py2, ln2w, ln2b, out, nullptr, nullptr);
}

// round 6
// speedup vs baseline: 3.0538x; 2.1876x over previous
#include <cuda_runtime.h>
#include <cuda_bf16.h>
#include <cstdint>
#include <math.h>

#define BB 2
#define SS 2048
#define DD 768
#define HH 12
#define DKK 64
#define DFF 3072
#define MROWS (BB*SS)   // 4096

// ======================= device scratch (no allocs allowed) ================
__device__ float g_y[MROWS*DD];
__device__ float g_x[MROWS*DD];
__device__ float g_y2[MROWS*DD];
// bf16 hi/lo pairs
__device__ __nv_bfloat16 s_srch[MROWS*DD],  s_srcl[MROWS*DD];
__device__ __nv_bfloat16 s_ctxh[MROWS*DD],  s_ctxl[MROWS*DD];
__device__ __nv_bfloat16 s_xh[MROWS*DD],    s_xl[MROWS*DD];
__device__ __nv_bfloat16 s_ffh[MROWS*DFF],  s_ffl[MROWS*DFF];
__device__ __nv_bfloat16 a_qh[BB*HH*SS*DKK], a_ql[BB*HH*SS*DKK];
__device__ __nv_bfloat16 a_kh[BB*HH*SS*DKK], a_kl[BB*HH*SS*DKK];
__device__ __nv_bfloat16 a_vth[BB*HH*DKK*SS], a_vtl[BB*HH*DKK*SS];
__device__ __nv_bfloat16 w_qh[DD*DD], w_ql[DD*DD];
__device__ __nv_bfloat16 w_kh[DD*DD], w_kl[DD*DD];
__device__ __nv_bfloat16 w_vh[DD*DD], w_vl[DD*DD];
__device__ __nv_bfloat16 w_oh[DD*DD], w_ol[DD*DD];
__device__ __nv_bfloat16 w_1h[DFF*DD], w_1l[DFF*DD];
__device__ __nv_bfloat16 w_2h[DD*DFF], w_2l[DD*DFF];

// ======================= PTX helpers (stable ISA only) =====================
__device__ __forceinline__ uint32_t smem_u32(const void* p) {
    uint32_t a;
    asm("{ .reg .u64 t; cvta.to.shared.u64 t, %1; cvt.u32.u64 %0, t; }" : "=r"(a) : "l"(p));
    return a;
}
#define CP_ASYNC16(dst, src) \
    asm volatile("cp.async.cg.shared.global [%0], [%1], 16;" :: "r"(dst), "l"(src) : "memory")
#define CP_COMMIT() asm volatile("cp.async.commit_group;" ::: "memory")
#define CP_WAIT(n)  asm volatile("cp.async.wait_group %0;" :: "n"(n) : "memory")

__device__ __forceinline__ void ldm_x4(uint32_t* r, uint32_t addr) {
    asm volatile("ldmatrix.sync.aligned.m8n8.x4.shared.b16 {%0,%1,%2,%3}, [%4];"
        : "=r"(r[0]), "=r"(r[1]), "=r"(r[2]), "=r"(r[3]) : "r"(addr));
}
__device__ __forceinline__ void mma_bf16(float* c, const uint32_t* a, const uint32_t* b) {
    asm volatile("mma.sync.aligned.m16n8k16.row.col.f32.bf16.bf16.f32 "
        "{%0,%1,%2,%3}, {%4,%5,%6,%7}, {%8,%9}, {%0,%1,%2,%3};"
        : "+f"(c[0]), "+f"(c[1]), "+f"(c[2]), "+f"(c[3])
        : "r"(a[0]), "r"(a[1]), "r"(a[2]), "r"(a[3]), "r"(b[0]), "r"(b[1]));
}
__device__ __forceinline__ float ex2(float x) {
    float y; asm("ex2.approx.ftz.f32 %0, %1;" : "=f"(y) : "f"(x)); return y;
}
// pack (v0,v1) into bf16x2 hi-part and residual bf16x2 lo-part
__device__ __forceinline__ void pack_pair(float v0, float v1, uint32_t& ph, uint32_t& pl) {
    asm("cvt.rn.bf16x2.f32 %0, %1, %2;" : "=r"(ph) : "f"(v1), "f"(v0));
    float h0 = __uint_as_float(ph << 16);
    float h1 = __uint_as_float(ph & 0xFFFF0000u);
    float r0 = v0 - h0, r1 = v1 - h1;
    asm("cvt.rn.bf16x2.f32 %0, %1, %2;" : "=r"(pl) : "f"(r1), "f"(r0));
}
__device__ __forceinline__ void split_bf16(float v, __nv_bfloat16& h, __nv_bfloat16& l) {
    h = __float2bfloat16(v);
    l = __float2bfloat16(v - __bfloat162float(h));
}

// ======================= conversion / repack kernels =======================
__global__ void cvt_pair(const float* __restrict__ in,
                         __nv_bfloat16* __restrict__ oh, __nv_bfloat16* __restrict__ ol, int n) {
    int i = blockIdx.x * 256 + threadIdx.x;
    if (i >= n) return;
    __nv_bfloat16 h, l; split_bf16(in[i], h, l);
    oh[i] = h; ol[i] = l;
}

__global__ void repack_headw(const float* __restrict__ Wq, const float* __restrict__ Wk,
                             const float* __restrict__ Wv) {
    int idx = blockIdx.x * 256 + threadIdx.x;
    if (idx >= DD * DD) return;
    int n = idx / DD, d = idx % DD;
    int h = n >> 6, dk = n & 63;
    int s = (h * DD + d) * DKK + dk;
    __nv_bfloat16 hh, ll;
    split_bf16(Wq[s], hh, ll); w_qh[idx] = hh; w_ql[idx] = ll;
    split_bf16(Wk[s], hh, ll); w_kh[idx] = hh; w_kl[idx] = ll;
    split_bf16(Wv[s], hh, ll); w_vh[idx] = hh; w_vl[idx] = ll;
}

__global__ void repack_T(const float* __restrict__ W,
                         __nv_bfloat16* __restrict__ oh, __nv_bfloat16* __restrict__ ol,
                         int N, int K) {
    int idx = blockIdx.x * 256 + threadIdx.x;
    if (idx >= N * K) return;
    int n = idx / K, k = idx % K;
    __nv_bfloat16 h, l; split_bf16(W[(size_t)k * N + n], h, l);
    oh[idx] = h; ol[idx] = l;
}

// ======================= mma.sync split-bf16 GEMM ==========================
// MODE 0: (acc+bias)*scale -> split bf16 scatter [B,H,S,DK]  (Q / K)
// MODE 3: (acc+bias) -> split bf16 transposed scatter [B,H,DK,S]  (V)
// MODE 1: acc + bias + res -> fp32 row-major
// MODE 2: relu(acc+bias) -> split bf16 row-major
static constexpr int RS    = 80;
static constexpr int MATB  = 128 * RS;
static constexpr int STG   = 4 * MATB;
static constexpr int GSMEM = 2 * STG;       // 81920

template<int MODE>
__global__ void __launch_bounds__(256, 1) gemm_mma(
    const __nv_bfloat16* __restrict__ Ah, const __nv_bfloat16* __restrict__ Al,
    const __nv_bfloat16* __restrict__ Bh, const __nv_bfloat16* __restrict__ Bl,
    const float* __restrict__ bias, const float* __restrict__ res,
    float* __restrict__ C, __nv_bfloat16* __restrict__ Ch, __nv_bfloat16* __restrict__ Cl,
    int M, int N, int K, float scale)
{
    extern __shared__ char sb[];
    const uint32_t sbu = smem_u32(sb);
    const int tid  = threadIdx.x;
    const int wid  = tid >> 5;
    const int lane = tid & 31;
    const int wm   = wid & 3;
    const int wn   = wid >> 2;

    const int rowBase = blockIdx.y << 7;
    const int colBase = blockIdx.x << 7;
    const __nv_bfloat16* gA[2] = { Ah + (size_t)rowBase * K, Al + (size_t)rowBase * K };
    const __nv_bfloat16* gB[2] = { Bh + (size_t)colBase * K, Bl + (size_t)colBase * K };

    int ld_mat[8], ld_r[8], ld_q[8];
    #pragma unroll
    for (int i = 0; i < 8; i++) {
        int slot = (i << 8) + tid;
        ld_mat[i] = slot >> 9;
        int rem = slot & 511;
        ld_r[i] = rem >> 2;
        ld_q[i] = rem & 3;
    }

    auto load_stage = [&](int kc, int buf) {
        const uint32_t base = sbu + buf * STG;
        #pragma unroll
        for (int i = 0; i < 8; i++) {
            const __nv_bfloat16* src = (ld_mat[i] < 2 ? gA[ld_mat[i]] : gB[ld_mat[i] - 2])
                                       + (size_t)ld_r[i] * K + kc + (ld_q[i] << 3);
            uint32_t dst = base + ld_mat[i] * MATB + ld_r[i] * RS + (ld_q[i] << 4);
            CP_ASYNC16(dst, src);
        }
        CP_COMMIT();
    };

    float acc[2][8][4];
    #pragma unroll
    for (int mt = 0; mt < 2; mt++)
        #pragma unroll
        for (int nt = 0; nt < 8; nt++)
            #pragma unroll
            for (int j = 0; j < 4; j++) acc[mt][nt][j] = 0.0f;

    const uint32_t aAddr = (uint32_t)((wm * 32 + (lane & 15)) * RS + (lane >> 4) * 16);
    const uint32_t bAddr = (uint32_t)((wn * 64 + ((lane >> 4) << 3) + (lane & 7)) * RS
                                      + ((lane >> 3) & 1) * 16);

    const int nStages = K >> 5;
    load_stage(0, 0);

    for (int c = 0; c < nStages; c++) {
        if (c + 1 < nStages) load_stage((c + 1) << 5, (c + 1) & 1);
        if (c + 1 < nStages) { CP_WAIT(1); } else { CP_WAIT(0); }
        __syncthreads();

        const uint32_t base = sbu + (c & 1) * STG;
        #pragma unroll
        for (int ks = 0; ks < 2; ks++) {
            const uint32_t ko = ks * 32;
            uint32_t bh[16], bl[16];
            #pragma unroll
            for (int np = 0; np < 4; np++) {
                ldm_x4(bh + np * 4, base + 2 * MATB + bAddr + np * 16 * RS + ko);
                ldm_x4(bl + np * 4, base + 3 * MATB + bAddr + np * 16 * RS + ko);
            }
            #pragma unroll
            for (int mt = 0; mt < 2; mt++) {
                uint32_t ah[4], al[4];
                ldm_x4(ah, base + 0 * MATB + aAddr + mt * 16 * RS + ko);
                ldm_x4(al, base + 1 * MATB + aAddr + mt * 16 * RS + ko);
                #pragma unroll
                for (int nt = 0; nt < 8; nt++) {
                    mma_bf16(acc[mt][nt], ah, bh + nt * 2);
                    mma_bf16(acc[mt][nt], ah, bl + nt * 2);
                    mma_bf16(acc[mt][nt], al, bh + nt * 2);
                }
            }
        }
        __syncthreads();
    }

    // ---------------- epilogue ----------------
    const int g  = lane >> 2;
    const int tc = (lane & 3) << 1;

    #pragma unroll
    for (int mt = 0; mt < 2; mt++) {
        #pragma unroll
        for (int half = 0; half < 2; half++) {
            const int orow = rowBase + wm * 32 + mt * 16 + g + half * 8;
            #pragma unroll
            for (int nt = 0; nt < 8; nt++) {
                const int col = colBase + wn * 64 + nt * 8 + tc;
                float v0 = acc[mt][nt][half * 2 + 0] + bias[col];
                float v1 = acc[mt][nt][half * 2 + 1] + bias[col + 1];
                if (MODE == 0) {
                    v0 *= scale; v1 *= scale;
                    const int b = orow >> 11, s = orow & 2047;
                    const int h = col >> 6, dk = col & 63;
                    uint32_t hw, lw; pack_pair(v0, v1, hw, lw);
                    size_t off = (((size_t)b * HH + h) * SS + s) * DKK + dk;
                    *(uint32_t*)(Ch + off) = hw;
                    *(uint32_t*)(Cl + off) = lw;
                } else if (MODE == 3) {
                    const int b = orow >> 11, s = orow & 2047;
                    const int h = col >> 6, dk = col & 63;
                    __nv_bfloat16 h0, l0, h1, l1;
                    split_bf16(v0, h0, l0); split_bf16(v1, h1, l1);
                    size_t off = (((size_t)b * HH + h) * DKK + dk) * SS + s;
                    Ch[off] = h0; Cl[off] = l0;
                    Ch[off + SS] = h1; Cl[off + SS] = l1;
                } else if (MODE == 1) {
                    const float* rp = res + (size_t)orow * N + col;
                    float2 rv = *(const float2*)rp;
                    *(float2*)(C + (size_t)orow * N + col) = make_float2(v0 + rv.x, v1 + rv.y);
                } else {
                    v0 = fmaxf(v0, 0.0f); v1 = fmaxf(v1, 0.0f);
                    uint32_t hw, lw; pack_pair(v0, v1, hw, lw);
                    *(uint32_t*)(Ch + (size_t)orow * N + col) = hw;
                    *(uint32_t*)(Cl + (size_t)orow * N + col) = lw;
                }
            }
        }
    }
}

// ======================= mma.sync flash attention ==========================
// block: 256 thr (8 warps), 128 queries; key tiles of 64, double-buffered.
static constexpr int ATT_RS  = 144;           // 64 bf16 = 128B + 16B pad
static constexpr int ATT_BUF = 64 * ATT_RS;   // 9216
static constexpr int ATT_STG = 4 * ATT_BUF;   // 36864 (Kh,Kl,Vh,Vl)
static constexpr int ATT_SMEM = 2 * ATT_STG;  // 73728

__global__ void __launch_bounds__(256, 2) attn_mma(
    const __nv_bfloat16* __restrict__ Qh, const __nv_bfloat16* __restrict__ Ql,
    const __nv_bfloat16* __restrict__ Kh, const __nv_bfloat16* __restrict__ Kl,
    const __nv_bfloat16* __restrict__ VTh, const __nv_bfloat16* __restrict__ VTl,
    __nv_bfloat16* __restrict__ Ch, __nv_bfloat16* __restrict__ Cl)
{
    extern __shared__ char sm[];
    const uint32_t sbu = smem_u32(sm);
    const int qt = blockIdx.x, h = blockIdx.y, b = blockIdx.z;
    const int tid = threadIdx.x, wid = tid >> 5, lane = tid & 31;

    const size_t bh = (size_t)b * HH + h;
    const __nv_bfloat16* gQh = Qh + (bh * SS + qt * 128) * DKK;
    const __nv_bfloat16* gQl = Ql + (bh * SS + qt * 128) * DKK;
    const __nv_bfloat16* gKh = Kh + bh * SS * DKK;
    const __nv_bfloat16* gKl = Kl + bh * SS * DKK;
    const __nv_bfloat16* gVh = VTh + bh * DKK * SS;
    const __nv_bfloat16* gVl = VTl + bh * DKK * SS;

    // ---- stage Q tile (128x64 hi + lo) via cp.async, extract A-frags ----
    {
        #pragma unroll
        for (int i = 0; i < 8; i++) {
            int slot = (i << 8) + tid;          // 0..2047
            int split = slot >> 10;
            int rem = slot & 1023;
            int r = rem >> 3, c = rem & 7;
            const __nv_bfloat16* src = (split ? gQl : gQh) + r * DKK + (c << 3);
            CP_ASYNC16(sbu + split * (128 * ATT_RS) + r * ATT_RS + (c << 4), src);
        }
        CP_COMMIT(); CP_WAIT(0);
        __syncthreads();
    }
    uint32_t qfh[4][4], qfl[4][4];
    {
        const uint32_t qa = sbu + (wid * 16 + (lane & 15)) * ATT_RS + ((lane >> 4) << 4);
        #pragma unroll
        for (int ks = 0; ks < 4; ks++) {
            ldm_x4(qfh[ks], qa + ks * 32);
            ldm_x4(qfl[ks], qa + 128 * ATT_RS + ks * 32);
        }
    }
    __syncthreads();

    auto load_kv = [&](int t0, int buf) {
        const uint32_t base = sbu + buf * ATT_STG;
        #pragma unroll
        for (int i = 0; i < 8; i++) {
            int slot = (i << 8) + tid;          // 0..2047
            int arr = slot >> 9;                // 0 Kh,1 Kl,2 Vh,3 Vl
            int rem = slot & 511;
            int r = rem >> 3, c = rem & 7;
            const __nv_bfloat16* src;
            if (arr == 0)      src = gKh + (size_t)(t0 + r) * DKK + (c << 3);
            else if (arr == 1) src = gKl + (size_t)(t0 + r) * DKK + (c << 3);
            else if (arr == 2) src = gVh + (size_t)r * SS + t0 + (c << 3);
            else               src = gVl + (size_t)r * SS + t0 + (c << 3);
            CP_ASYNC16(base + arr * ATT_BUF + r * ATT_RS + (c << 4), src);
        }
        CP_COMMIT();
    };

    float ctx[8][4];
    #pragma unroll
    for (int nt = 0; nt < 8; nt++)
        #pragma unroll
        for (int j = 0; j < 4; j++) ctx[nt][j] = 0.0f;
    float m0 = -1e30f, m1 = -1e30f, l0 = 0.0f, l1 = 0.0f;

    const uint32_t bAddr = (uint32_t)(((((lane >> 4) << 3) | (lane & 7)) * ATT_RS)
                                      + ((lane >> 3) & 1) * 16);

    load_kv(0, 0);
    #pragma unroll 1
    for (int t = 0; t < SS / 64; t++) {
        if (t + 1 < SS / 64) { load_kv((t + 1) * 64, (t + 1) & 1); CP_WAIT(1); }
        else                 { CP_WAIT(0); }
        __syncthreads();
        const uint32_t base = sbu + (t & 1) * ATT_STG;

        // ---- S = Q @ K^T (3-term split) ----
        float sa[8][4];
        #pragma unroll
        for (int nt = 0; nt < 8; nt++)
            #pragma unroll
            for (int j = 0; j < 4; j++) sa[nt][j] = 0.0f;
        #pragma unroll
        for (int ks = 0; ks < 4; ks++) {
            #pragma unroll
            for (int np = 0; np < 4; np++) {
                uint32_t kbh[4], kbl[4];
                ldm_x4(kbh, base + 0 * ATT_BUF + bAddr + np * 16 * ATT_RS + ks * 32);
                ldm_x4(kbl, base + 1 * ATT_BUF + bAddr + np * 16 * ATT_RS + ks * 32);
                mma_bf16(sa[2 * np],     qfh[ks], kbh);
                mma_bf16(sa[2 * np],     qfh[ks], kbl);
                mma_bf16(sa[2 * np],     qfl[ks], kbh);
                mma_bf16(sa[2 * np + 1], qfh[ks], kbh + 2);
                mma_bf16(sa[2 * np + 1], qfh[ks], kbl + 2);
                mma_bf16(sa[2 * np + 1], qfl[ks], kbh + 2);
            }
        }

        // ---- online softmax (base-2; Q pre-scaled by 0.125*log2e) ----
        float rm0 = -1e30f, rm1 = -1e30f;
        #pragma unroll
        for (int nt = 0; nt < 8; nt++) {
            rm0 = fmaxf(rm0, fmaxf(sa[nt][0], sa[nt][1]));
            rm1 = fmaxf(rm1, fmaxf(sa[nt][2], sa[nt][3]));
        }
        rm0 = fmaxf(rm0, __shfl_xor_sync(0xFFFFFFFFu, rm0, 1));
        rm0 = fmaxf(rm0, __shfl_xor_sync(0xFFFFFFFFu, rm0, 2));
        rm1 = fmaxf(rm1, __shfl_xor_sync(0xFFFFFFFFu, rm1, 1));
        rm1 = fmaxf(rm1, __shfl_xor_sync(0xFFFFFFFFu, rm1, 2));
        const float nm0 = fmaxf(m0, rm0), nm1 = fmaxf(m1, rm1);
        const float c0 = ex2(m0 - nm0), c1 = ex2(m1 - nm1);
        l0 *= c0; l1 *= c1;
        #pragma unroll
        for (int nt = 0; nt < 8; nt++) {
            ctx[nt][0] *= c0; ctx[nt][1] *= c0;
            ctx[nt][2] *= c1; ctx[nt][3] *= c1;
        }
        float s0 = 0.0f, s1 = 0.0f;
        #pragma unroll
        for (int nt = 0; nt < 8; nt++) {
            float p0 = ex2(sa[nt][0] - nm0); sa[nt][0] = p0; s0 += p0;
            float p1 = ex2(sa[nt][1] - nm0); sa[nt][1] = p1; s0 += p1;
            float p2 = ex2(sa[nt][2] - nm1); sa[nt][2] = p2; s1 += p2;
            float p3 = ex2(sa[nt][3] - nm1); sa[nt][3] = p3; s1 += p3;
        }
        s0 += __shfl_xor_sync(0xFFFFFFFFu, s0, 1);
        s0 += __shfl_xor_sync(0xFFFFFFFFu, s0, 2);
        s1 += __shfl_xor_sync(0xFFFFFFFFu, s1, 1);
        s1 += __shfl_xor_sync(0xFFFFFFFFu, s1, 2);
        l0 += s0; l1 += s1; m0 = nm0; m1 = nm1;

        // ---- ctx += P @ V  (P A-frags built from S acc registers) ----
        #pragma unroll
        for (int ks = 0; ks < 4; ks++) {
            uint32_t ah[4], al[4];
            pack_pair(sa[2 * ks][0],     sa[2 * ks][1],     ah[0], al[0]);
            pack_pair(sa[2 * ks][2],     sa[2 * ks][3],     ah[1], al[1]);
            pack_pair(sa[2 * ks + 1][0], sa[2 * ks + 1][1], ah[2], al[2]);
            pack_pair(sa[2 * ks + 1][2], sa[2 * ks + 1][3], ah[3], al[3]);
            #pragma unroll
            for (int np = 0; np < 4; np++) {
                uint32_t vbh[4], vbl[4];
                ldm_x4(vbh, base + 2 * ATT_BUF + bAddr + np * 16 * ATT_RS + ks * 32);
                ldm_x4(vbl, base + 3 * ATT_BUF + bAddr + np * 16 * ATT_RS + ks * 32);
                mma_bf16(ctx[2 * np],     ah, vbh);
                mma_bf16(ctx[2 * np],     al, vbh);
                mma_bf16(ctx[2 * np],     ah, vbl);
                mma_bf16(ctx[2 * np + 1], ah, vbh + 2);
                mma_bf16(ctx[2 * np + 1], al, vbh + 2);
                mma_bf16(ctx[2 * np + 1], ah, vbl + 2);
            }
        }
        __syncthreads();
    }

    // ---- epilogue: ctx/l -> split bf16 [B, S, H*DK] ----
    const float i0 = 1.0f / l0, i1 = 1.0f / l1;
    const int g = lane >> 2, tc2 = (lane & 3) << 1;
    const int r0 = qt * 128 + wid * 16 + g;
    const size_t base0 = ((size_t)b * SS + r0) * DD + h * DKK;
    #pragma unroll
    for (int nt = 0; nt < 8; nt++) {
        const int col = nt * 8 + tc2;
        uint32_t hw, lw;
        pack_pair(ctx[nt][0] * i0, ctx[nt][1] * i0, hw, lw);
        *(uint32_t*)(Ch + base0 + col) = hw;
        *(uint32_t*)(Cl + base0 + col) = lw;
        pack_pair(ctx[nt][2] * i1, ctx[nt][3] * i1, hw, lw);
        *(uint32_t*)(Ch + base0 + (size_t)8 * DD + col) = hw;
        *(uint32_t*)(Cl + base0 + (size_t)8 * DD + col) = lw;
    }
}

// ======================= LayerNorm (optionally emits bf16 pair) ============
template<int WB>
__global__ __launch_bounds__(256)
void ln_k(const float* __restrict__ in, const float* __restrict__ w,
          const float* __restrict__ bsh, float* __restrict__ out,
          __nv_bfloat16* __restrict__ oh, __nv_bfloat16* __restrict__ ol)
{
    const size_t row = blockIdx.x;
    const float* x = in + row * DD;
    float s = 0.0f, s2 = 0.0f;
    for (int i = threadIdx.x; i < DD; i += 256) {
        float v = x[i]; s += v; s2 += v * v;
    }
    #pragma unroll
    for (int o = 16; o > 0; o >>= 1) {
        s  += __shfl_xor_sync(0xFFFFFFFFu, s,  o);
        s2 += __shfl_xor_sync(0xFFFFFFFFu, s2, o);
    }
    __shared__ float ws[8], ws2[8];
    const int wid = threadIdx.x >> 5, lane = threadIdx.x & 31;
    if (lane == 0) { ws[wid] = s; ws2[wid] = s2; }
    __syncthreads();
    float ts = 0.0f, ts2 = 0.0f;
    #pragma unroll
    for (int i = 0; i < 8; i++) { ts += ws[i]; ts2 += ws2[i]; }
    const float mu   = ts  * (1.0f / DD);
    const float var  = ts2 * (1.0f / DD) - mu * mu;
    const float rstd = rsqrtf(var + 1e-5f);
    for (int i = threadIdx.x; i < DD; i += 256) {
        float r = (x[i] - mu) * rstd * w[i] + bsh[i];
        out[row * DD + i] = r;
        if (WB) {
            __nv_bfloat16 h, l; split_bf16(r, h, l);
            oh[row * DD + i] = h; ol[row * DD + i] = l;
        }
    }
}

// ======================= launch ============================================
template<typename T>
static void* sym_addr(T& sym) {
    void* p = nullptr;
    cudaGetSymbolAddress(&p, sym);
    return p;
}

extern "C" void kernel_launch(void* const* d_in, const int* in_sizes, int n_in,
                              void* d_out, int out_size)
{
    const float* src  = (const float*)d_in[0];
    const float* Wq   = (const float*)d_in[1];
    const float* bq   = (const float*)d_in[2];
    const float* Wk   = (const float*)d_in[3];
    const float* bk   = (const float*)d_in[4];
    const float* Wv   = (const float*)d_in[5];
    const float* bv   = (const float*)d_in[6];
    const float* Wo   = (const float*)d_in[7];
    const float* bo   = (const float*)d_in[8];
    const float* ln1w = (const float*)d_in[9];
    const float* ln1b = (const float*)d_in[10];
    const float* W1   = (const float*)d_in[11];
    const float* b1   = (const float*)d_in[12];
    const float* W2   = (const float*)d_in[13];
    const float* b2   = (const float*)d_in[14];
    const float* ln2w = (const float*)d_in[15];
    const float* ln2b = (const float*)d_in[16];
    float* out = (float*)d_out;

    float* py   = (float*)sym_addr(g_y);
    float* px   = (float*)sym_addr(g_x);
    float* py2  = (float*)sym_addr(g_y2);

    __nv_bfloat16* srch = (__nv_bfloat16*)sym_addr(s_srch);
    __nv_bfloat16* srcl = (__nv_bfloat16*)sym_addr(s_srcl);
    __nv_bfloat16* ctxh = (__nv_bfloat16*)sym_addr(s_ctxh);
    __nv_bfloat16* ctxl = (__nv_bfloat16*)sym_addr(s_ctxl);
    __nv_bfloat16* xh   = (__nv_bfloat16*)sym_addr(s_xh);
    __nv_bfloat16* xl   = (__nv_bfloat16*)sym_addr(s_xl);
    __nv_bfloat16* ffh  = (__nv_bfloat16*)sym_addr(s_ffh);
    __nv_bfloat16* ffl  = (__nv_bfloat16*)sym_addr(s_ffl);
    __nv_bfloat16* qh   = (__nv_bfloat16*)sym_addr(a_qh);
    __nv_bfloat16* ql   = (__nv_bfloat16*)sym_addr(a_ql);
    __nv_bfloat16* kh   = (__nv_bfloat16*)sym_addr(a_kh);
    __nv_bfloat16* kl   = (__nv_bfloat16*)sym_addr(a_kl);
    __nv_bfloat16* vth  = (__nv_bfloat16*)sym_addr(a_vth);
    __nv_bfloat16* vtl  = (__nv_bfloat16*)sym_addr(a_vtl);
    __nv_bfloat16* wqh  = (__nv_bfloat16*)sym_addr(w_qh);
    __nv_bfloat16* wql  = (__nv_bfloat16*)sym_addr(w_ql);
    __nv_bfloat16* wkh  = (__nv_bfloat16*)sym_addr(w_kh);
    __nv_bfloat16* wkl  = (__nv_bfloat16*)sym_addr(w_kl);
    __nv_bfloat16* wvh  = (__nv_bfloat16*)sym_addr(w_vh);
    __nv_bfloat16* wvl  = (__nv_bfloat16*)sym_addr(w_vl);
    __nv_bfloat16* woh  = (__nv_bfloat16*)sym_addr(w_oh);
    __nv_bfloat16* wol  = (__nv_bfloat16*)sym_addr(w_ol);
    __nv_bfloat16* w1h  = (__nv_bfloat16*)sym_addr(w_1h);
    __nv_bfloat16* w1l  = (__nv_bfloat16*)sym_addr(w_1l);
    __nv_bfloat16* w2h  = (__nv_bfloat16*)sym_addr(w_2h);
    __nv_bfloat16* w2l  = (__nv_bfloat16*)sym_addr(w_2l);

    cudaFuncSetAttribute((const void*)gemm_mma<0>, cudaFuncAttributeMaxDynamicSharedMemorySize, GSMEM);
    cudaFuncSetAttribute((const void*)gemm_mma<1>, cudaFuncAttributeMaxDynamicSharedMemorySize, GSMEM);
    cudaFuncSetAttribute((const void*)gemm_mma<2>, cudaFuncAttributeMaxDynamicSharedMemorySize, GSMEM);
    cudaFuncSetAttribute((const void*)gemm_mma<3>, cudaFuncAttributeMaxDynamicSharedMemorySize, GSMEM);
    cudaFuncSetAttribute((const void*)attn_mma,    cudaFuncAttributeMaxDynamicSharedMemorySize, ATT_SMEM);

    // weight repack + activation split
    cvt_pair<<<(MROWS*DD + 255)/256, 256>>>(src, srch, srcl, MROWS*DD);
    repack_headw<<<(DD*DD + 255)/256, 256>>>(Wq, Wk, Wv);
    repack_T<<<(DD*DD + 255)/256, 256>>>(Wo, woh, wol, DD, DD);
    repack_T<<<(DFF*DD + 255)/256, 256>>>(W1, w1h, w1l, DFF, DD);
    repack_T<<<(DD*DFF + 255)/256, 256>>>(W2, w2h, w2l, DD, DFF);

    // QKV projections: Q scaled by 0.125*log2(e) (base-2 softmax), K plain, V transposed
    const float QSCALE = 0.125f * 1.44269504088896340736f;
    dim3 g768(DD/128, MROWS/128);
    gemm_mma<0><<<g768, 256, GSMEM>>>(srch, srcl, wqh, wql, bq, nullptr, nullptr, qh, ql, MROWS, DD, DD, QSCALE);
    gemm_mma<0><<<g768, 256, GSMEM>>>(srch, srcl, wkh, wkl, bk, nullptr, nullptr, kh, kl, MROWS, DD, DD, 1.0f);
    gemm_mma<3><<<g768, 256, GSMEM>>>(srch, srcl, wvh, wvl, bv, nullptr, nullptr, vth, vtl, MROWS, DD, DD, 1.0f);

    // flash attention (split-bf16 mma) -> ctx split pair [B,S,H*DK]
    attn_mma<<<dim3(SS/128, HH, BB), 256, ATT_SMEM>>>(qh, ql, kh, kl, vth, vtl, ctxh, ctxl);

    // out projection + residual -> y ; LN1 -> x (+ bf16 pair)
    gemm_mma<1><<<g768, 256, GSMEM>>>(ctxh, ctxl, woh, wol, bo, src, py, nullptr, nullptr, MROWS, DD, DD, 1.0f);
    ln_k<1><<<MROWS, 256>>>(py, ln1w, ln1b, px, xh, xl);

    // FFN
    gemm_mma<2><<<dim3(DFF/128, MROWS/128), 256, GSMEM>>>(xh, xl, w1h, w1l, b1, nullptr, nullptr, ffh, ffl, MROWS, DFF, DD, 1.0f);
    gemm_mma<1><<<g768, 256, GSMEM>>>(ffh, ffl, w2h, w2l, b2, px, py2, nullptr, nullptr, MROWS, DD, DFF, 1.0f);

    // LN2 -> output
    ln_k<0><<<MROWS, 256>>>(py2, ln2w, ln2b, out, nullptr, nullptr);
}

// round 7
// speedup vs baseline: 3.6165x; 1.1843x over previous
#include <cuda_runtime.h>
#include <cuda_bf16.h>
#include <cstdint>
#include <math.h>

#define BB 2
#define SS 2048
#define DD 768
#define HH 12
#define DKK 64
#define DFF 3072
#define MROWS (BB*SS)   // 4096

// ======================= device scratch (no allocs allowed) ================
__device__ float g_y[MROWS*DD];
__device__ float g_x[MROWS*DD];
__device__ float g_y2[MROWS*DD];
// bf16 hi/lo pairs
__device__ __nv_bfloat16 s_srch[MROWS*DD],  s_srcl[MROWS*DD];
__device__ __nv_bfloat16 s_ctxh[MROWS*DD],  s_ctxl[MROWS*DD];
__device__ __nv_bfloat16 s_xh[MROWS*DD],    s_xl[MROWS*DD];
__device__ __nv_bfloat16 s_ffh[MROWS*DFF],  s_ffl[MROWS*DFF];
__device__ __nv_bfloat16 a_qh[BB*HH*SS*DKK], a_ql[BB*HH*SS*DKK];
__device__ __nv_bfloat16 a_kh[BB*HH*SS*DKK], a_kl[BB*HH*SS*DKK];
__device__ __nv_bfloat16 a_vth[BB*HH*DKK*SS], a_vtl[BB*HH*DKK*SS];
__device__ __nv_bfloat16 w_qkvh[3*DD*DD], w_qkvl[3*DD*DD];   // [2304, 768]
__device__ __nv_bfloat16 w_oh[DD*DD], w_ol[DD*DD];
__device__ __nv_bfloat16 w_1h[DFF*DD], w_1l[DFF*DD];
__device__ __nv_bfloat16 w_2h[DD*DFF], w_2l[DD*DFF];

// ======================= PTX helpers (stable ISA only) =====================
__device__ __forceinline__ uint32_t smem_u32(const void* p) {
    uint32_t a;
    asm("{ .reg .u64 t; cvta.to.shared.u64 t, %1; cvt.u32.u64 %0, t; }" : "=r"(a) : "l"(p));
    return a;
}
#define CP_ASYNC16(dst, src) \
    asm volatile("cp.async.cg.shared.global [%0], [%1], 16;" :: "r"(dst), "l"(src) : "memory")
#define CP_COMMIT() asm volatile("cp.async.commit_group;" ::: "memory")
#define CP_WAIT(n)  asm volatile("cp.async.wait_group %0;" :: "n"(n) : "memory")

__device__ __forceinline__ void ldm_x4(uint32_t* r, uint32_t addr) {
    asm volatile("ldmatrix.sync.aligned.m8n8.x4.shared.b16 {%0,%1,%2,%3}, [%4];"
        : "=r"(r[0]), "=r"(r[1]), "=r"(r[2]), "=r"(r[3]) : "r"(addr));
}
__device__ __forceinline__ void mma_bf16(float* c, const uint32_t* a, const uint32_t* b) {
    asm volatile("mma.sync.aligned.m16n8k16.row.col.f32.bf16.bf16.f32 "
        "{%0,%1,%2,%3}, {%4,%5,%6,%7}, {%8,%9}, {%0,%1,%2,%3};"
        : "+f"(c[0]), "+f"(c[1]), "+f"(c[2]), "+f"(c[3])
        : "r"(a[0]), "r"(a[1]), "r"(a[2]), "r"(a[3]), "r"(b[0]), "r"(b[1]));
}
__device__ __forceinline__ float ex2(float x) {
    float y; asm("ex2.approx.ftz.f32 %0, %1;" : "=f"(y) : "f"(x)); return y;
}
__device__ __forceinline__ void pack_pair(float v0, float v1, uint32_t& ph, uint32_t& pl) {
    asm("cvt.rn.bf16x2.f32 %0, %1, %2;" : "=r"(ph) : "f"(v1), "f"(v0));
    float h0 = __uint_as_float(ph << 16);
    float h1 = __uint_as_float(ph & 0xFFFF0000u);
    float r0 = v0 - h0, r1 = v1 - h1;
    asm("cvt.rn.bf16x2.f32 %0, %1, %2;" : "=r"(pl) : "f"(r1), "f"(r0));
}
__device__ __forceinline__ void split_bf16(float v, __nv_bfloat16& h, __nv_bfloat16& l) {
    h = __float2bfloat16(v);
    l = __float2bfloat16(v - __bfloat162float(h));
}

static __device__ __constant__ const float QSCALE_D = 0.125f * 1.44269504088896340736f;

// ======================= conversion / repack kernels =======================
__global__ void cvt_pair(const float* __restrict__ in,
                         __nv_bfloat16* __restrict__ oh, __nv_bfloat16* __restrict__ ol, int n) {
    int i = blockIdx.x * 256 + threadIdx.x;
    if (i >= n) return;
    __nv_bfloat16 h, l; split_bf16(in[i], h, l);
    oh[i] = h; ol[i] = l;
}

// W [K, N] row-major -> (oh,ol) [N, K]; smem-tiled transpose, block (32,8)
__global__ void repack_T2(const float* __restrict__ W,
                          __nv_bfloat16* __restrict__ oh, __nv_bfloat16* __restrict__ ol,
                          int N, int K) {
    __shared__ float t[32][33];
    const int n0 = blockIdx.x * 32, k0 = blockIdx.y * 32;
    const int tx = threadIdx.x, ty = threadIdx.y;
    #pragma unroll
    for (int r = 0; r < 4; r++)
        t[ty + 8 * r][tx] = W[(size_t)(k0 + ty + 8 * r) * N + n0 + tx];
    __syncthreads();
    #pragma unroll
    for (int r = 0; r < 4; r++) {
        float v = t[tx][ty + 8 * r];
        __nv_bfloat16 h, l; split_bf16(v, h, l);
        size_t o = (size_t)(n0 + ty + 8 * r) * K + k0 + tx;
        oh[o] = h; ol[o] = l;
    }
}

// Wq/Wk/Wv [H,D,DK] -> w_qkv [2304 rows (sel*768 + h*64 + dk), 768 cols (d)]
// grid (DK/32=2, D/32=24, 3*H=36), block (32,8)
__global__ void repack_qkvw(const float* __restrict__ Wq, const float* __restrict__ Wk,
                            const float* __restrict__ Wv) {
    __shared__ float t[32][33];
    const int sel = blockIdx.z / HH, h = blockIdx.z % HH;
    const float* W = (sel == 0 ? Wq : sel == 1 ? Wk : Wv) + (size_t)h * DD * DKK;
    const int dk0 = blockIdx.x * 32, d0 = blockIdx.y * 32;
    const int tx = threadIdx.x, ty = threadIdx.y;
    #pragma unroll
    for (int r = 0; r < 4; r++)
        t[ty + 8 * r][tx] = W[(size_t)(d0 + ty + 8 * r) * DKK + dk0 + tx];
    __syncthreads();
    #pragma unroll
    for (int r = 0; r < 4; r++) {
        float v = t[tx][ty + 8 * r];
        __nv_bfloat16 hh, ll; split_bf16(v, hh, ll);
        size_t row = (size_t)sel * DD + h * DKK + dk0 + ty + 8 * r;
        w_qkvh[row * DD + d0 + tx] = hh;
        w_qkvl[row * DD + d0 + tx] = ll;
    }
}

// ======================= mma.sync split-bf16 GEMM ==========================
// C[M,N] = (Ah+Al)[M,K] @ (Bh+Bl)[N,K]^T  (Al*Bl dropped)
// MODE 1: acc + bias + res -> fp32 row-major
// MODE 2: relu(acc+bias) -> split bf16 row-major
// MODE 4: fused QKV epilogue (writes a_q*/a_k*/a_vt* device symbols;
//         bias=bq, res=bk(cast), C=bv(cast))
static constexpr int RS = 80;

template<int BN> struct GP {
    static constexpr int A_BYTES = 128 * RS;
    static constexpr int B_BYTES = BN * RS;
    static constexpr int STGB    = 2 * A_BYTES + 2 * B_BYTES;
    static constexpr int SMEM    = 2 * STGB;
    static constexpr int NTW     = BN / 16;     // acc n8-tiles per warp
    static constexpr int NPB     = BN / 32;     // B ldm 16-row groups per warp
    static constexpr int CPT     = (1024 + 8 * BN) / 256;  // 16B chunks / thread
};

template<int MODE, int BN>
__global__ void __launch_bounds__(256, 1) gemm_mma(
    const __nv_bfloat16* __restrict__ Ah, const __nv_bfloat16* __restrict__ Al,
    const __nv_bfloat16* __restrict__ Bh, const __nv_bfloat16* __restrict__ Bl,
    const float* __restrict__ bias, const float* __restrict__ res,
    float* __restrict__ C, __nv_bfloat16* __restrict__ Ch, __nv_bfloat16* __restrict__ Cl,
    int M, int N, int K)
{
    using P = GP<BN>;
    extern __shared__ char sb[];
    const uint32_t sbu = smem_u32(sb);
    const int tid  = threadIdx.x;
    const int wid  = tid >> 5;
    const int lane = tid & 31;
    const int wm   = wid & 3;
    const int wn   = wid >> 2;

    const int rowBase = blockIdx.y << 7;
    const int colBase = blockIdx.x * BN;
    const __nv_bfloat16* gA[2] = { Ah + (size_t)rowBase * K, Al + (size_t)rowBase * K };
    const __nv_bfloat16* gB[2] = { Bh + (size_t)colBase * K, Bl + (size_t)colBase * K };

    int ld_mat[P::CPT], ld_r[P::CPT], ld_q[P::CPT];
    #pragma unroll
    for (int i = 0; i < P::CPT; i++) {
        int slot = (i << 8) + tid;
        int mat, rem;
        if (slot < 1024) { mat = slot >> 9; rem = slot & 511; }
        else             { mat = 2 + (slot - 1024) / (4 * BN); rem = (slot - 1024) % (4 * BN); }
        ld_mat[i] = mat; ld_r[i] = rem >> 2; ld_q[i] = rem & 3;
    }

    const uint32_t OFF_M[4] = { 0u, (uint32_t)P::A_BYTES, (uint32_t)(2*P::A_BYTES),
                                (uint32_t)(2*P::A_BYTES + P::B_BYTES) };

    auto load_stage = [&](int kc, int buf) {
        const uint32_t base = sbu + buf * P::STGB;
        #pragma unroll
        for (int i = 0; i < P::CPT; i++) {
            const __nv_bfloat16* src = (ld_mat[i] < 2 ? gA[ld_mat[i]] : gB[ld_mat[i] - 2])
                                       + (size_t)ld_r[i] * K + kc + (ld_q[i] << 3);
            uint32_t dst = base + OFF_M[ld_mat[i]] + ld_r[i] * RS + (ld_q[i] << 4);
            CP_ASYNC16(dst, src);
        }
        CP_COMMIT();
    };

    float acc[2][P::NTW][4];
    #pragma unroll
    for (int mt = 0; mt < 2; mt++)
        #pragma unroll
        for (int nt = 0; nt < P::NTW; nt++)
            #pragma unroll
            for (int j = 0; j < 4; j++) acc[mt][nt][j] = 0.0f;

    const uint32_t aAddr = (uint32_t)((wm * 32 + (lane & 15)) * RS + (lane >> 4) * 16);
    const uint32_t bAddr = (uint32_t)((wn * (BN/2) + ((lane >> 4) << 3) + (lane & 7)) * RS
                                      + ((lane >> 3) & 1) * 16);

    const int nStages = K >> 5;
    load_stage(0, 0);

    for (int c = 0; c < nStages; c++) {
        if (c + 1 < nStages) load_stage((c + 1) << 5, (c + 1) & 1);
        if (c + 1 < nStages) { CP_WAIT(1); } else { CP_WAIT(0); }
        __syncthreads();

        const uint32_t base = sbu + (c & 1) * P::STGB;
        #pragma unroll
        for (int ks = 0; ks < 2; ks++) {
            const uint32_t ko = ks * 32;
            uint32_t bh[P::NTW*2], bl[P::NTW*2];
            #pragma unroll
            for (int np = 0; np < P::NPB; np++) {
                ldm_x4(bh + np * 4, base + OFF_M[2] + bAddr + np * 16 * RS + ko);
                ldm_x4(bl + np * 4, base + OFF_M[3] + bAddr + np * 16 * RS + ko);
            }
            #pragma unroll
            for (int mt = 0; mt < 2; mt++) {
                uint32_t ah[4], al[4];
                ldm_x4(ah, base + OFF_M[0] + aAddr + mt * 16 * RS + ko);
                ldm_x4(al, base + OFF_M[1] + aAddr + mt * 16 * RS + ko);
                #pragma unroll
                for (int nt = 0; nt < P::NTW; nt++) {
                    mma_bf16(acc[mt][nt], ah, bh + nt * 2);
                    mma_bf16(acc[mt][nt], ah, bl + nt * 2);
                    mma_bf16(acc[mt][nt], al, bh + nt * 2);
                }
            }
        }
        __syncthreads();
    }

    // ---------------- epilogue ----------------
    const int g  = lane >> 2;
    const int tc = (lane & 3) << 1;

    #pragma unroll
    for (int mt = 0; mt < 2; mt++) {
        #pragma unroll
        for (int half = 0; half < 2; half++) {
            const int orow = rowBase + wm * 32 + mt * 16 + g + half * 8;
            #pragma unroll
            for (int nt = 0; nt < P::NTW; nt++) {
                const int col = colBase + wn * (BN/2) + nt * 8 + tc;
                float a0 = acc[mt][nt][half * 2 + 0];
                float a1 = acc[mt][nt][half * 2 + 1];
                if (MODE == 4) {
                    const int sel = col / DD;
                    const int lc  = col - sel * DD;
                    const float* bptr = sel == 0 ? bias : sel == 1 ? res : (const float*)C;
                    float v0 = a0 + bptr[lc];
                    float v1 = a1 + bptr[lc + 1];
                    const int b = orow >> 11, s = orow & 2047;
                    const int h = lc >> 6, dk = lc & 63;
                    if (sel == 2) {
                        __nv_bfloat16 h0, l0, h1, l1;
                        split_bf16(v0, h0, l0); split_bf16(v1, h1, l1);
                        size_t off = (((size_t)b * HH + h) * DKK + dk) * SS + s;
                        a_vth[off] = h0; a_vtl[off] = l0;
                        a_vth[off + SS] = h1; a_vtl[off + SS] = l1;
                    } else {
                        if (sel == 0) { v0 *= QSCALE_D; v1 *= QSCALE_D; }
                        uint32_t hw, lw; pack_pair(v0, v1, hw, lw);
                        size_t off = (((size_t)b * HH + h) * SS + s) * DKK + dk;
                        __nv_bfloat16* dh = sel == 0 ? a_qh : a_kh;
                        __nv_bfloat16* dl = sel == 0 ? a_ql : a_kl;
                        *(uint32_t*)(dh + off) = hw;
                        *(uint32_t*)(dl + off) = lw;
                    }
                } else if (MODE == 1) {
                    float v0 = a0 + bias[col];
                    float v1 = a1 + bias[col + 1];
                    const float* rp = res + (size_t)orow * N + col;
                    float2 rv = *(const float2*)rp;
                    *(float2*)(C + (size_t)orow * N + col) = make_float2(v0 + rv.x, v1 + rv.y);
                } else {
                    float v0 = fmaxf(a0 + bias[col], 0.0f);
                    float v1 = fmaxf(a1 + bias[col + 1], 0.0f);
                    uint32_t hw, lw; pack_pair(v0, v1, hw, lw);
                    *(uint32_t*)(Ch + (size_t)orow * N + col) = hw;
                    *(uint32_t*)(Cl + (size_t)orow * N + col) = lw;
                }
            }
        }
    }
}

// ======================= mma.sync flash attention ==========================
static constexpr int ATT_RS  = 144;
static constexpr int ATT_BUF = 64 * ATT_RS;
static constexpr int ATT_STG = 4 * ATT_BUF;
static constexpr int ATT_SMEM = 2 * ATT_STG;  // 73728

__global__ void __launch_bounds__(256, 2) attn_mma(
    const __nv_bfloat16* __restrict__ Qh, const __nv_bfloat16* __restrict__ Ql,
    const __nv_bfloat16* __restrict__ Kh, const __nv_bfloat16* __restrict__ Kl,
    const __nv_bfloat16* __restrict__ VTh, const __nv_bfloat16* __restrict__ VTl,
    __nv_bfloat16* __restrict__ Ch, __nv_bfloat16* __restrict__ Cl)
{
    extern __shared__ char sm[];
    const uint32_t sbu = smem_u32(sm);
    const int qt = blockIdx.x, h = blockIdx.y, b = blockIdx.z;
    const int tid = threadIdx.x, wid = tid >> 5, lane = tid & 31;

    const size_t bh = (size_t)b * HH + h;
    const __nv_bfloat16* gQh = Qh + (bh * SS + qt * 128) * DKK;
    const __nv_bfloat16* gQl = Ql + (bh * SS + qt * 128) * DKK;
    const __nv_bfloat16* gKh = Kh + bh * SS * DKK;
    const __nv_bfloat16* gKl = Kl + bh * SS * DKK;
    const __nv_bfloat16* gVh = VTh + bh * DKK * SS;
    const __nv_bfloat16* gVl = VTl + bh * DKK * SS;

    {
        #pragma unroll
        for (int i = 0; i < 8; i++) {
            int slot = (i << 8) + tid;
            int split = slot >> 10;
            int rem = slot & 1023;
            int r = rem >> 3, c = rem & 7;
            const __nv_bfloat16* src = (split ? gQl : gQh) + r * DKK + (c << 3);
            CP_ASYNC16(sbu + split * (128 * ATT_RS) + r * ATT_RS + (c << 4), src);
        }
        CP_COMMIT(); CP_WAIT(0);
        __syncthreads();
    }
    uint32_t qfh[4][4], qfl[4][4];
    {
        const uint32_t qa = sbu + (wid * 16 + (lane & 15)) * ATT_RS + ((lane >> 4) << 4);
        #pragma unroll
        for (int ks = 0; ks < 4; ks++) {
            ldm_x4(qfh[ks], qa + ks * 32);
            ldm_x4(qfl[ks], qa + 128 * ATT_RS + ks * 32);
        }
    }
    __syncthreads();

    auto load_kv = [&](int t0, int buf) {
        const uint32_t base = sbu + buf * ATT_STG;
        #pragma unroll
        for (int i = 0; i < 8; i++) {
            int slot = (i << 8) + tid;
            int arr = slot >> 9;
            int rem = slot & 511;
            int r = rem >> 3, c = rem & 7;
            const __nv_bfloat16* src;
            if (arr == 0)      src = gKh + (size_t)(t0 + r) * DKK + (c << 3);
            else if (arr == 1) src = gKl + (size_t)(t0 + r) * DKK + (c << 3);
            else if (arr == 2) src = gVh + (size_t)r * SS + t0 + (c << 3);
            else               src = gVl + (size_t)r * SS + t0 + (c << 3);
            CP_ASYNC16(base + arr * ATT_BUF + r * ATT_RS + (c << 4), src);
        }
        CP_COMMIT();
    };

    float ctx[8][4];
    #pragma unroll
    for (int nt = 0; nt < 8; nt++)
        #pragma unroll
        for (int j = 0; j < 4; j++) ctx[nt][j] = 0.0f;
    float m0 = -1e30f, m1 = -1e30f, l0 = 0.0f, l1 = 0.0f;

    const uint32_t bAddr = (uint32_t)(((((lane >> 4) << 3) | (lane & 7)) * ATT_RS)
                                      + ((lane >> 3) & 1) * 16);

    load_kv(0, 0);
    #pragma unroll 1
    for (int t = 0; t < SS / 64; t++) {
        if (t + 1 < SS / 64) { load_kv((t + 1) * 64, (t + 1) & 1); CP_WAIT(1); }
        else                 { CP_WAIT(0); }
        __syncthreads();
        const uint32_t base = sbu + (t & 1) * ATT_STG;

        float sa[8][4];
        #pragma unroll
        for (int nt = 0; nt < 8; nt++)
            #pragma unroll
            for (int j = 0; j < 4; j++) sa[nt][j] = 0.0f;
        #pragma unroll
        for (int ks = 0; ks < 4; ks++) {
            #pragma unroll
            for (int np = 0; np < 4; np++) {
                uint32_t kbh[4], kbl[4];
                ldm_x4(kbh, base + 0 * ATT_BUF + bAddr + np * 16 * ATT_RS + ks * 32);
                ldm_x4(kbl, base + 1 * ATT_BUF + bAddr + np * 16 * ATT_RS + ks * 32);
                mma_bf16(sa[2 * np],     qfh[ks], kbh);
                mma_bf16(sa[2 * np],     qfh[ks], kbl);
                mma_bf16(sa[2 * np],     qfl[ks], kbh);
                mma_bf16(sa[2 * np + 1], qfh[ks], kbh + 2);
                mma_bf16(sa[2 * np + 1], qfh[ks], kbl + 2);
                mma_bf16(sa[2 * np + 1], qfl[ks], kbh + 2);
            }
        }

        float rm0 = -1e30f, rm1 = -1e30f;
        #pragma unroll
        for (int nt = 0; nt < 8; nt++) {
            rm0 = fmaxf(rm0, fmaxf(sa[nt][0], sa[nt][1]));
            rm1 = fmaxf(rm1, fmaxf(sa[nt][2], sa[nt][3]));
        }
        rm0 = fmaxf(rm0, __shfl_xor_sync(0xFFFFFFFFu, rm0, 1));
        rm0 = fmaxf(rm0, __shfl_xor_sync(0xFFFFFFFFu, rm0, 2));
        rm1 = fmaxf(rm1, __shfl_xor_sync(0xFFFFFFFFu, rm1, 1));
        rm1 = fmaxf(rm1, __shfl_xor_sync(0xFFFFFFFFu, rm1, 2));
        const float nm0 = fmaxf(m0, rm0), nm1 = fmaxf(m1, rm1);
        const float c0 = ex2(m0 - nm0), c1 = ex2(m1 - nm1);
        l0 *= c0; l1 *= c1;
        #pragma unroll
        for (int nt = 0; nt < 8; nt++) {
            ctx[nt][0] *= c0; ctx[nt][1] *= c0;
            ctx[nt][2] *= c1; ctx[nt][3] *= c1;
        }
        float s0 = 0.0f, s1 = 0.0f;
        #pragma unroll
        for (int nt = 0; nt < 8; nt++) {
            float p0 = ex2(sa[nt][0] - nm0); sa[nt][0] = p0; s0 += p0;
            float p1 = ex2(sa[nt][1] - nm0); sa[nt][1] = p1; s0 += p1;
            float p2 = ex2(sa[nt][2] - nm1); sa[nt][2] = p2; s1 += p2;
            float p3 = ex2(sa[nt][3] - nm1); sa[nt][3] = p3; s1 += p3;
        }
        s0 += __shfl_xor_sync(0xFFFFFFFFu, s0, 1);
        s0 += __shfl_xor_sync(0xFFFFFFFFu, s0, 2);
        s1 += __shfl_xor_sync(0xFFFFFFFFu, s1, 1);
        s1 += __shfl_xor_sync(0xFFFFFFFFu, s1, 2);
        l0 += s0; l1 += s1; m0 = nm0; m1 = nm1;

        #pragma unroll
        for (int ks = 0; ks < 4; ks++) {
            uint32_t ah[4], al[4];
            pack_pair(sa[2 * ks][0],     sa[2 * ks][1],     ah[0], al[0]);
            pack_pair(sa[2 * ks][2],     sa[2 * ks][3],     ah[1], al[1]);
            pack_pair(sa[2 * ks + 1][0], sa[2 * ks + 1][1], ah[2], al[2]);
            pack_pair(sa[2 * ks + 1][2], sa[2 * ks + 1][3], ah[3], al[3]);
            #pragma unroll
            for (int np = 0; np < 4; np++) {
                uint32_t vbh[4], vbl[4];
                ldm_x4(vbh, base + 2 * ATT_BUF + bAddr + np * 16 * ATT_RS + ks * 32);
                ldm_x4(vbl, base + 3 * ATT_BUF + bAddr + np * 16 * ATT_RS + ks * 32);
                mma_bf16(ctx[2 * np],     ah, vbh);
                mma_bf16(ctx[2 * np],     al, vbh);
                mma_bf16(ctx[2 * np],     ah, vbl);
                mma_bf16(ctx[2 * np + 1], ah, vbh + 2);
                mma_bf16(ctx[2 * np + 1], al, vbh + 2);
                mma_bf16(ctx[2 * np + 1], ah, vbl + 2);
            }
        }
        __syncthreads();
    }

    const float i0 = 1.0f / l0, i1 = 1.0f / l1;
    const int g = lane >> 2, tc2 = (lane & 3) << 1;
    const int r0 = qt * 128 + wid * 16 + g;
    const size_t base0 = ((size_t)b * SS + r0) * DD + h * DKK;
    #pragma unroll
    for (int nt = 0; nt < 8; nt++) {
        const int col = nt * 8 + tc2;
        uint32_t hw, lw;
        pack_pair(ctx[nt][0] * i0, ctx[nt][1] * i0, hw, lw);
        *(uint32_t*)(Ch + base0 + col) = hw;
        *(uint32_t*)(Cl + base0 + col) = lw;
        pack_pair(ctx[nt][2] * i1, ctx[nt][3] * i1, hw, lw);
        *(uint32_t*)(Ch + base0 + (size_t)8 * DD + col) = hw;
        *(uint32_t*)(Cl + base0 + (size_t)8 * DD + col) = lw;
    }
}

// ======================= LayerNorm (optionally emits bf16 pair) ============
template<int WB>
__global__ __launch_bounds__(256)
void ln_k(const float* __restrict__ in, const float* __restrict__ w,
          const float* __restrict__ bsh, float* __restrict__ out,
          __nv_bfloat16* __restrict__ oh, __nv_bfloat16* __restrict__ ol)
{
    const size_t row = blockIdx.x;
    const float* x = in + row * DD;
    float s = 0.0f, s2 = 0.0f;
    for (int i = threadIdx.x; i < DD; i += 256) {
        float v = x[i]; s += v; s2 += v * v;
    }
    #pragma unroll
    for (int o = 16; o > 0; o >>= 1) {
        s  += __shfl_xor_sync(0xFFFFFFFFu, s,  o);
        s2 += __shfl_xor_sync(0xFFFFFFFFu, s2, o);
    }
    __shared__ float ws[8], ws2[8];
    const int wid = threadIdx.x >> 5, lane = threadIdx.x & 31;
    if (lane == 0) { ws[wid] = s; ws2[wid] = s2; }
    __syncthreads();
    float ts = 0.0f, ts2 = 0.0f;
    #pragma unroll
    for (int i = 0; i < 8; i++) { ts += ws[i]; ts2 += ws2[i]; }
    const float mu   = ts  * (1.0f / DD);
    const float var  = ts2 * (1.0f / DD) - mu * mu;
    const float rstd = rsqrtf(var + 1e-5f);
    for (int i = threadIdx.x; i < DD; i += 256) {
        float r = (x[i] - mu) * rstd * w[i] + bsh[i];
        out[row * DD + i] = r;
        if (WB) {
            __nv_bfloat16 h, l; split_bf16(r, h, l);
            oh[row * DD + i] = h; ol[row * DD + i] = l;
        }
    }
}

// ======================= launch ============================================
template<typename T>
static void* sym_addr(T& sym) {
    void* p = nullptr;
    cudaGetSymbolAddress(&p, sym);
    return p;
}

extern "C" void kernel_launch(void* const* d_in, const int* in_sizes, int n_in,
                              void* d_out, int out_size)
{
    const float* src  = (const float*)d_in[0];
    const float* Wq   = (const float*)d_in[1];
    const float* bq   = (const float*)d_in[2];
    const float* Wk   = (const float*)d_in[3];
    const float* bk   = (const float*)d_in[4];
    const float* Wv   = (const float*)d_in[5];
    const float* bv   = (const float*)d_in[6];
    const float* Wo   = (const float*)d_in[7];
    const float* bo   = (const float*)d_in[8];
    const float* ln1w = (const float*)d_in[9];
    const float* ln1b = (const float*)d_in[10];
    const float* W1   = (const float*)d_in[11];
    const float* b1   = (const float*)d_in[12];
    const float* W2   = (const float*)d_in[13];
    const float* b2   = (const float*)d_in[14];
    const float* ln2w = (const float*)d_in[15];
    const float* ln2b = (const float*)d_in[16];
    float* out = (float*)d_out;

    float* py   = (float*)sym_addr(g_y);
    float* px   = (float*)sym_addr(g_x);
    float* py2  = (float*)sym_addr(g_y2);

    __nv_bfloat16* srch = (__nv_bfloat16*)sym_addr(s_srch);
    __nv_bfloat16* srcl = (__nv_bfloat16*)sym_addr(s_srcl);
    __nv_bfloat16* ctxh = (__nv_bfloat16*)sym_addr(s_ctxh);
    __nv_bfloat16* ctxl = (__nv_bfloat16*)sym_addr(s_ctxl);
    __nv_bfloat16* xh   = (__nv_bfloat16*)sym_addr(s_xh);
    __nv_bfloat16* xl   = (__nv_bfloat16*)sym_addr(s_xl);
    __nv_bfloat16* ffh  = (__nv_bfloat16*)sym_addr(s_ffh);
    __nv_bfloat16* ffl  = (__nv_bfloat16*)sym_addr(s_ffl);
    __nv_bfloat16* qh   = (__nv_bfloat16*)sym_addr(a_qh);
    __nv_bfloat16* ql   = (__nv_bfloat16*)sym_addr(a_ql);
    __nv_bfloat16* kh   = (__nv_bfloat16*)sym_addr(a_kh);
    __nv_bfloat16* kl   = (__nv_bfloat16*)sym_addr(a_kl);
    __nv_bfloat16* vth  = (__nv_bfloat16*)sym_addr(a_vth);
    __nv_bfloat16* vtl  = (__nv_bfloat16*)sym_addr(a_vtl);
    __nv_bfloat16* wqkvh = (__nv_bfloat16*)sym_addr(w_qkvh);
    __nv_bfloat16* wqkvl = (__nv_bfloat16*)sym_addr(w_qkvl);
    __nv_bfloat16* woh  = (__nv_bfloat16*)sym_addr(w_oh);
    __nv_bfloat16* wol  = (__nv_bfloat16*)sym_addr(w_ol);
    __nv_bfloat16* w1h  = (__nv_bfloat16*)sym_addr(w_1h);
    __nv_bfloat16* w1l  = (__nv_bfloat16*)sym_addr(w_1l);
    __nv_bfloat16* w2h  = (__nv_bfloat16*)sym_addr(w_2h);
    __nv_bfloat16* w2l  = (__nv_bfloat16*)sym_addr(w_2l);

    cudaFuncSetAttribute((const void*)gemm_mma<4,128>, cudaFuncAttributeMaxDynamicSharedMemorySize, GP<128>::SMEM);
    cudaFuncSetAttribute((const void*)gemm_mma<2,128>, cudaFuncAttributeMaxDynamicSharedMemorySize, GP<128>::SMEM);
    cudaFuncSetAttribute((const void*)gemm_mma<1,64>,  cudaFuncAttributeMaxDynamicSharedMemorySize, GP<64>::SMEM);
    cudaFuncSetAttribute((const void*)attn_mma,        cudaFuncAttributeMaxDynamicSharedMemorySize, ATT_SMEM);

    // weight repack + activation split (smem-tiled transposes)
    cvt_pair<<<(MROWS*DD + 255)/256, 256>>>(src, srch, srcl, MROWS*DD);
    repack_qkvw<<<dim3(DKK/32, DD/32, 3*HH), dim3(32,8)>>>(Wq, Wk, Wv);
    repack_T2<<<dim3(DD/32, DD/32),  dim3(32,8)>>>(Wo, woh, wol, DD, DD);
    repack_T2<<<dim3(DFF/32, DD/32), dim3(32,8)>>>(W1, w1h, w1l, DFF, DD);
    repack_T2<<<dim3(DD/32, DFF/32), dim3(32,8)>>>(W2, w2h, w2l, DD, DFF);

    // fused QKV projection (N=2304); epilogue scatters Q (scaled), K, V^T
    gemm_mma<4,128><<<dim3(3*DD/128, MROWS/128), 256, GP<128>::SMEM>>>(
        srch, srcl, wqkvh, wqkvl, bq, bk, (float*)bv, nullptr, nullptr, MROWS, 3*DD, DD);

    // flash attention -> ctx split pair [B,S,H*DK]
    attn_mma<<<dim3(SS/128, HH, BB), 256, ATT_SMEM>>>(qh, ql, kh, kl, vth, vtl, ctxh, ctxl);

    // out projection + residual -> y ; LN1 -> x (+ bf16 pair)   (BN=64)
    gemm_mma<1,64><<<dim3(DD/64, MROWS/128), 256, GP<64>::SMEM>>>(
        ctxh, ctxl, woh, wol, bo, src, py, nullptr, nullptr, MROWS, DD, DD);
    ln_k<1><<<MROWS, 256>>>(py, ln1w, ln1b, px, xh, xl);

    // FFN: FF1 (BN=128), FF2 (K=3072 -> BN=64 for tile granularity)
    gemm_mma<2,128><<<dim3(DFF/128, MROWS/128), 256, GP<128>::SMEM>>>(
        xh, xl, w1h, w1l, b1, nullptr, nullptr, ffh, ffl, MROWS, DFF, DD);
    gemm_mma<1,64><<<dim3(DD/64, MROWS/128), 256, GP<64>::SMEM>>>(
        ffh, ffl, w2h, w2l, b2, px, py2, nullptr, nullptr, MROWS, DD, DFF);

    // LN2 -> output
    ln_k<0><<<MROWS, 256>>>(py2, ln2w, ln2b, out, nullptr, nullptr);
}

// round 8
// speedup vs baseline: 5.0646x; 1.4004x over previous
#include <cuda_runtime.h>
#include <cuda_fp16.h>
#include <cstdint>
#include <math.h>

#define BB 2
#define SS 2048
#define DD 768
#define HH 12
#define DKK 64
#define DFF 3072
#define MROWS (BB*SS)   // 4096

// ======================= device scratch (no allocs allowed) ================
__device__ float g_y[MROWS*DD];
__device__ float g_x[MROWS*DD];
__device__ float g_y2[MROWS*DD];
// fp16 activations (A-side: single precision; B-side needs pairs)
__device__ __half s_srch[MROWS*DD];
__device__ __half s_ctxh[MROWS*DD];
__device__ __half s_xh[MROWS*DD];
__device__ __half s_ffh[MROWS*DFF];
__device__ __half a_q[BB*HH*SS*DKK];
__device__ __half a_kh[BB*HH*SS*DKK], a_kl[BB*HH*SS*DKK];
__device__ __half a_vh[BB*HH*SS*DKK], a_vl[BB*HH*SS*DKK];
// fp16 weight hi/lo pairs
__device__ __half w_qkvh[3*DD*DD], w_qkvl[3*DD*DD];   // [2304, 768]
__device__ __half w_oh[DD*DD], w_ol[DD*DD];
__device__ __half w_1h[DFF*DD], w_1l[DFF*DD];
__device__ __half w_2h[DD*DFF], w_2l[DD*DFF];

// ======================= PTX helpers (stable ISA only) =====================
__device__ __forceinline__ uint32_t smem_u32(const void* p) {
    uint32_t a;
    asm("{ .reg .u64 t; cvta.to.shared.u64 t, %1; cvt.u32.u64 %0, t; }" : "=r"(a) : "l"(p));
    return a;
}
#define CP_ASYNC16(dst, src) \
    asm volatile("cp.async.cg.shared.global [%0], [%1], 16;" :: "r"(dst), "l"(src) : "memory")
#define CP_COMMIT() asm volatile("cp.async.commit_group;" ::: "memory")
#define CP_WAIT(n)  asm volatile("cp.async.wait_group %0;" :: "n"(n) : "memory")

__device__ __forceinline__ void ldm_x4(uint32_t* r, uint32_t addr) {
    asm volatile("ldmatrix.sync.aligned.m8n8.x4.shared.b16 {%0,%1,%2,%3}, [%4];"
        : "=r"(r[0]), "=r"(r[1]), "=r"(r[2]), "=r"(r[3]) : "r"(addr));
}
__device__ __forceinline__ void ldm_x4_t(uint32_t* r, uint32_t addr) {
    asm volatile("ldmatrix.sync.aligned.m8n8.x4.trans.shared.b16 {%0,%1,%2,%3}, [%4];"
        : "=r"(r[0]), "=r"(r[1]), "=r"(r[2]), "=r"(r[3]) : "r"(addr));
}
__device__ __forceinline__ void mma_f16(float* c, const uint32_t* a, const uint32_t* b) {
    asm volatile("mma.sync.aligned.m16n8k16.row.col.f32.f16.f16.f32 "
        "{%0,%1,%2,%3}, {%4,%5,%6,%7}, {%8,%9}, {%0,%1,%2,%3};"
        : "+f"(c[0]), "+f"(c[1]), "+f"(c[2]), "+f"(c[3])
        : "r"(a[0]), "r"(a[1]), "r"(a[2]), "r"(a[3]), "r"(b[0]), "r"(b[1]));
}
__device__ __forceinline__ float ex2(float x) {
    float y; asm("ex2.approx.ftz.f32 %0, %1;" : "=f"(y) : "f"(x)); return y;
}
// pack two floats into one f16x2 word (v0 -> low half)
__device__ __forceinline__ uint32_t pack_h2(float v0, float v1) {
    uint32_t r;
    asm("cvt.rn.f16x2.f32 %0, %1, %2;" : "=r"(r) : "f"(v1), "f"(v0));
    return r;
}
// hi f16x2 + residual-lo f16x2
__device__ __forceinline__ void split_pack(float v0, float v1, uint32_t& ph, uint32_t& pl) {
    ph = pack_h2(v0, v1);
    __half2 h = *reinterpret_cast<__half2*>(&ph);
    float r0 = v0 - __low2float(h);
    float r1 = v1 - __high2float(h);
    pl = pack_h2(r0, r1);
}
__device__ __forceinline__ void split_h(float v, __half& h, __half& l) {
    h = __float2half_rn(v);
    l = __float2half_rn(v - __half2float(h));
}

static __device__ __constant__ const float QSCALE_D = 0.125f * 1.44269504088896340736f;

// ======================= conversion / repack kernels =======================
__global__ void cvt_half(const float* __restrict__ in, __half* __restrict__ o, int n) {
    int i = blockIdx.x * 256 + threadIdx.x;
    if (i >= n) return;
    o[i] = __float2half_rn(in[i]);
}

// W [K, N] row-major -> (oh,ol) [N, K] fp16 pair; smem-tiled, block (32,8)
__global__ void repack_T2(const float* __restrict__ W,
                          __half* __restrict__ oh, __half* __restrict__ ol,
                          int N, int K) {
    __shared__ float t[32][33];
    const int n0 = blockIdx.x * 32, k0 = blockIdx.y * 32;
    const int tx = threadIdx.x, ty = threadIdx.y;
    #pragma unroll
    for (int r = 0; r < 4; r++)
        t[ty + 8 * r][tx] = W[(size_t)(k0 + ty + 8 * r) * N + n0 + tx];
    __syncthreads();
    #pragma unroll
    for (int r = 0; r < 4; r++) {
        float v = t[tx][ty + 8 * r];
        __half h, l; split_h(v, h, l);
        size_t o = (size_t)(n0 + ty + 8 * r) * K + k0 + tx;
        oh[o] = h; ol[o] = l;
    }
}

// Wq/Wk/Wv [H,D,DK] -> w_qkv [2304, 768] fp16 pair
__global__ void repack_qkvw(const float* __restrict__ Wq, const float* __restrict__ Wk,
                            const float* __restrict__ Wv) {
    __shared__ float t[32][33];
    const int sel = blockIdx.z / HH, h = blockIdx.z % HH;
    const float* W = (sel == 0 ? Wq : sel == 1 ? Wk : Wv) + (size_t)h * DD * DKK;
    const int dk0 = blockIdx.x * 32, d0 = blockIdx.y * 32;
    const int tx = threadIdx.x, ty = threadIdx.y;
    #pragma unroll
    for (int r = 0; r < 4; r++)
        t[ty + 8 * r][tx] = W[(size_t)(d0 + ty + 8 * r) * DKK + dk0 + tx];
    __syncthreads();
    #pragma unroll
    for (int r = 0; r < 4; r++) {
        float v = t[tx][ty + 8 * r];
        __half hh, ll; split_h(v, hh, ll);
        size_t row = (size_t)sel * DD + h * DKK + dk0 + ty + 8 * r;
        w_qkvh[row * DD + d0 + tx] = hh;
        w_qkvl[row * DD + d0 + tx] = ll;
    }
}

// ======================= mma.sync 2-term split-fp16 GEMM ===================
// C[M,N] = A_h[M,K] @ (Bh+Bl)[N,K]^T   (A-low term dropped; ~2^-11 rel err)
// MODE 1: acc + bias + res -> fp32 row-major
// MODE 2: relu(acc+bias) -> single fp16 row-major
// MODE 4: fused QKV epilogue: Q scaled single fp16, K pair, V pair, all [B,H,S,DK]
static constexpr int RS = 80;   // 32 fp16 (64B) + 16B pad

template<int BN> struct GP {
    static constexpr int A_BYTES = 128 * RS;
    static constexpr int B_BYTES = BN * RS;
    static constexpr int STGB    = A_BYTES + 2 * B_BYTES;
    static constexpr int SMEM    = 2 * STGB;
    static constexpr int NTW     = BN / 16;
    static constexpr int NPB     = BN / 32;
    static constexpr int CPT     = (512 + 8 * BN) / 256;
};

template<int MODE, int BN>
__global__ void __launch_bounds__(256, 1) gemm_mma(
    const __half* __restrict__ A,
    const __half* __restrict__ Bh, const __half* __restrict__ Bl,
    const float* __restrict__ bias, const float* __restrict__ res,
    float* __restrict__ C, __half* __restrict__ Cs,
    int M, int N, int K)
{
    using P = GP<BN>;
    extern __shared__ char sb[];
    const uint32_t sbu = smem_u32(sb);
    const int tid  = threadIdx.x;
    const int wid  = tid >> 5;
    const int lane = tid & 31;
    const int wm   = wid & 3;
    const int wn   = wid >> 2;

    const int rowBase = blockIdx.y << 7;
    const int colBase = blockIdx.x * BN;
    const __half* gA  = A  + (size_t)rowBase * K;
    const __half* gBh = Bh + (size_t)colBase * K;
    const __half* gBl = Bl + (size_t)colBase * K;

    int ld_mat[P::CPT], ld_r[P::CPT], ld_q[P::CPT];
    #pragma unroll
    for (int i = 0; i < P::CPT; i++) {
        int slot = (i << 8) + tid;
        int mat, rem;
        if (slot < 512) { mat = 0; rem = slot; }
        else { int t = slot - 512; mat = 1 + t / (4 * BN); rem = t % (4 * BN); }
        ld_mat[i] = mat; ld_r[i] = rem >> 2; ld_q[i] = rem & 3;
    }

    const uint32_t OFF_M[3] = { 0u, (uint32_t)P::A_BYTES, (uint32_t)(P::A_BYTES + P::B_BYTES) };

    auto load_stage = [&](int kc, int buf) {
        const uint32_t base = sbu + buf * P::STGB;
        #pragma unroll
        for (int i = 0; i < P::CPT; i++) {
            const __half* src = (ld_mat[i] == 0 ? gA : ld_mat[i] == 1 ? gBh : gBl)
                                + (size_t)ld_r[i] * K + kc + (ld_q[i] << 3);
            uint32_t dst = base + OFF_M[ld_mat[i]] + ld_r[i] * RS + (ld_q[i] << 4);
            CP_ASYNC16(dst, src);
        }
        CP_COMMIT();
    };

    float acc[2][P::NTW][4];
    #pragma unroll
    for (int mt = 0; mt < 2; mt++)
        #pragma unroll
        for (int nt = 0; nt < P::NTW; nt++)
            #pragma unroll
            for (int j = 0; j < 4; j++) acc[mt][nt][j] = 0.0f;

    const uint32_t aAddr = (uint32_t)((wm * 32 + (lane & 15)) * RS + (lane >> 4) * 16);
    const uint32_t bAddr = (uint32_t)((wn * (BN/2) + ((lane >> 4) << 3) + (lane & 7)) * RS
                                      + ((lane >> 3) & 1) * 16);

    const int nStages = K >> 5;
    load_stage(0, 0);

    for (int c = 0; c < nStages; c++) {
        if (c + 1 < nStages) load_stage((c + 1) << 5, (c + 1) & 1);
        if (c + 1 < nStages) { CP_WAIT(1); } else { CP_WAIT(0); }
        __syncthreads();

        const uint32_t base = sbu + (c & 1) * P::STGB;
        #pragma unroll
        for (int ks = 0; ks < 2; ks++) {
            const uint32_t ko = ks * 32;
            uint32_t bh[P::NTW*2], bl[P::NTW*2];
            #pragma unroll
            for (int np = 0; np < P::NPB; np++) {
                ldm_x4(bh + np * 4, base + OFF_M[1] + bAddr + np * 16 * RS + ko);
                ldm_x4(bl + np * 4, base + OFF_M[2] + bAddr + np * 16 * RS + ko);
            }
            #pragma unroll
            for (int mt = 0; mt < 2; mt++) {
                uint32_t ah[4];
                ldm_x4(ah, base + OFF_M[0] + aAddr + mt * 16 * RS + ko);
                #pragma unroll
                for (int nt = 0; nt < P::NTW; nt++) {
                    mma_f16(acc[mt][nt], ah, bh + nt * 2);
                    mma_f16(acc[mt][nt], ah, bl + nt * 2);
                }
            }
        }
        __syncthreads();
    }

    // ---------------- epilogue ----------------
    const int g  = lane >> 2;
    const int tc = (lane & 3) << 1;

    #pragma unroll
    for (int mt = 0; mt < 2; mt++) {
        #pragma unroll
        for (int half_i = 0; half_i < 2; half_i++) {
            const int orow = rowBase + wm * 32 + mt * 16 + g + half_i * 8;
            #pragma unroll
            for (int nt = 0; nt < P::NTW; nt++) {
                const int col = colBase + wn * (BN/2) + nt * 8 + tc;
                float a0 = acc[mt][nt][half_i * 2 + 0];
                float a1 = acc[mt][nt][half_i * 2 + 1];
                if (MODE == 4) {
                    const int sel = col / DD;
                    const int lc  = col - sel * DD;
                    const float* bptr = sel == 0 ? bias : sel == 1 ? res : (const float*)C;
                    float v0 = a0 + bptr[lc];
                    float v1 = a1 + bptr[lc + 1];
                    const int b = orow >> 11, s = orow & 2047;
                    const int h = lc >> 6, dk = lc & 63;
                    size_t off = (((size_t)b * HH + h) * SS + s) * DKK + dk;
                    if (sel == 0) {
                        v0 *= QSCALE_D; v1 *= QSCALE_D;
                        *(uint32_t*)(a_q + off) = pack_h2(v0, v1);
                    } else {
                        uint32_t hw, lw; split_pack(v0, v1, hw, lw);
                        __half* dh = sel == 1 ? a_kh : a_vh;
                        __half* dl = sel == 1 ? a_kl : a_vl;
                        *(uint32_t*)(dh + off) = hw;
                        *(uint32_t*)(dl + off) = lw;
                    }
                } else if (MODE == 1) {
                    float v0 = a0 + bias[col];
                    float v1 = a1 + bias[col + 1];
                    const float* rp = res + (size_t)orow * N + col;
                    float2 rv = *(const float2*)rp;
                    *(float2*)(C + (size_t)orow * N + col) = make_float2(v0 + rv.x, v1 + rv.y);
                } else {
                    float v0 = fmaxf(a0 + bias[col], 0.0f);
                    float v1 = fmaxf(a1 + bias[col + 1], 0.0f);
                    *(uint32_t*)(Cs + (size_t)orow * N + col) = pack_h2(v0, v1);
                }
            }
        }
    }
}

// ======================= mma.sync flash attention (fp16) ===================
// Q single fp16 (A-side), K/V pairs (B-side). V in [S,DK]; PV B-frags via
// ldmatrix.trans (row-major B path). 128 queries/CTA, 64-key tiles, dbl-buf.
static constexpr int ATT_RS  = 144;           // 64 fp16 = 128B + 16B pad
static constexpr int ATT_BUF = 64 * ATT_RS;   // 9216
static constexpr int ATT_STG = 4 * ATT_BUF;   // 36864 (Kh,Kl,Vh,Vl)
static constexpr int ATT_SMEM = 2 * ATT_STG;  // 73728

__global__ void __launch_bounds__(256, 2) attn_mma(
    const __half* __restrict__ Q,
    const __half* __restrict__ Kh, const __half* __restrict__ Kl,
    const __half* __restrict__ Vh, const __half* __restrict__ Vl,
    __half* __restrict__ Cs)
{
    extern __shared__ char sm[];
    const uint32_t sbu = smem_u32(sm);
    const int qt = blockIdx.x, h = blockIdx.y, b = blockIdx.z;
    const int tid = threadIdx.x, wid = tid >> 5, lane = tid & 31;

    const size_t bh = (size_t)b * HH + h;
    const __half* gQ  = Q  + (bh * SS + qt * 128) * DKK;
    const __half* gKh = Kh + bh * SS * DKK;
    const __half* gKl = Kl + bh * SS * DKK;
    const __half* gVh = Vh + bh * SS * DKK;
    const __half* gVl = Vl + bh * SS * DKK;

    // ---- stage Q tile (128x64 fp16) and extract A-frags ----
    {
        #pragma unroll
        for (int i = 0; i < 4; i++) {
            int slot = (i << 8) + tid;          // 0..1023
            int r = slot >> 3, c = slot & 7;
            CP_ASYNC16(sbu + r * ATT_RS + (c << 4), gQ + r * DKK + (c << 3));
        }
        CP_COMMIT(); CP_WAIT(0);
        __syncthreads();
    }
    uint32_t qf[4][4];
    {
        const uint32_t qa = sbu + (wid * 16 + (lane & 15)) * ATT_RS + ((lane >> 4) << 4);
        #pragma unroll
        for (int ks = 0; ks < 4; ks++) ldm_x4(qf[ks], qa + ks * 32);
    }
    __syncthreads();

    auto load_kv = [&](int t0, int buf) {
        const uint32_t base = sbu + buf * ATT_STG;
        #pragma unroll
        for (int i = 0; i < 8; i++) {
            int slot = (i << 8) + tid;          // 0..2047
            int arr = slot >> 9;                // 0 Kh,1 Kl,2 Vh,3 Vl
            int rem = slot & 511;
            int r = rem >> 3, c = rem & 7;
            const __half* src = (arr == 0 ? gKh : arr == 1 ? gKl : arr == 2 ? gVh : gVl)
                                + (size_t)(t0 + r) * DKK + (c << 3);
            CP_ASYNC16(base + arr * ATT_BUF + r * ATT_RS + (c << 4), src);
        }
        CP_COMMIT();
    };

    float ctx[8][4];
    #pragma unroll
    for (int nt = 0; nt < 8; nt++)
        #pragma unroll
        for (int j = 0; j < 4; j++) ctx[nt][j] = 0.0f;
    float m0 = -1e30f, m1 = -1e30f, l0 = 0.0f, l1 = 0.0f;

    // K (non-trans, [n=key][k=dk] K-contig) frag address
    const uint32_t kAddr = (uint32_t)(((((lane >> 4) << 3) | (lane & 7)) * ATT_RS)
                                      + ((lane >> 3) & 1) * 16);
    // V (trans, [k=key][n=dk] row-major) frag address: row = key, col-block = dk
    const uint32_t vAddr = (uint32_t)((lane & 15) * ATT_RS + ((lane >> 4) << 4));

    load_kv(0, 0);
    #pragma unroll 1
    for (int t = 0; t < SS / 64; t++) {
        if (t + 1 < SS / 64) { load_kv((t + 1) * 64, (t + 1) & 1); CP_WAIT(1); }
        else                 { CP_WAIT(0); }
        __syncthreads();
        const uint32_t base = sbu + (t & 1) * ATT_STG;

        // ---- S = Q @ K^T (2-term: q_h * (k_h + k_l)) ----
        float sa[8][4];
        #pragma unroll
        for (int nt = 0; nt < 8; nt++)
            #pragma unroll
            for (int j = 0; j < 4; j++) sa[nt][j] = 0.0f;
        #pragma unroll
        for (int ks = 0; ks < 4; ks++) {
            #pragma unroll
            for (int np = 0; np < 4; np++) {
                uint32_t kbh[4], kbl[4];
                ldm_x4(kbh, base + 0 * ATT_BUF + kAddr + np * 16 * ATT_RS + ks * 32);
                ldm_x4(kbl, base + 1 * ATT_BUF + kAddr + np * 16 * ATT_RS + ks * 32);
                mma_f16(sa[2 * np],     qf[ks], kbh);
                mma_f16(sa[2 * np],     qf[ks], kbl);
                mma_f16(sa[2 * np + 1], qf[ks], kbh + 2);
                mma_f16(sa[2 * np + 1], qf[ks], kbl + 2);
            }
        }

        // ---- online softmax (base-2) ----
        float rm0 = -1e30f, rm1 = -1e30f;
        #pragma unroll
        for (int nt = 0; nt < 8; nt++) {
            rm0 = fmaxf(rm0, fmaxf(sa[nt][0], sa[nt][1]));
            rm1 = fmaxf(rm1, fmaxf(sa[nt][2], sa[nt][3]));
        }
        rm0 = fmaxf(rm0, __shfl_xor_sync(0xFFFFFFFFu, rm0, 1));
        rm0 = fmaxf(rm0, __shfl_xor_sync(0xFFFFFFFFu, rm0, 2));
        rm1 = fmaxf(rm1, __shfl_xor_sync(0xFFFFFFFFu, rm1, 1));
        rm1 = fmaxf(rm1, __shfl_xor_sync(0xFFFFFFFFu, rm1, 2));
        const float nm0 = fmaxf(m0, rm0), nm1 = fmaxf(m1, rm1);
        const float c0 = ex2(m0 - nm0), c1 = ex2(m1 - nm1);
        l0 *= c0; l1 *= c1;
        #pragma unroll
        for (int nt = 0; nt < 8; nt++) {
            ctx[nt][0] *= c0; ctx[nt][1] *= c0;
            ctx[nt][2] *= c1; ctx[nt][3] *= c1;
        }
        float s0 = 0.0f, s1 = 0.0f;
        #pragma unroll
        for (int nt = 0; nt < 8; nt++) {
            float p0 = ex2(sa[nt][0] - nm0); sa[nt][0] = p0; s0 += p0;
            float p1 = ex2(sa[nt][1] - nm0); sa[nt][1] = p1; s0 += p1;
            float p2 = ex2(sa[nt][2] - nm1); sa[nt][2] = p2; s1 += p2;
            float p3 = ex2(sa[nt][3] - nm1); sa[nt][3] = p3; s1 += p3;
        }
        s0 += __shfl_xor_sync(0xFFFFFFFFu, s0, 1);
        s0 += __shfl_xor_sync(0xFFFFFFFFu, s0, 2);
        s1 += __shfl_xor_sync(0xFFFFFFFFu, s1, 1);
        s1 += __shfl_xor_sync(0xFFFFFFFFu, s1, 2);
        l0 += s0; l1 += s1; m0 = nm0; m1 = nm1;

        // ---- ctx += P @ V  (P single fp16 A-frags from S registers;
        //      V B-frags via ldmatrix.trans; 2-term p*(v_h+v_l)) ----
        #pragma unroll
        for (int ks = 0; ks < 4; ks++) {
            uint32_t ph[4];
            ph[0] = pack_h2(sa[2 * ks][0],     sa[2 * ks][1]);
            ph[1] = pack_h2(sa[2 * ks][2],     sa[2 * ks][3]);
            ph[2] = pack_h2(sa[2 * ks + 1][0], sa[2 * ks + 1][1]);
            ph[3] = pack_h2(sa[2 * ks + 1][2], sa[2 * ks + 1][3]);
            const uint32_t vrow = vAddr + ks * 16 * ATT_RS;
            #pragma unroll
            for (int np = 0; np < 4; np++) {
                uint32_t vbh[4], vbl[4];
                ldm_x4_t(vbh, base + 2 * ATT_BUF + vrow + np * 32);
                ldm_x4_t(vbl, base + 3 * ATT_BUF + vrow + np * 32);
                mma_f16(ctx[2 * np],     ph, vbh);
                mma_f16(ctx[2 * np],     ph, vbl);
                mma_f16(ctx[2 * np + 1], ph, vbh + 2);
                mma_f16(ctx[2 * np + 1], ph, vbl + 2);
            }
        }
        __syncthreads();
    }

    // ---- epilogue: ctx/l -> single fp16 [B, S, H*DK] ----
    const float i0 = 1.0f / l0, i1 = 1.0f / l1;
    const int g = lane >> 2, tc2 = (lane & 3) << 1;
    const int r0 = qt * 128 + wid * 16 + g;
    const size_t base0 = ((size_t)b * SS + r0) * DD + h * DKK;
    #pragma unroll
    for (int nt = 0; nt < 8; nt++) {
        const int col = nt * 8 + tc2;
        *(uint32_t*)(Cs + base0 + col) = pack_h2(ctx[nt][0] * i0, ctx[nt][1] * i0);
        *(uint32_t*)(Cs + base0 + (size_t)8 * DD + col) = pack_h2(ctx[nt][2] * i1, ctx[nt][3] * i1);
    }
}

// ======================= LayerNorm (optionally emits fp16) =================
template<int WB>
__global__ __launch_bounds__(256)
void ln_k(const float* __restrict__ in, const float* __restrict__ w,
          const float* __restrict__ bsh, float* __restrict__ out,
          __half* __restrict__ oh)
{
    const size_t row = blockIdx.x;
    const float* x = in + row * DD;
    float s = 0.0f, s2 = 0.0f;
    for (int i = threadIdx.x; i < DD; i += 256) {
        float v = x[i]; s += v; s2 += v * v;
    }
    #pragma unroll
    for (int o = 16; o > 0; o >>= 1) {
        s  += __shfl_xor_sync(0xFFFFFFFFu, s,  o);
        s2 += __shfl_xor_sync(0xFFFFFFFFu, s2, o);
    }
    __shared__ float ws[8], ws2[8];
    const int wid = threadIdx.x >> 5, lane = threadIdx.x & 31;
    if (lane == 0) { ws[wid] = s; ws2[wid] = s2; }
    __syncthreads();
    float ts = 0.0f, ts2 = 0.0f;
    #pragma unroll
    for (int i = 0; i < 8; i++) { ts += ws[i]; ts2 += ws2[i]; }
    const float mu   = ts  * (1.0f / DD);
    const float var  = ts2 * (1.0f / DD) - mu * mu;
    const float rstd = rsqrtf(var + 1e-5f);
    for (int i = threadIdx.x; i < DD; i += 256) {
        float r = (x[i] - mu) * rstd * w[i] + bsh[i];
        out[row * DD + i] = r;
        if (WB) oh[row * DD + i] = __float2half_rn(r);
    }
}

// ======================= launch ============================================
template<typename T>
static void* sym_addr(T& sym) {
    void* p = nullptr;
    cudaGetSymbolAddress(&p, sym);
    return p;
}

extern "C" void kernel_launch(void* const* d_in, const int* in_sizes, int n_in,
                              void* d_out, int out_size)
{
    const float* src  = (const float*)d_in[0];
    const float* Wq   = (const float*)d_in[1];
    const float* bq   = (const float*)d_in[2];
    const float* Wk   = (const float*)d_in[3];
    const float* bk   = (const float*)d_in[4];
    const float* Wv   = (const float*)d_in[5];
    const float* bv   = (const float*)d_in[6];
    const float* Wo   = (const float*)d_in[7];
    const float* bo   = (const float*)d_in[8];
    const float* ln1w = (const float*)d_in[9];
    const float* ln1b = (const float*)d_in[10];
    const float* W1   = (const float*)d_in[11];
    const float* b1   = (const float*)d_in[12];
    const float* W2   = (const float*)d_in[13];
    const float* b2   = (const float*)d_in[14];
    const float* ln2w = (const float*)d_in[15];
    const float* ln2b = (const float*)d_in[16];
    float* out = (float*)d_out;

    float* py   = (float*)sym_addr(g_y);
    float* px   = (float*)sym_addr(g_x);
    float* py2  = (float*)sym_addr(g_y2);

    __half* srch = (__half*)sym_addr(s_srch);
    __half* ctxh = (__half*)sym_addr(s_ctxh);
    __half* xh   = (__half*)sym_addr(s_xh);
    __half* ffh  = (__half*)sym_addr(s_ffh);
    __half* q1   = (__half*)sym_addr(a_q);
    __half* kh   = (__half*)sym_addr(a_kh);
    __half* kl   = (__half*)sym_addr(a_kl);
    __half* vh   = (__half*)sym_addr(a_vh);
    __half* vl   = (__half*)sym_addr(a_vl);
    __half* wqkvh = (__half*)sym_addr(w_qkvh);
    __half* wqkvl = (__half*)sym_addr(w_qkvl);
    __half* woh  = (__half*)sym_addr(w_oh);
    __half* wol  = (__half*)sym_addr(w_ol);
    __half* w1h  = (__half*)sym_addr(w_1h);
    __half* w1l  = (__half*)sym_addr(w_1l);
    __half* w2h  = (__half*)sym_addr(w_2h);
    __half* w2l  = (__half*)sym_addr(w_2l);

    cudaFuncSetAttribute((const void*)gemm_mma<4,128>, cudaFuncAttributeMaxDynamicSharedMemorySize, GP<128>::SMEM);
    cudaFuncSetAttribute((const void*)gemm_mma<2,64>,  cudaFuncAttributeMaxDynamicSharedMemorySize, GP<64>::SMEM);
    cudaFuncSetAttribute((const void*)gemm_mma<1,64>,  cudaFuncAttributeMaxDynamicSharedMemorySize, GP<64>::SMEM);
    cudaFuncSetAttribute((const void*)attn_mma,        cudaFuncAttributeMaxDynamicSharedMemorySize, ATT_SMEM);

    // preprocessing
    cvt_half<<<(MROWS*DD + 255)/256, 256>>>(src, srch, MROWS*DD);
    repack_qkvw<<<dim3(DKK/32, DD/32, 3*HH), dim3(32,8)>>>(Wq, Wk, Wv);
    repack_T2<<<dim3(DD/32, DD/32),  dim3(32,8)>>>(Wo, woh, wol, DD, DD);
    repack_T2<<<dim3(DFF/32, DD/32), dim3(32,8)>>>(W1, w1h, w1l, DFF, DD);
    repack_T2<<<dim3(DD/32, DFF/32), dim3(32,8)>>>(W2, w2h, w2l, DD, DFF);

    // fused QKV projection (N=2304): Q single (scaled), K pair, V pair
    gemm_mma<4,128><<<dim3(3*DD/128, MROWS/128), 256, GP<128>::SMEM>>>(
        srch, wqkvh, wqkvl, bq, bk, (float*)bv, nullptr, MROWS, 3*DD, DD);

    // flash attention -> ctx single fp16 [B,S,H*DK]
    attn_mma<<<dim3(SS/128, HH, BB), 256, ATT_SMEM>>>(q1, kh, kl, vh, vl, ctxh);

    // out projection + residual -> y ; LN1 -> x (+ fp16)
    gemm_mma<1,64><<<dim3(DD/64, MROWS/128), 256, GP<64>::SMEM>>>(
        ctxh, woh, wol, bo, src, py, nullptr, MROWS, DD, DD);
    ln_k<1><<<MROWS, 256>>>(py, ln1w, ln1b, px, xh);

    // FFN
    gemm_mma<2,64><<<dim3(DFF/64, MROWS/128), 256, GP<64>::SMEM>>>(
        xh, w1h, w1l, b1, nullptr, nullptr, ffh, MROWS, DFF, DD);
    gemm_mma<1,64><<<dim3(DD/64, MROWS/128), 256, GP<64>::SMEM>>>(
        ffh, w2h, w2l, b2, px, py2, nullptr, MROWS, DD, DFF);

    // LN2 -> output
    ln_k<0><<<MROWS, 256>>>(py2, ln2w, ln2b, out, nullptr);
}

// round 9
// speedup vs baseline: 7.3457x; 1.4504x over previous
#include <cuda_runtime.h>
#include <cuda_fp16.h>
#include <cstdint>
#include <math.h>

#define BB 2
#define SS 2048
#define DD 768
#define HH 12
#define DKK 64
#define DFF 3072
#define MROWS (BB*SS)   // 4096

// ======================= device scratch (no allocs allowed) ================
__device__ float g_y[MROWS*DD];
__device__ float g_x[MROWS*DD];
__device__ float g_y2[MROWS*DD];
// fp16 activations / weights (single precision everywhere)
__device__ __half s_srch[MROWS*DD];
__device__ __half s_ctxh[MROWS*DD];
__device__ __half s_xh[MROWS*DD];
__device__ __half s_ffh[MROWS*DFF];
__device__ __half a_q[BB*HH*SS*DKK];
__device__ __half a_k[BB*HH*SS*DKK];
__device__ __half a_v[BB*HH*SS*DKK];
__device__ __half w_qkv[3*DD*DD];   // [2304, 768]
__device__ __half w_o[DD*DD];
__device__ __half w_1[DFF*DD];
__device__ __half w_2[DD*DFF];

// ======================= PTX helpers (stable ISA only) =====================
__device__ __forceinline__ uint32_t smem_u32(const void* p) {
    uint32_t a;
    asm("{ .reg .u64 t; cvta.to.shared.u64 t, %1; cvt.u32.u64 %0, t; }" : "=r"(a) : "l"(p));
    return a;
}
#define CP_ASYNC16(dst, src) \
    asm volatile("cp.async.cg.shared.global [%0], [%1], 16;" :: "r"(dst), "l"(src) : "memory")
#define CP_COMMIT() asm volatile("cp.async.commit_group;" ::: "memory")
#define CP_WAIT(n)  asm volatile("cp.async.wait_group %0;" :: "n"(n) : "memory")

__device__ __forceinline__ void ldm_x4(uint32_t* r, uint32_t addr) {
    asm volatile("ldmatrix.sync.aligned.m8n8.x4.shared.b16 {%0,%1,%2,%3}, [%4];"
        : "=r"(r[0]), "=r"(r[1]), "=r"(r[2]), "=r"(r[3]) : "r"(addr));
}
__device__ __forceinline__ void ldm_x4_t(uint32_t* r, uint32_t addr) {
    asm volatile("ldmatrix.sync.aligned.m8n8.x4.trans.shared.b16 {%0,%1,%2,%3}, [%4];"
        : "=r"(r[0]), "=r"(r[1]), "=r"(r[2]), "=r"(r[3]) : "r"(addr));
}
__device__ __forceinline__ void mma_f16(float* c, const uint32_t* a, const uint32_t* b) {
    asm volatile("mma.sync.aligned.m16n8k16.row.col.f32.f16.f16.f32 "
        "{%0,%1,%2,%3}, {%4,%5,%6,%7}, {%8,%9}, {%0,%1,%2,%3};"
        : "+f"(c[0]), "+f"(c[1]), "+f"(c[2]), "+f"(c[3])
        : "r"(a[0]), "r"(a[1]), "r"(a[2]), "r"(a[3]), "r"(b[0]), "r"(b[1]));
}
__device__ __forceinline__ float ex2(float x) {
    float y; asm("ex2.approx.ftz.f32 %0, %1;" : "=f"(y) : "f"(x)); return y;
}
__device__ __forceinline__ uint32_t pack_h2(float v0, float v1) {
    uint32_t r;
    asm("cvt.rn.f16x2.f32 %0, %1, %2;" : "=r"(r) : "f"(v1), "f"(v0));
    return r;
}

static __device__ __constant__ const float QSCALE_D = 0.125f * 1.44269504088896340736f;

// ======================= conversion / repack kernels =======================
__global__ void cvt_half(const float* __restrict__ in, __half* __restrict__ o, int n) {
    int i = blockIdx.x * 256 + threadIdx.x;
    if (i >= n) return;
    o[i] = __float2half_rn(in[i]);
}

// W [K, N] row-major -> o [N, K] fp16; smem-tiled, block (32,8)
__global__ void repack_T2(const float* __restrict__ W, __half* __restrict__ o,
                          int N, int K) {
    __shared__ float t[32][33];
    const int n0 = blockIdx.x * 32, k0 = blockIdx.y * 32;
    const int tx = threadIdx.x, ty = threadIdx.y;
    #pragma unroll
    for (int r = 0; r < 4; r++)
        t[ty + 8 * r][tx] = W[(size_t)(k0 + ty + 8 * r) * N + n0 + tx];
    __syncthreads();
    #pragma unroll
    for (int r = 0; r < 4; r++)
        o[(size_t)(n0 + ty + 8 * r) * K + k0 + tx] = __float2half_rn(t[tx][ty + 8 * r]);
}

// Wq/Wk/Wv [H,D,DK] -> w_qkv [2304, 768] fp16
__global__ void repack_qkvw(const float* __restrict__ Wq, const float* __restrict__ Wk,
                            const float* __restrict__ Wv) {
    __shared__ float t[32][33];
    const int sel = blockIdx.z / HH, h = blockIdx.z % HH;
    const float* W = (sel == 0 ? Wq : sel == 1 ? Wk : Wv) + (size_t)h * DD * DKK;
    const int dk0 = blockIdx.x * 32, d0 = blockIdx.y * 32;
    const int tx = threadIdx.x, ty = threadIdx.y;
    #pragma unroll
    for (int r = 0; r < 4; r++)
        t[ty + 8 * r][tx] = W[(size_t)(d0 + ty + 8 * r) * DKK + dk0 + tx];
    __syncthreads();
    #pragma unroll
    for (int r = 0; r < 4; r++) {
        size_t row = (size_t)sel * DD + h * DKK + dk0 + ty + 8 * r;
        w_qkv[row * DD + d0 + tx] = __float2half_rn(t[tx][ty + 8 * r]);
    }
}

// ======================= mma.sync fp16 GEMM ================================
// C[M,N] = A[M,K] @ B[N,K]^T, fp32 accumulate
// MODE 1: acc + bias + res -> fp32 row-major
// MODE 2: relu(acc+bias) -> fp16 row-major
// MODE 4: fused QKV epilogue: Q (scaled) / K / V all fp16 [B,H,S,DK]
static constexpr int RS = 80;   // 32 fp16 (64B) + 16B pad

template<int BN> struct GP {
    static constexpr int A_BYTES = 128 * RS;
    static constexpr int B_BYTES = BN * RS;
    static constexpr int STGB    = A_BYTES + B_BYTES;
    static constexpr int SMEM    = 2 * STGB;
    static constexpr int NTW     = BN / 16;
    static constexpr int NPB     = BN / 32;
    static constexpr int CPT     = (512 + 4 * BN) / 256;
};

template<int MODE, int BN, int MINB>
__global__ void __launch_bounds__(256, MINB) gemm_mma(
    const __half* __restrict__ A, const __half* __restrict__ B,
    const float* __restrict__ bias, const float* __restrict__ res,
    float* __restrict__ C, __half* __restrict__ Cs,
    int M, int N, int K)
{
    using P = GP<BN>;
    extern __shared__ char sb[];
    const uint32_t sbu = smem_u32(sb);
    const int tid  = threadIdx.x;
    const int wid  = tid >> 5;
    const int lane = tid & 31;
    const int wm   = wid & 3;
    const int wn   = wid >> 2;

    const int rowBase = blockIdx.y << 7;
    const int colBase = blockIdx.x * BN;
    const __half* gA = A + (size_t)rowBase * K;
    const __half* gB = B + (size_t)colBase * K;

    int ld_mat[P::CPT], ld_r[P::CPT], ld_q[P::CPT];
    #pragma unroll
    for (int i = 0; i < P::CPT; i++) {
        int slot = (i << 8) + tid;
        int mat, rem;
        if (slot < 512) { mat = 0; rem = slot; }
        else            { mat = 1; rem = slot - 512; }
        ld_mat[i] = mat; ld_r[i] = rem >> 2; ld_q[i] = rem & 3;
    }

    auto load_stage = [&](int kc, int buf) {
        const uint32_t base = sbu + buf * P::STGB;
        #pragma unroll
        for (int i = 0; i < P::CPT; i++) {
            const __half* src = (ld_mat[i] == 0 ? gA : gB)
                                + (size_t)ld_r[i] * K + kc + (ld_q[i] << 3);
            uint32_t dst = base + ld_mat[i] * P::A_BYTES + ld_r[i] * RS + (ld_q[i] << 4);
            CP_ASYNC16(dst, src);
        }
        CP_COMMIT();
    };

    float acc[2][P::NTW][4];
    #pragma unroll
    for (int mt = 0; mt < 2; mt++)
        #pragma unroll
        for (int nt = 0; nt < P::NTW; nt++)
            #pragma unroll
            for (int j = 0; j < 4; j++) acc[mt][nt][j] = 0.0f;

    const uint32_t aAddr = (uint32_t)((wm * 32 + (lane & 15)) * RS + (lane >> 4) * 16);
    const uint32_t bAddr = (uint32_t)((wn * (BN/2) + ((lane >> 4) << 3) + (lane & 7)) * RS
                                      + ((lane >> 3) & 1) * 16);

    const int nStages = K >> 5;
    load_stage(0, 0);

    for (int c = 0; c < nStages; c++) {
        if (c + 1 < nStages) load_stage((c + 1) << 5, (c + 1) & 1);
        if (c + 1 < nStages) { CP_WAIT(1); } else { CP_WAIT(0); }
        __syncthreads();

        const uint32_t base = sbu + (c & 1) * P::STGB;
        #pragma unroll
        for (int ks = 0; ks < 2; ks++) {
            const uint32_t ko = ks * 32;
            uint32_t bf[P::NTW*2];
            #pragma unroll
            for (int np = 0; np < P::NPB; np++)
                ldm_x4(bf + np * 4, base + P::A_BYTES + bAddr + np * 16 * RS + ko);
            #pragma unroll
            for (int mt = 0; mt < 2; mt++) {
                uint32_t ah[4];
                ldm_x4(ah, base + aAddr + mt * 16 * RS + ko);
                #pragma unroll
                for (int nt = 0; nt < P::NTW; nt++)
                    mma_f16(acc[mt][nt], ah, bf + nt * 2);
            }
        }
        __syncthreads();
    }

    // ---------------- epilogue ----------------
    const int g  = lane >> 2;
    const int tc = (lane & 3) << 1;

    #pragma unroll
    for (int mt = 0; mt < 2; mt++) {
        #pragma unroll
        for (int half_i = 0; half_i < 2; half_i++) {
            const int orow = rowBase + wm * 32 + mt * 16 + g + half_i * 8;
            #pragma unroll
            for (int nt = 0; nt < P::NTW; nt++) {
                const int col = colBase + wn * (BN/2) + nt * 8 + tc;
                float a0 = acc[mt][nt][half_i * 2 + 0];
                float a1 = acc[mt][nt][half_i * 2 + 1];
                if (MODE == 4) {
                    const int sel = col / DD;
                    const int lc  = col - sel * DD;
                    const float* bptr = sel == 0 ? bias : sel == 1 ? res : (const float*)C;
                    float v0 = a0 + bptr[lc];
                    float v1 = a1 + bptr[lc + 1];
                    const int b = orow >> 11, s = orow & 2047;
                    const int h = lc >> 6, dk = lc & 63;
                    size_t off = (((size_t)b * HH + h) * SS + s) * DKK + dk;
                    if (sel == 0) { v0 *= QSCALE_D; v1 *= QSCALE_D; }
                    __half* dst = sel == 0 ? a_q : sel == 1 ? a_k : a_v;
                    *(uint32_t*)(dst + off) = pack_h2(v0, v1);
                } else if (MODE == 1) {
                    float v0 = a0 + bias[col];
                    float v1 = a1 + bias[col + 1];
                    const float* rp = res + (size_t)orow * N + col;
                    float2 rv = *(const float2*)rp;
                    *(float2*)(C + (size_t)orow * N + col) = make_float2(v0 + rv.x, v1 + rv.y);
                } else {
                    float v0 = fmaxf(a0 + bias[col], 0.0f);
                    float v1 = fmaxf(a1 + bias[col + 1], 0.0f);
                    *(uint32_t*)(Cs + (size_t)orow * N + col) = pack_h2(v0, v1);
                }
            }
        }
    }
}

// ======================= mma.sync flash attention (fp16) ===================
// Q/K/V single fp16. 128 queries/CTA, 64-key tiles, double-buffered K+V.
static constexpr int ATT_RS  = 144;           // 64 fp16 = 128B + 16B pad
static constexpr int ATT_BUF = 64 * ATT_RS;   // 9216
static constexpr int ATT_STG = 2 * ATT_BUF;   // 18432 (K,V)
static constexpr int ATT_SMEM = 2 * ATT_STG;  // 36864

__global__ void __launch_bounds__(256, 2) attn_mma(
    const __half* __restrict__ Q, const __half* __restrict__ K,
    const __half* __restrict__ V, __half* __restrict__ Cs)
{
    extern __shared__ char sm[];
    const uint32_t sbu = smem_u32(sm);
    const int qt = blockIdx.x, h = blockIdx.y, b = blockIdx.z;
    const int tid = threadIdx.x, wid = tid >> 5, lane = tid & 31;

    const size_t bh = (size_t)b * HH + h;
    const __half* gQ = Q + (bh * SS + qt * 128) * DKK;
    const __half* gK = K + bh * SS * DKK;
    const __half* gV = V + bh * SS * DKK;

    // ---- stage Q tile (128x64 fp16) and extract A-frags ----
    {
        #pragma unroll
        for (int i = 0; i < 4; i++) {
            int slot = (i << 8) + tid;          // 0..1023
            int r = slot >> 3, c = slot & 7;
            CP_ASYNC16(sbu + r * ATT_RS + (c << 4), gQ + r * DKK + (c << 3));
        }
        CP_COMMIT(); CP_WAIT(0);
        __syncthreads();
    }
    uint32_t qf[4][4];
    {
        const uint32_t qa = sbu + (wid * 16 + (lane & 15)) * ATT_RS + ((lane >> 4) << 4);
        #pragma unroll
        for (int ks = 0; ks < 4; ks++) ldm_x4(qf[ks], qa + ks * 32);
    }
    __syncthreads();

    auto load_kv = [&](int t0, int buf) {
        const uint32_t base = sbu + buf * ATT_STG;
        #pragma unroll
        for (int i = 0; i < 4; i++) {
            int slot = (i << 8) + tid;          // 0..1023
            int arr = slot >> 9;                // 0 K, 1 V
            int rem = slot & 511;
            int r = rem >> 3, c = rem & 7;
            const __half* src = (arr == 0 ? gK : gV) + (size_t)(t0 + r) * DKK + (c << 3);
            CP_ASYNC16(base + arr * ATT_BUF + r * ATT_RS + (c << 4), src);
        }
        CP_COMMIT();
    };

    float ctx[8][4];
    #pragma unroll
    for (int nt = 0; nt < 8; nt++)
        #pragma unroll
        for (int j = 0; j < 4; j++) ctx[nt][j] = 0.0f;
    float m0 = -1e30f, m1 = -1e30f, l0 = 0.0f, l1 = 0.0f;

    const uint32_t kAddr = (uint32_t)(((((lane >> 4) << 3) | (lane & 7)) * ATT_RS)
                                      + ((lane >> 3) & 1) * 16);
    const uint32_t vAddr = (uint32_t)((lane & 15) * ATT_RS + ((lane >> 4) << 4));

    load_kv(0, 0);
    #pragma unroll 1
    for (int t = 0; t < SS / 64; t++) {
        if (t + 1 < SS / 64) { load_kv((t + 1) * 64, (t + 1) & 1); CP_WAIT(1); }
        else                 { CP_WAIT(0); }
        __syncthreads();
        const uint32_t base = sbu + (t & 1) * ATT_STG;

        // ---- S = Q @ K^T ----
        float sa[8][4];
        #pragma unroll
        for (int nt = 0; nt < 8; nt++)
            #pragma unroll
            for (int j = 0; j < 4; j++) sa[nt][j] = 0.0f;
        #pragma unroll
        for (int ks = 0; ks < 4; ks++) {
            #pragma unroll
            for (int np = 0; np < 4; np++) {
                uint32_t kb[4];
                ldm_x4(kb, base + kAddr + np * 16 * ATT_RS + ks * 32);
                mma_f16(sa[2 * np],     qf[ks], kb);
                mma_f16(sa[2 * np + 1], qf[ks], kb + 2);
            }
        }

        // ---- online softmax (base-2) ----
        float rm0 = -1e30f, rm1 = -1e30f;
        #pragma unroll
        for (int nt = 0; nt < 8; nt++) {
            rm0 = fmaxf(rm0, fmaxf(sa[nt][0], sa[nt][1]));
            rm1 = fmaxf(rm1, fmaxf(sa[nt][2], sa[nt][3]));
        }
        rm0 = fmaxf(rm0, __shfl_xor_sync(0xFFFFFFFFu, rm0, 1));
        rm0 = fmaxf(rm0, __shfl_xor_sync(0xFFFFFFFFu, rm0, 2));
        rm1 = fmaxf(rm1, __shfl_xor_sync(0xFFFFFFFFu, rm1, 1));
        rm1 = fmaxf(rm1, __shfl_xor_sync(0xFFFFFFFFu, rm1, 2));
        const float nm0 = fmaxf(m0, rm0), nm1 = fmaxf(m1, rm1);
        const float c0 = ex2(m0 - nm0), c1 = ex2(m1 - nm1);
        l0 *= c0; l1 *= c1;
        #pragma unroll
        for (int nt = 0; nt < 8; nt++) {
            ctx[nt][0] *= c0; ctx[nt][1] *= c0;
            ctx[nt][2] *= c1; ctx[nt][3] *= c1;
        }
        float s0 = 0.0f, s1 = 0.0f;
        #pragma unroll
        for (int nt = 0; nt < 8; nt++) {
            float p0 = ex2(sa[nt][0] - nm0); sa[nt][0] = p0; s0 += p0;
            float p1 = ex2(sa[nt][1] - nm0); sa[nt][1] = p1; s0 += p1;
            float p2 = ex2(sa[nt][2] - nm1); sa[nt][2] = p2; s1 += p2;
            float p3 = ex2(sa[nt][3] - nm1); sa[nt][3] = p3; s1 += p3;
        }
        s0 += __shfl_xor_sync(0xFFFFFFFFu, s0, 1);
        s0 += __shfl_xor_sync(0xFFFFFFFFu, s0, 2);
        s1 += __shfl_xor_sync(0xFFFFFFFFu, s1, 1);
        s1 += __shfl_xor_sync(0xFFFFFFFFu, s1, 2);
        l0 += s0; l1 += s1; m0 = nm0; m1 = nm1;

        // ---- ctx += P @ V (P A-frags from S regs; V via ldmatrix.trans) ----
        #pragma unroll
        for (int ks = 0; ks < 4; ks++) {
            uint32_t ph[4];
            ph[0] = pack_h2(sa[2 * ks][0],     sa[2 * ks][1]);
            ph[1] = pack_h2(sa[2 * ks][2],     sa[2 * ks][3]);
            ph[2] = pack_h2(sa[2 * ks + 1][0], sa[2 * ks + 1][1]);
            ph[3] = pack_h2(sa[2 * ks + 1][2], sa[2 * ks + 1][3]);
            const uint32_t vrow = vAddr + ks * 16 * ATT_RS;
            #pragma unroll
            for (int np = 0; np < 4; np++) {
                uint32_t vb[4];
                ldm_x4_t(vb, base + ATT_BUF + vrow + np * 32);
                mma_f16(ctx[2 * np],     ph, vb);
                mma_f16(ctx[2 * np + 1], ph, vb + 2);
            }
        }
        __syncthreads();
    }

    // ---- epilogue: ctx/l -> fp16 [B, S, H*DK] ----
    const float i0 = 1.0f / l0, i1 = 1.0f / l1;
    const int g = lane >> 2, tc2 = (lane & 3) << 1;
    const int r0 = qt * 128 + wid * 16 + g;
    const size_t base0 = ((size_t)b * SS + r0) * DD + h * DKK;
    #pragma unroll
    for (int nt = 0; nt < 8; nt++) {
        const int col = nt * 8 + tc2;
        *(uint32_t*)(Cs + base0 + col) = pack_h2(ctx[nt][0] * i0, ctx[nt][1] * i0);
        *(uint32_t*)(Cs + base0 + (size_t)8 * DD + col) = pack_h2(ctx[nt][2] * i1, ctx[nt][3] * i1);
    }
}

// ======================= LayerNorm (optionally emits fp16) =================
template<int WB>
__global__ __launch_bounds__(256)
void ln_k(const float* __restrict__ in, const float* __restrict__ w,
          const float* __restrict__ bsh, float* __restrict__ out,
          __half* __restrict__ oh)
{
    const size_t row = blockIdx.x;
    const float* x = in + row * DD;
    float s = 0.0f, s2 = 0.0f;
    for (int i = threadIdx.x; i < DD; i += 256) {
        float v = x[i]; s += v; s2 += v * v;
    }
    #pragma unroll
    for (int o = 16; o > 0; o >>= 1) {
        s  += __shfl_xor_sync(0xFFFFFFFFu, s,  o);
        s2 += __shfl_xor_sync(0xFFFFFFFFu, s2, o);
    }
    __shared__ float ws[8], ws2[8];
    const int wid = threadIdx.x >> 5, lane = threadIdx.x & 31;
    if (lane == 0) { ws[wid] = s; ws2[wid] = s2; }
    __syncthreads();
    float ts = 0.0f, ts2 = 0.0f;
    #pragma unroll
    for (int i = 0; i < 8; i++) { ts += ws[i]; ts2 += ws2[i]; }
    const float mu   = ts  * (1.0f / DD);
    const float var  = ts2 * (1.0f / DD) - mu * mu;
    const float rstd = rsqrtf(var + 1e-5f);
    for (int i = threadIdx.x; i < DD; i += 256) {
        float r = (x[i] - mu) * rstd * w[i] + bsh[i];
        out[row * DD + i] = r;
        if (WB) oh[row * DD + i] = __float2half_rn(r);
    }
}

// ======================= launch ============================================
template<typename T>
static void* sym_addr(T& sym) {
    void* p = nullptr;
    cudaGetSymbolAddress(&p, sym);
    return p;
}

extern "C" void kernel_launch(void* const* d_in, const int* in_sizes, int n_in,
                              void* d_out, int out_size)
{
    const float* src  = (const float*)d_in[0];
    const float* Wq   = (const float*)d_in[1];
    const float* bq   = (const float*)d_in[2];
    const float* Wk   = (const float*)d_in[3];
    const float* bk   = (const float*)d_in[4];
    const float* Wv   = (const float*)d_in[5];
    const float* bv   = (const float*)d_in[6];
    const float* Wo   = (const float*)d_in[7];
    const float* bo   = (const float*)d_in[8];
    const float* ln1w = (const float*)d_in[9];
    const float* ln1b = (const float*)d_in[10];
    const float* W1   = (const float*)d_in[11];
    const float* b1   = (const float*)d_in[12];
    const float* W2   = (const float*)d_in[13];
    const float* b2   = (const float*)d_in[14];
    const float* ln2w = (const float*)d_in[15];
    const float* ln2b = (const float*)d_in[16];
    float* out = (float*)d_out;

    float* py   = (float*)sym_addr(g_y);
    float* px   = (float*)sym_addr(g_x);
    float* py2  = (float*)sym_addr(g_y2);

    __half* srch = (__half*)sym_addr(s_srch);
    __half* ctxh = (__half*)sym_addr(s_ctxh);
    __half* xh   = (__half*)sym_addr(s_xh);
    __half* ffh  = (__half*)sym_addr(s_ffh);
    __half* q1   = (__half*)sym_addr(a_q);
    __half* k1   = (__half*)sym_addr(a_k);
    __half* v1   = (__half*)sym_addr(a_v);
    __half* wqkv = (__half*)sym_addr(w_qkv);
    __half* wo   = (__half*)sym_addr(w_o);
    __half* w1   = (__half*)sym_addr(w_1);
    __half* w2   = (__half*)sym_addr(w_2);

    cudaFuncSetAttribute((const void*)gemm_mma<4,128,1>, cudaFuncAttributeMaxDynamicSharedMemorySize, GP<128>::SMEM);
    cudaFuncSetAttribute((const void*)gemm_mma<2,64,2>,  cudaFuncAttributeMaxDynamicSharedMemorySize, GP<64>::SMEM);
    cudaFuncSetAttribute((const void*)gemm_mma<1,64,2>,  cudaFuncAttributeMaxDynamicSharedMemorySize, GP<64>::SMEM);
    cudaFuncSetAttribute((const void*)attn_mma,          cudaFuncAttributeMaxDynamicSharedMemorySize, ATT_SMEM);

    // preprocessing
    cvt_half<<<(MROWS*DD + 255)/256, 256>>>(src, srch, MROWS*DD);
    repack_qkvw<<<dim3(DKK/32, DD/32, 3*HH), dim3(32,8)>>>(Wq, Wk, Wv);
    repack_T2<<<dim3(DD/32, DD/32),  dim3(32,8)>>>(Wo, wo, DD, DD);
    repack_T2<<<dim3(DFF/32, DD/32), dim3(32,8)>>>(W1, w1, DFF, DD);
    repack_T2<<<dim3(DD/32, DFF/32), dim3(32,8)>>>(W2, w2, DD, DFF);

    // fused QKV projection (N=2304): Q scaled, K, V -> [B,H,S,DK] fp16
    gemm_mma<4,128,1><<<dim3(3*DD/128, MROWS/128), 256, GP<128>::SMEM>>>(
        srch, wqkv, bq, bk, (float*)bv, nullptr, MROWS, 3*DD, DD);

    // flash attention -> ctx fp16 [B,S,H*DK]
    attn_mma<<<dim3(SS/128, HH, BB), 256, ATT_SMEM>>>(q1, k1, v1, ctxh);

    // out projection + residual -> y ; LN1 -> x (+ fp16)
    gemm_mma<1,64,2><<<dim3(DD/64, MROWS/128), 256, GP<64>::SMEM>>>(
        ctxh, wo, bo, src, py, nullptr, MROWS, DD, DD);
    ln_k<1><<<MROWS, 256>>>(py, ln1w, ln1b, px, xh);

    // FFN
    gemm_mma<2,64,2><<<dim3(DFF/64, MROWS/128), 256, GP<64>::SMEM>>>(
        xh, w1, b1, nullptr, nullptr, ffh, MROWS, DFF, DD);
    gemm_mma<1,64,2><<<dim3(DD/64, MROWS/128), 256, GP<64>::SMEM>>>(
        ffh, w2, b2, px, py2, nullptr, MROWS, DD, DFF);

    // LN2 -> output
    ln_k<0><<<MROWS, 256>>>(py2, ln2w, ln2b, out, nullptr);
}

// round 11
// speedup vs baseline: 7.9905x; 1.0878x over previous
#include <cuda_runtime.h>
#include <cuda_fp16.h>
#include <cstdint>
#include <math.h>

#define BB 2
#define SS 2048
#define DD 768
#define HH 12
#define DKK 64
#define DFF 3072
#define MROWS (BB*SS)   // 4096

// ======================= device scratch (no allocs allowed) ================
__device__ float g_p0[MROWS*DD];    // split-K partial 0 (bias folded in)
__device__ float g_p1[MROWS*DD];    // split-K partial 1
__device__ float g_x[MROWS*DD];     // post-LN1 fp32 (residual for FF2 path)
// fp16 activations / weights
__device__ __half s_srch[MROWS*DD];
__device__ __half s_ctxh[MROWS*DD];
__device__ __half s_xh[MROWS*DD];
__device__ __half s_ffh[MROWS*DFF];
__device__ __half a_q[BB*HH*SS*DKK];
__device__ __half a_k[BB*HH*SS*DKK];
__device__ __half a_v[BB*HH*SS*DKK];
__device__ __half w_qkv[3*DD*DD];   // [2304, 768]
__device__ __half w_o[DD*DD];
__device__ __half w_1[DFF*DD];
__device__ __half w_2[DD*DFF];

// ======================= PTX helpers (stable ISA only) =====================
__device__ __forceinline__ uint32_t smem_u32(const void* p) {
    uint32_t a;
    asm("{ .reg .u64 t; cvta.to.shared.u64 t, %1; cvt.u32.u64 %0, t; }" : "=r"(a) : "l"(p));
    return a;
}
#define CP_ASYNC16(dst, src) \
    asm volatile("cp.async.cg.shared.global [%0], [%1], 16;" :: "r"(dst), "l"(src) : "memory")
#define CP_COMMIT() asm volatile("cp.async.commit_group;" ::: "memory")
#define CP_WAIT(n)  asm volatile("cp.async.wait_group %0;" :: "n"(n) : "memory")

__device__ __forceinline__ void ldm_x4(uint32_t* r, uint32_t addr) {
    asm volatile("ldmatrix.sync.aligned.m8n8.x4.shared.b16 {%0,%1,%2,%3}, [%4];"
        : "=r"(r[0]), "=r"(r[1]), "=r"(r[2]), "=r"(r[3]) : "r"(addr));
}
__device__ __forceinline__ void ldm_x4_t(uint32_t* r, uint32_t addr) {
    asm volatile("ldmatrix.sync.aligned.m8n8.x4.trans.shared.b16 {%0,%1,%2,%3}, [%4];"
        : "=r"(r[0]), "=r"(r[1]), "=r"(r[2]), "=r"(r[3]) : "r"(addr));
}
__device__ __forceinline__ void mma_f16(float* c, const uint32_t* a, const uint32_t* b) {
    asm volatile("mma.sync.aligned.m16n8k16.row.col.f32.f16.f16.f32 "
        "{%0,%1,%2,%3}, {%4,%5,%6,%7}, {%8,%9}, {%0,%1,%2,%3};"
        : "+f"(c[0]), "+f"(c[1]), "+f"(c[2]), "+f"(c[3])
        : "r"(a[0]), "r"(a[1]), "r"(a[2]), "r"(a[3]), "r"(b[0]), "r"(b[1]));
}
__device__ __forceinline__ float ex2(float x) {
    float y; asm("ex2.approx.ftz.f32 %0, %1;" : "=f"(y) : "f"(x)); return y;
}
__device__ __forceinline__ uint32_t pack_h2(float v0, float v1) {
    uint32_t r;
    asm("cvt.rn.f16x2.f32 %0, %1, %2;" : "=r"(r) : "f"(v1), "f"(v0));
    return r;
}

static __device__ __constant__ const float QSCALE_D = 0.125f * 1.44269504088896340736f;

// ======================= fused preprocessing kernel ========================
// 1D grid, 256-thread blocks, range dispatch:
//   [0, NCVT)                : src fp32 -> fp16
//   [NCVT, +1728)            : Wq/Wk/Wv [H,D,DK] -> w_qkv [2304,768]
//   next 576 / 2304 / 2304   : Wo / W1 / W2 transpose [K,N]->[N,K] fp16
static constexpr int NCVT = (MROWS * DD) / 256;   // 12288
static constexpr int NQKV = 2 * 24 * 3 * HH;      // 1728
static constexpr int NWO  = 24 * 24;              // 576
static constexpr int NW1  = 96 * 24;              // 2304
static constexpr int NW2  = 24 * 96;              // 2304
static constexpr int PRE_GRID = NCVT + NQKV + NWO + NW1 + NW2;

__global__ void preproc(const float* __restrict__ src,
                        const float* __restrict__ Wq, const float* __restrict__ Wk,
                        const float* __restrict__ Wv, const float* __restrict__ Wo,
                        const float* __restrict__ W1, const float* __restrict__ W2)
{
    int blk = blockIdx.x;
    if (blk < NCVT) {
        int i = blk * 256 + threadIdx.x;
        s_srch[i] = __float2half_rn(src[i]);
        return;
    }
    blk -= NCVT;

    __shared__ float t[32][33];
    const int tx = threadIdx.x & 31, ty = threadIdx.x >> 5;

    const float* W; __half* o;
    int n0, k0, Kst;          // output row-major [N, Kst]
    size_t rowoff = 0;
    if (blk < NQKV) {
        const int z = blk / 48, rem = blk % 48;
        const int sel = z / HH, h = z % HH;
        W = (sel == 0 ? Wq : sel == 1 ? Wk : Wv) + (size_t)h * DD * DKK;
        n0 = (rem % 2) * 32;          // dk
        k0 = (rem / 2) * 32;          // d
        Kst = DD;
        o = w_qkv;
        rowoff = (size_t)sel * DD + h * DKK;
        // input W is [DD, DKK]: W[(k)(d) * DKK + n(dk)]
        #pragma unroll
        for (int r = 0; r < 4; r++)
            t[ty + 8 * r][tx] = W[(size_t)(k0 + ty + 8 * r) * DKK + n0 + tx];
        __syncthreads();
        #pragma unroll
        for (int r = 0; r < 4; r++)
            o[(rowoff + n0 + ty + 8 * r) * Kst + k0 + tx] =
                __float2half_rn(t[tx][ty + 8 * r]);
        return;
    }
    blk -= NQKV;
    int N;
    if (blk < NWO)      { W = Wo; o = w_o; N = DD;  Kst = DD;  n0 = (blk % 24) * 32; k0 = (blk / 24) * 32; }
    else if ((blk -= NWO) < NW1) { W = W1; o = w_1; N = DFF; Kst = DD;  n0 = (blk % 96) * 32; k0 = (blk / 96) * 32; }
    else                { blk -= NW1; W = W2; o = w_2; N = DD; Kst = DFF; n0 = (blk % 24) * 32; k0 = (blk / 24) * 32; }
    #pragma unroll
    for (int r = 0; r < 4; r++)
        t[ty + 8 * r][tx] = W[(size_t)(k0 + ty + 8 * r) * N + n0 + tx];
    __syncthreads();
    #pragma unroll
    for (int r = 0; r < 4; r++)
        o[(size_t)(n0 + ty + 8 * r) * Kst + k0 + tx] = __float2half_rn(t[tx][ty + 8 * r]);
}

// ======================= mma.sync fp16 GEMM ================================
// C[M,N] = A[M,K] @ B[N,K]^T, fp32 accumulate
// MODE 2: relu(acc+bias) -> fp16 row-major
// MODE 4: fused QKV epilogue: Q (scaled) / K / V fp16 [B,H,S,DK]
// MODE 5: split-K partial: acc (+bias iff z==0) -> fp32 at C + z*M*N
static constexpr int RS = 80;

template<int BN> struct GP {
    static constexpr int A_BYTES = 128 * RS;
    static constexpr int B_BYTES = BN * RS;
    static constexpr int STGB    = A_BYTES + B_BYTES;
    static constexpr int SMEM    = 2 * STGB;
    static constexpr int NTW     = BN / 16;
    static constexpr int NPB     = BN / 32;
    static constexpr int CPT     = (512 + 4 * BN) / 256;
};

template<int MODE, int BN, int MINB>
__global__ void __launch_bounds__(256, MINB) gemm_mma(
    const __half* __restrict__ A, const __half* __restrict__ B,
    const float* __restrict__ bias, const float* __restrict__ res,
    float* __restrict__ C, __half* __restrict__ Cs,
    int M, int N, int K)
{
    using P = GP<BN>;
    extern __shared__ char sb[];
    const uint32_t sbu = smem_u32(sb);
    const int tid  = threadIdx.x;
    const int wid  = tid >> 5;
    const int lane = tid & 31;
    const int wm   = wid & 3;
    const int wn   = wid >> 2;

    const int z      = (MODE == 5) ? blockIdx.z : 0;
    const int kLen   = (MODE == 5) ? K / ((int)gridDim.z) : K;
    const int kc0    = z * kLen;

    const int rowBase = blockIdx.y << 7;
    const int colBase = blockIdx.x * BN;
    const __half* gA = A + (size_t)rowBase * K;
    const __half* gB = B + (size_t)colBase * K;

    int ld_mat[P::CPT], ld_r[P::CPT], ld_q[P::CPT];
    #pragma unroll
    for (int i = 0; i < P::CPT; i++) {
        int slot = (i << 8) + tid;
        int mat, rem;
        if (slot < 512) { mat = 0; rem = slot; }
        else            { mat = 1; rem = slot - 512; }
        ld_mat[i] = mat; ld_r[i] = rem >> 2; ld_q[i] = rem & 3;
    }

    auto load_stage = [&](int kc, int buf) {
        const uint32_t base = sbu + buf * P::STGB;
        #pragma unroll
        for (int i = 0; i < P::CPT; i++) {
            const __half* src = (ld_mat[i] == 0 ? gA : gB)
                                + (size_t)ld_r[i] * K + kc + (ld_q[i] << 3);
            uint32_t dst = base + ld_mat[i] * P::A_BYTES + ld_r[i] * RS + (ld_q[i] << 4);
            CP_ASYNC16(dst, src);
        }
        CP_COMMIT();
    };

    float acc[2][P::NTW][4];
    #pragma unroll
    for (int mt = 0; mt < 2; mt++)
        #pragma unroll
        for (int nt = 0; nt < P::NTW; nt++)
            #pragma unroll
            for (int j = 0; j < 4; j++) acc[mt][nt][j] = 0.0f;

    const uint32_t aAddr = (uint32_t)((wm * 32 + (lane & 15)) * RS + (lane >> 4) * 16);
    const uint32_t bAddr = (uint32_t)((wn * (BN/2) + ((lane >> 4) << 3) + (lane & 7)) * RS
                                      + ((lane >> 3) & 1) * 16);

    const int nStages = kLen >> 5;
    load_stage(kc0, 0);

    for (int c = 0; c < nStages; c++) {
        if (c + 1 < nStages) load_stage(kc0 + ((c + 1) << 5), (c + 1) & 1);
        if (c + 1 < nStages) { CP_WAIT(1); } else { CP_WAIT(0); }
        __syncthreads();

        const uint32_t base = sbu + (c & 1) * P::STGB;
        #pragma unroll
        for (int ks = 0; ks < 2; ks++) {
            const uint32_t ko = ks * 32;
            uint32_t bf[P::NTW*2];
            #pragma unroll
            for (int np = 0; np < P::NPB; np++)
                ldm_x4(bf + np * 4, base + P::A_BYTES + bAddr + np * 16 * RS + ko);
            #pragma unroll
            for (int mt = 0; mt < 2; mt++) {
                uint32_t ah[4];
                ldm_x4(ah, base + aAddr + mt * 16 * RS + ko);
                #pragma unroll
                for (int nt = 0; nt < P::NTW; nt++)
                    mma_f16(acc[mt][nt], ah, bf + nt * 2);
            }
        }
        __syncthreads();
    }

    // ---------------- epilogue ----------------
    const int g  = lane >> 2;
    const int tc = (lane & 3) << 1;

    #pragma unroll
    for (int mt = 0; mt < 2; mt++) {
        #pragma unroll
        for (int half_i = 0; half_i < 2; half_i++) {
            const int orow = rowBase + wm * 32 + mt * 16 + g + half_i * 8;
            #pragma unroll
            for (int nt = 0; nt < P::NTW; nt++) {
                const int col = colBase + wn * (BN/2) + nt * 8 + tc;
                float a0 = acc[mt][nt][half_i * 2 + 0];
                float a1 = acc[mt][nt][half_i * 2 + 1];
                if (MODE == 4) {
                    const int sel = col / DD;
                    const int lc  = col - sel * DD;
                    const float* bptr = sel == 0 ? bias : sel == 1 ? res : (const float*)C;
                    float v0 = a0 + bptr[lc];
                    float v1 = a1 + bptr[lc + 1];
                    const int b = orow >> 11, s = orow & 2047;
                    const int h = lc >> 6, dk = lc & 63;
                    size_t off = (((size_t)b * HH + h) * SS + s) * DKK + dk;
                    if (sel == 0) { v0 *= QSCALE_D; v1 *= QSCALE_D; }
                    __half* dst = sel == 0 ? a_q : sel == 1 ? a_k : a_v;
                    *(uint32_t*)(dst + off) = pack_h2(v0, v1);
                } else if (MODE == 5) {
                    float b0 = (z == 0) ? bias[col] : 0.0f;
                    float b1 = (z == 0) ? bias[col + 1] : 0.0f;
                    *(float2*)(C + (size_t)z * M * N + (size_t)orow * N + col)
                        = make_float2(a0 + b0, a1 + b1);
                } else {
                    float v0 = fmaxf(a0 + bias[col], 0.0f);
                    float v1 = fmaxf(a1 + bias[col + 1], 0.0f);
                    *(uint32_t*)(Cs + (size_t)orow * N + col) = pack_h2(v0, v1);
                }
            }
        }
    }
}

// ======================= mma.sync flash attention (fp16) ===================
static constexpr int ATT_RS  = 144;
static constexpr int ATT_BUF = 64 * ATT_RS;
static constexpr int ATT_STG = 2 * ATT_BUF;   // 18432 (K,V)
static constexpr int ATT_SMEM = 2 * ATT_STG;  // 36864

__global__ void __launch_bounds__(256, 2) attn_mma(
    const __half* __restrict__ Q, const __half* __restrict__ K,
    const __half* __restrict__ V, __half* __restrict__ Cs)
{
    extern __shared__ char sm[];
    const uint32_t sbu = smem_u32(sm);
    const int qt = blockIdx.x, h = blockIdx.y, b = blockIdx.z;
    const int tid = threadIdx.x, wid = tid >> 5, lane = tid & 31;

    const size_t bh = (size_t)b * HH + h;
    const __half* gQ = Q + (bh * SS + qt * 128) * DKK;
    const __half* gK = K + bh * SS * DKK;
    const __half* gV = V + bh * SS * DKK;

    {
        #pragma unroll
        for (int i = 0; i < 4; i++) {
            int slot = (i << 8) + tid;
            int r = slot >> 3, c = slot & 7;
            CP_ASYNC16(sbu + r * ATT_RS + (c << 4), gQ + r * DKK + (c << 3));
        }
        CP_COMMIT(); CP_WAIT(0);
        __syncthreads();
    }
    uint32_t qf[4][4];
    {
        const uint32_t qa = sbu + (wid * 16 + (lane & 15)) * ATT_RS + ((lane >> 4) << 4);
        #pragma unroll
        for (int ks = 0; ks < 4; ks++) ldm_x4(qf[ks], qa + ks * 32);
    }
    __syncthreads();

    auto load_kv = [&](int t0, int buf) {
        const uint32_t base = sbu + buf * ATT_STG;
        #pragma unroll
        for (int i = 0; i < 4; i++) {
            int slot = (i << 8) + tid;
            int arr = slot >> 9;
            int rem = slot & 511;
            int r = rem >> 3, c = rem & 7;
            const __half* src = (arr == 0 ? gK : gV) + (size_t)(t0 + r) * DKK + (c << 3);
            CP_ASYNC16(base + arr * ATT_BUF + r * ATT_RS + (c << 4), src);
        }
        CP_COMMIT();
    };

    float ctx[8][4];
    #pragma unroll
    for (int nt = 0; nt < 8; nt++)
        #pragma unroll
        for (int j = 0; j < 4; j++) ctx[nt][j] = 0.0f;
    float m0 = -1e30f, m1 = -1e30f, l0 = 0.0f, l1 = 0.0f;

    const uint32_t kAddr = (uint32_t)(((((lane >> 4) << 3) | (lane & 7)) * ATT_RS)
                                      + ((lane >> 3) & 1) * 16);
    const uint32_t vAddr = (uint32_t)((lane & 15) * ATT_RS + ((lane >> 4) << 4));

    load_kv(0, 0);
    #pragma unroll 1
    for (int t = 0; t < SS / 64; t++) {
        if (t + 1 < SS / 64) { load_kv((t + 1) * 64, (t + 1) & 1); CP_WAIT(1); }
        else                 { CP_WAIT(0); }
        __syncthreads();
        const uint32_t base = sbu + (t & 1) * ATT_STG;

        float sa[8][4];
        #pragma unroll
        for (int nt = 0; nt < 8; nt++)
            #pragma unroll
            for (int j = 0; j < 4; j++) sa[nt][j] = 0.0f;
        #pragma unroll
        for (int ks = 0; ks < 4; ks++) {
            #pragma unroll
            for (int np = 0; np < 4; np++) {
                uint32_t kb[4];
                ldm_x4(kb, base + kAddr + np * 16 * ATT_RS + ks * 32);
                mma_f16(sa[2 * np],     qf[ks], kb);
                mma_f16(sa[2 * np + 1], qf[ks], kb + 2);
            }
        }

        float rm0 = -1e30f, rm1 = -1e30f;
        #pragma unroll
        for (int nt = 0; nt < 8; nt++) {
            rm0 = fmaxf(rm0, fmaxf(sa[nt][0], sa[nt][1]));
            rm1 = fmaxf(rm1, fmaxf(sa[nt][2], sa[nt][3]));
        }
        rm0 = fmaxf(rm0, __shfl_xor_sync(0xFFFFFFFFu, rm0, 1));
        rm0 = fmaxf(rm0, __shfl_xor_sync(0xFFFFFFFFu, rm0, 2));
        rm1 = fmaxf(rm1, __shfl_xor_sync(0xFFFFFFFFu, rm1, 1));
        rm1 = fmaxf(rm1, __shfl_xor_sync(0xFFFFFFFFu, rm1, 2));
        const float nm0 = fmaxf(m0, rm0), nm1 = fmaxf(m1, rm1);
        const float c0 = ex2(m0 - nm0), c1 = ex2(m1 - nm1);
        l0 *= c0; l1 *= c1;
        #pragma unroll
        for (int nt = 0; nt < 8; nt++) {
            ctx[nt][0] *= c0; ctx[nt][1] *= c0;
            ctx[nt][2] *= c1; ctx[nt][3] *= c1;
        }
        float s0 = 0.0f, s1 = 0.0f;
        #pragma unroll
        for (int nt = 0; nt < 8; nt++) {
            float p0 = ex2(sa[nt][0] - nm0); sa[nt][0] = p0; s0 += p0;
            float p1 = ex2(sa[nt][1] - nm0); sa[nt][1] = p1; s0 += p1;
            float p2 = ex2(sa[nt][2] - nm1); sa[nt][2] = p2; s1 += p2;
            float p3 = ex2(sa[nt][3] - nm1); sa[nt][3] = p3; s1 += p3;
        }
        s0 += __shfl_xor_sync(0xFFFFFFFFu, s0, 1);
        s0 += __shfl_xor_sync(0xFFFFFFFFu, s0, 2);
        s1 += __shfl_xor_sync(0xFFFFFFFFu, s1, 1);
        s1 += __shfl_xor_sync(0xFFFFFFFFu, s1, 2);
        l0 += s0; l1 += s1; m0 = nm0; m1 = nm1;

        #pragma unroll
        for (int ks = 0; ks < 4; ks++) {
            uint32_t ph[4];
            ph[0] = pack_h2(sa[2 * ks][0],     sa[2 * ks][1]);
            ph[1] = pack_h2(sa[2 * ks][2],     sa[2 * ks][3]);
            ph[2] = pack_h2(sa[2 * ks + 1][0], sa[2 * ks + 1][1]);
            ph[3] = pack_h2(sa[2 * ks + 1][2], sa[2 * ks + 1][3]);
            const uint32_t vrow = vAddr + ks * 16 * ATT_RS;
            #pragma unroll
            for (int np = 0; np < 4; np++) {
                uint32_t vb[4];
                ldm_x4_t(vb, base + ATT_BUF + vrow + np * 32);
                mma_f16(ctx[2 * np],     ph, vb);
                mma_f16(ctx[2 * np + 1], ph, vb + 2);
            }
        }
        __syncthreads();
    }

    const float i0 = 1.0f / l0, i1 = 1.0f / l1;
    const int g = lane >> 2, tc2 = (lane & 3) << 1;
    const int r0 = qt * 128 + wid * 16 + g;
    const size_t base0 = ((size_t)b * SS + r0) * DD + h * DKK;
    #pragma unroll
    for (int nt = 0; nt < 8; nt++) {
        const int col = nt * 8 + tc2;
        *(uint32_t*)(Cs + base0 + col) = pack_h2(ctx[nt][0] * i0, ctx[nt][1] * i0);
        *(uint32_t*)(Cs + base0 + (size_t)8 * DD + col) = pack_h2(ctx[nt][2] * i1, ctx[nt][3] * i1);
    }
}

// ======================= LayerNorm over (p0 + p1 + res) ====================
template<int WB>
__global__ __launch_bounds__(256)
void ln_k(const float* __restrict__ in0, const float* __restrict__ in1,
          const float* __restrict__ res, const float* __restrict__ w,
          const float* __restrict__ bsh, float* __restrict__ out,
          __half* __restrict__ oh)
{
    const size_t row = blockIdx.x;
    const float* x0 = in0 + row * DD;
    const float* x1 = in1 + row * DD;
    const float* xr = res + row * DD;
    float xv[3];
    float s = 0.0f, s2 = 0.0f;
    #pragma unroll
    for (int it = 0; it < 3; it++) {
        int i = threadIdx.x + it * 256;
        float v = x0[i] + x1[i] + xr[i];
        xv[it] = v; s += v; s2 += v * v;
    }
    #pragma unroll
    for (int o = 16; o > 0; o >>= 1) {
        s  += __shfl_xor_sync(0xFFFFFFFFu, s,  o);
        s2 += __shfl_xor_sync(0xFFFFFFFFu, s2, o);
    }
    __shared__ float ws[8], ws2[8];
    const int wid = threadIdx.x >> 5, lane = threadIdx.x & 31;
    if (lane == 0) { ws[wid] = s; ws2[wid] = s2; }
    __syncthreads();
    float ts = 0.0f, ts2 = 0.0f;
    #pragma unroll
    for (int i = 0; i < 8; i++) { ts += ws[i]; ts2 += ws2[i]; }
    const float mu   = ts  * (1.0f / DD);
    const float var  = ts2 * (1.0f / DD) - mu * mu;
    const float rstd = rsqrtf(var + 1e-5f);
    #pragma unroll
    for (int it = 0; it < 3; it++) {
        int i = threadIdx.x + it * 256;
        float r = (xv[it] - mu) * rstd * w[i] + bsh[i];
        if (out) out[row * DD + i] = r;
        if (WB) oh[row * DD + i] = __float2half_rn(r);
    }
}

// ======================= launch ============================================
template<typename T>
static void* sym_addr(T& sym) {
    void* p = nullptr;
    cudaGetSymbolAddress(&p, sym);
    return p;
}

extern "C" void kernel_launch(void* const* d_in, const int* in_sizes, int n_in,
                              void* d_out, int out_size)
{
    const float* src  = (const float*)d_in[0];
    const float* Wq   = (const float*)d_in[1];
    const float* bq   = (const float*)d_in[2];
    const float* Wk   = (const float*)d_in[3];
    const float* bk   = (const float*)d_in[4];
    const float* Wv   = (const float*)d_in[5];
    const float* bv   = (const float*)d_in[6];
    const float* Wo   = (const float*)d_in[7];
    const float* bo   = (const float*)d_in[8];
    const float* ln1w = (const float*)d_in[9];
    const float* ln1b = (const float*)d_in[10];
    const float* W1   = (const float*)d_in[11];
    const float* b1   = (const float*)d_in[12];
    const float* W2   = (const float*)d_in[13];
    const float* b2   = (const float*)d_in[14];
    const float* ln2w = (const float*)d_in[15];
    const float* ln2b = (const float*)d_in[16];
    float* out = (float*)d_out;

    float* pp0  = (float*)sym_addr(g_p0);
    float* pp1  = (float*)sym_addr(g_p1);
    float* px   = (float*)sym_addr(g_x);

    __half* ctxh = (__half*)sym_addr(s_ctxh);
    __half* srch = (__half*)sym_addr(s_srch);
    __half* xh   = (__half*)sym_addr(s_xh);
    __half* ffh  = (__half*)sym_addr(s_ffh);
    __half* q1   = (__half*)sym_addr(a_q);
    __half* k1   = (__half*)sym_addr(a_k);
    __half* v1   = (__half*)sym_addr(a_v);
    __half* wqkv = (__half*)sym_addr(w_qkv);
    __half* wo   = (__half*)sym_addr(w_o);
    __half* w1   = (__half*)sym_addr(w_1);
    __half* w2   = (__half*)sym_addr(w_2);

    cudaFuncSetAttribute((const void*)gemm_mma<4,128,2>, cudaFuncAttributeMaxDynamicSharedMemorySize, GP<128>::SMEM);
    cudaFuncSetAttribute((const void*)gemm_mma<2,64,2>,  cudaFuncAttributeMaxDynamicSharedMemorySize, GP<64>::SMEM);
    cudaFuncSetAttribute((const void*)gemm_mma<5,64,2>,  cudaFuncAttributeMaxDynamicSharedMemorySize, GP<64>::SMEM);
    cudaFuncSetAttribute((const void*)attn_mma,          cudaFuncAttributeMaxDynamicSharedMemorySize, ATT_SMEM);

    // fused preprocessing (cvt + all weight repacks)
    preproc<<<PRE_GRID, 256>>>(src, Wq, Wk, Wv, Wo, W1, W2);

    // fused QKV projection (N=2304, occ 2): Q scaled, K, V -> [B,H,S,DK] fp16
    gemm_mma<4,128,2><<<dim3(3*DD/128, MROWS/128), 256, GP<128>::SMEM>>>(
        srch, wqkv, bq, bk, (float*)bv, nullptr, MROWS, 3*DD, DD);

    // flash attention -> ctx fp16 [B,S,H*DK]
    attn_mma<<<dim3(SS/128, HH, BB), 256, ATT_SMEM>>>(q1, k1, v1, ctxh);

    // out projection (split-K 2) -> partials ; LN1(p0+p1+src) -> x fp32 + fp16
    gemm_mma<5,64,2><<<dim3(DD/64, MROWS/128, 2), 256, GP<64>::SMEM>>>(
        ctxh, wo, bo, nullptr, pp0, nullptr, MROWS, DD, DD);
    ln_k<1><<<MROWS, 256>>>(pp0, pp0 + (size_t)MROWS*DD, src, ln1w, ln1b, px, xh);

    // FF1 (relu -> fp16)
    gemm_mma<2,64,2><<<dim3(DFF/64, MROWS/128), 256, GP<64>::SMEM>>>(
        xh, w1, b1, nullptr, nullptr, ffh, MROWS, DFF, DD);

    // FF2 (split-K 2) -> partials ; LN2(p0+p1+x) -> out
    gemm_mma<5,64,2><<<dim3(DD/64, MROWS/128, 2), 256, GP<64>::SMEM>>>(
        ffh, w2, b2, nullptr, pp0, nullptr, MROWS, DD, DFF);
    ln_k<0><<<MROWS, 256>>>(pp0, pp0 + (size_t)MROWS*DD, px, ln2w, ln2b, out, nullptr);
}

// round 14
// speedup vs baseline: 8.6531x; 1.0829x over previous
#include <cuda_runtime.h>
#include <cuda_fp16.h>
#include <cstdint>
#include <math.h>

#define BB 2
#define SS 2048
#define DD 768
#define HH 12
#define DKK 64
#define DFF 3072
#define MROWS (BB*SS)   // 4096

// ======================= device scratch (no allocs allowed) ================
__device__ float g_p[4*MROWS*DD];   // split-K partials (bias folded into z=0)
__device__ float g_x[MROWS*DD];     // post-LN1 fp32 (residual for LN2)
// fp16 activations / weights
__device__ __half s_srch[MROWS*DD];
__device__ __half s_ctxh[MROWS*DD];
__device__ __half s_xh[MROWS*DD];
__device__ __half s_ffh[MROWS*DFF];
__device__ __half a_q[BB*HH*SS*DKK];
__device__ __half a_k[BB*HH*SS*DKK];
__device__ __half a_v[BB*HH*SS*DKK];
__device__ __half w_qkv[3*DD*DD];   // [2304, 768]
__device__ __half w_o[DD*DD];
__device__ __half w_1[DFF*DD];
__device__ __half w_2[DD*DFF];

// ======================= PTX helpers (stable ISA only) =====================
__device__ __forceinline__ uint32_t smem_u32(const void* p) {
    uint32_t a;
    asm("{ .reg .u64 t; cvta.to.shared.u64 t, %1; cvt.u32.u64 %0, t; }" : "=r"(a) : "l"(p));
    return a;
}
#define CP_ASYNC16(dst, src) \
    asm volatile("cp.async.cg.shared.global [%0], [%1], 16;" :: "r"(dst), "l"(src) : "memory")
#define CP_COMMIT() asm volatile("cp.async.commit_group;" ::: "memory")
#define CP_WAIT(n)  asm volatile("cp.async.wait_group %0;" :: "n"(n) : "memory")

__device__ __forceinline__ void ldm_x4(uint32_t* r, uint32_t addr) {
    asm volatile("ldmatrix.sync.aligned.m8n8.x4.shared.b16 {%0,%1,%2,%3}, [%4];"
        : "=r"(r[0]), "=r"(r[1]), "=r"(r[2]), "=r"(r[3]) : "r"(addr));
}
__device__ __forceinline__ void ldm_x4_t(uint32_t* r, uint32_t addr) {
    asm volatile("ldmatrix.sync.aligned.m8n8.x4.trans.shared.b16 {%0,%1,%2,%3}, [%4];"
        : "=r"(r[0]), "=r"(r[1]), "=r"(r[2]), "=r"(r[3]) : "r"(addr));
}
__device__ __forceinline__ void mma_f16(float* c, const uint32_t* a, const uint32_t* b) {
    asm volatile("mma.sync.aligned.m16n8k16.row.col.f32.f16.f16.f32 "
        "{%0,%1,%2,%3}, {%4,%5,%6,%7}, {%8,%9}, {%0,%1,%2,%3};"
        : "+f"(c[0]), "+f"(c[1]), "+f"(c[2]), "+f"(c[3])
        : "r"(a[0]), "r"(a[1]), "r"(a[2]), "r"(a[3]), "r"(b[0]), "r"(b[1]));
}
__device__ __forceinline__ float ex2(float x) {
    float y; asm("ex2.approx.ftz.f32 %0, %1;" : "=f"(y) : "f"(x)); return y;
}
__device__ __forceinline__ uint32_t pack_h2(float v0, float v1) {
    uint32_t r;
    asm("cvt.rn.f16x2.f32 %0, %1, %2;" : "=r"(r) : "f"(v1), "f"(v0));
    return r;
}

static __device__ __constant__ const float QSCALE_D = 0.125f * 1.44269504088896340736f;

// ======================= fused preprocessing kernel ========================
static constexpr int NCVT = (MROWS * DD) / 256;   // 12288
static constexpr int NQKV = 2 * 24 * 3 * HH;      // 1728
static constexpr int NWO  = 24 * 24;              // 576
static constexpr int NW1  = 96 * 24;              // 2304
static constexpr int NW2  = 24 * 96;              // 2304
static constexpr int PRE_GRID = NCVT + NQKV + NWO + NW1 + NW2;

__global__ void preproc(const float* __restrict__ src,
                        const float* __restrict__ Wq, const float* __restrict__ Wk,
                        const float* __restrict__ Wv, const float* __restrict__ Wo,
                        const float* __restrict__ W1, const float* __restrict__ W2)
{
    int blk = blockIdx.x;
    if (blk < NCVT) {
        int i = blk * 256 + threadIdx.x;
        s_srch[i] = __float2half_rn(src[i]);
        return;
    }
    blk -= NCVT;

    __shared__ float t[32][33];
    const int tx = threadIdx.x & 31, ty = threadIdx.x >> 5;

    const float* W; __half* o;
    int n0, k0, Kst;
    size_t rowoff = 0;
    if (blk < NQKV) {
        const int z = blk / 48, rem = blk % 48;
        const int sel = z / HH, h = z % HH;
        W = (sel == 0 ? Wq : sel == 1 ? Wk : Wv) + (size_t)h * DD * DKK;
        n0 = (rem % 2) * 32;
        k0 = (rem / 2) * 32;
        Kst = DD;
        o = w_qkv;
        rowoff = (size_t)sel * DD + h * DKK;
        #pragma unroll
        for (int r = 0; r < 4; r++)
            t[ty + 8 * r][tx] = W[(size_t)(k0 + ty + 8 * r) * DKK + n0 + tx];
        __syncthreads();
        #pragma unroll
        for (int r = 0; r < 4; r++)
            o[(rowoff + n0 + ty + 8 * r) * Kst + k0 + tx] =
                __float2half_rn(t[tx][ty + 8 * r]);
        return;
    }
    blk -= NQKV;
    int N;
    if (blk < NWO)      { W = Wo; o = w_o; N = DD;  Kst = DD;  n0 = (blk % 24) * 32; k0 = (blk / 24) * 32; }
    else if ((blk -= NWO) < NW1) { W = W1; o = w_1; N = DFF; Kst = DD;  n0 = (blk % 96) * 32; k0 = (blk / 96) * 32; }
    else                { blk -= NW1; W = W2; o = w_2; N = DD; Kst = DFF; n0 = (blk % 24) * 32; k0 = (blk / 24) * 32; }
    #pragma unroll
    for (int r = 0; r < 4; r++)
        t[ty + 8 * r][tx] = W[(size_t)(k0 + ty + 8 * r) * N + n0 + tx];
    __syncthreads();
    #pragma unroll
    for (int r = 0; r < 4; r++)
        o[(size_t)(n0 + ty + 8 * r) * Kst + k0 + tx] = __float2half_rn(t[tx][ty + 8 * r]);
}

// ======================= mma.sync fp16 GEMM ================================
// MODE 2: relu(acc+bias) -> fp16 row-major
// MODE 4: fused QKV epilogue: Q (scaled) / K / V fp16 [B,H,S,DK]
// MODE 5: split-K partial: acc (+bias iff z==0) -> fp32 at C + z*M*N
static constexpr int RS = 80;

template<int BN> struct GP {
    static constexpr int A_BYTES = 128 * RS;
    static constexpr int B_BYTES = BN * RS;
    static constexpr int STGB    = A_BYTES + B_BYTES;
    static constexpr int SMEM    = 2 * STGB;
    static constexpr int NTW     = BN / 16;
    static constexpr int NPB     = BN / 32;
    static constexpr int CPT     = (512 + 4 * BN) / 256;
};

template<int MODE, int BN, int MINB>
__global__ void __launch_bounds__(256, MINB) gemm_mma(
    const __half* __restrict__ A, const __half* __restrict__ B,
    const float* __restrict__ bias, const float* __restrict__ res,
    float* __restrict__ C, __half* __restrict__ Cs,
    int M, int N, int K)
{
    using P = GP<BN>;
    extern __shared__ char sb[];
    const uint32_t sbu = smem_u32(sb);
    const int tid  = threadIdx.x;
    const int wid  = tid >> 5;
    const int lane = tid & 31;
    const int wm   = wid & 3;
    const int wn   = wid >> 2;

    const int z      = (MODE == 5) ? blockIdx.z : 0;
    const int kLen   = (MODE == 5) ? K / ((int)gridDim.z) : K;
    const int kc0    = z * kLen;

    const int rowBase = blockIdx.y << 7;
    const int colBase = blockIdx.x * BN;
    const __half* gA = A + (size_t)rowBase * K;
    const __half* gB = B + (size_t)colBase * K;

    int ld_mat[P::CPT], ld_r[P::CPT], ld_q[P::CPT];
    #pragma unroll
    for (int i = 0; i < P::CPT; i++) {
        int slot = (i << 8) + tid;
        int mat, rem;
        if (slot < 512) { mat = 0; rem = slot; }
        else            { mat = 1; rem = slot - 512; }
        ld_mat[i] = mat; ld_r[i] = rem >> 2; ld_q[i] = rem & 3;
    }

    auto load_stage = [&](int kc, int buf) {
        const uint32_t base = sbu + buf * P::STGB;
        #pragma unroll
        for (int i = 0; i < P::CPT; i++) {
            const __half* src = (ld_mat[i] == 0 ? gA : gB)
                                + (size_t)ld_r[i] * K + kc + (ld_q[i] << 3);
            uint32_t dst = base + ld_mat[i] * P::A_BYTES + ld_r[i] * RS + (ld_q[i] << 4);
            CP_ASYNC16(dst, src);
        }
        CP_COMMIT();
    };

    float acc[2][P::NTW][4];
    #pragma unroll
    for (int mt = 0; mt < 2; mt++)
        #pragma unroll
        for (int nt = 0; nt < P::NTW; nt++)
            #pragma unroll
            for (int j = 0; j < 4; j++) acc[mt][nt][j] = 0.0f;

    const uint32_t aAddr = (uint32_t)((wm * 32 + (lane & 15)) * RS + (lane >> 4) * 16);
    const uint32_t bAddr = (uint32_t)((wn * (BN/2) + ((lane >> 4) << 3) + (lane & 7)) * RS
                                      + ((lane >> 3) & 1) * 16);

    const int nStages = kLen >> 5;
    load_stage(kc0, 0);

    for (int c = 0; c < nStages; c++) {
        if (c + 1 < nStages) load_stage(kc0 + ((c + 1) << 5), (c + 1) & 1);
        if (c + 1 < nStages) { CP_WAIT(1); } else { CP_WAIT(0); }
        __syncthreads();

        const uint32_t base = sbu + (c & 1) * P::STGB;
        #pragma unroll
        for (int ks = 0; ks < 2; ks++) {
            const uint32_t ko = ks * 32;
            uint32_t bf[P::NTW*2];
            #pragma unroll
            for (int np = 0; np < P::NPB; np++)
                ldm_x4(bf + np * 4, base + P::A_BYTES + bAddr + np * 16 * RS + ko);
            #pragma unroll
            for (int mt = 0; mt < 2; mt++) {
                uint32_t ah[4];
                ldm_x4(ah, base + aAddr + mt * 16 * RS + ko);
                #pragma unroll
                for (int nt = 0; nt < P::NTW; nt++)
                    mma_f16(acc[mt][nt], ah, bf + nt * 2);
            }
        }
        __syncthreads();
    }

    // ---------------- epilogue ----------------
    const int g  = lane >> 2;
    const int tc = (lane & 3) << 1;

    #pragma unroll
    for (int mt = 0; mt < 2; mt++) {
        #pragma unroll
        for (int half_i = 0; half_i < 2; half_i++) {
            const int orow = rowBase + wm * 32 + mt * 16 + g + half_i * 8;
            #pragma unroll
            for (int nt = 0; nt < P::NTW; nt++) {
                const int col = colBase + wn * (BN/2) + nt * 8 + tc;
                float a0 = acc[mt][nt][half_i * 2 + 0];
                float a1 = acc[mt][nt][half_i * 2 + 1];
                if (MODE == 4) {
                    const int sel = col / DD;
                    const int lc  = col - sel * DD;
                    const float* bptr = sel == 0 ? bias : sel == 1 ? res : (const float*)C;
                    float v0 = a0 + bptr[lc];
                    float v1 = a1 + bptr[lc + 1];
                    const int b = orow >> 11, s = orow & 2047;
                    const int h = lc >> 6, dk = lc & 63;
                    size_t off = (((size_t)b * HH + h) * SS + s) * DKK + dk;
                    if (sel == 0) { v0 *= QSCALE_D; v1 *= QSCALE_D; }
                    __half* dst = sel == 0 ? a_q : sel == 1 ? a_k : a_v;
                    *(uint32_t*)(dst + off) = pack_h2(v0, v1);
                } else if (MODE == 5) {
                    float b0 = (z == 0) ? bias[col] : 0.0f;
                    float b1 = (z == 0) ? bias[col + 1] : 0.0f;
                    *(float2*)(C + (size_t)z * M * N + (size_t)orow * N + col)
                        = make_float2(a0 + b0, a1 + b1);
                } else {
                    float v0 = fmaxf(a0 + bias[col], 0.0f);
                    float v1 = fmaxf(a1 + bias[col + 1], 0.0f);
                    *(uint32_t*)(Cs + (size_t)orow * N + col) = pack_h2(v0, v1);
                }
            }
        }
    }
}

// ======================= mma.sync flash attention (fp16) ===================
static constexpr int ATT_RS  = 144;
static constexpr int ATT_BUF = 64 * ATT_RS;
static constexpr int ATT_STG = 2 * ATT_BUF;   // 18432 (K,V)
static constexpr int ATT_SMEM = 2 * ATT_STG;  // 36864

__global__ void __launch_bounds__(256, 2) attn_mma(
    const __half* __restrict__ Q, const __half* __restrict__ K,
    const __half* __restrict__ V, __half* __restrict__ Cs)
{
    extern __shared__ char sm[];
    const uint32_t sbu = smem_u32(sm);
    const int qt = blockIdx.x, h = blockIdx.y, b = blockIdx.z;
    const int tid = threadIdx.x, wid = tid >> 5, lane = tid & 31;

    const size_t bh = (size_t)b * HH + h;
    const __half* gQ = Q + (bh * SS + qt * 128) * DKK;
    const __half* gK = K + bh * SS * DKK;
    const __half* gV = V + bh * SS * DKK;

    {
        #pragma unroll
        for (int i = 0; i < 4; i++) {
            int slot = (i << 8) + tid;
            int r = slot >> 3, c = slot & 7;
            CP_ASYNC16(sbu + r * ATT_RS + (c << 4), gQ + r * DKK + (c << 3));
        }
        CP_COMMIT(); CP_WAIT(0);
        __syncthreads();
    }
    uint32_t qf[4][4];
    {
        const uint32_t qa = sbu + (wid * 16 + (lane & 15)) * ATT_RS + ((lane >> 4) << 4);
        #pragma unroll
        for (int ks = 0; ks < 4; ks++) ldm_x4(qf[ks], qa + ks * 32);
    }
    __syncthreads();

    auto load_kv = [&](int t0, int buf) {
        const uint32_t base = sbu + buf * ATT_STG;
        #pragma unroll
        for (int i = 0; i < 4; i++) {
            int slot = (i << 8) + tid;
            int arr = slot >> 9;
            int rem = slot & 511;
            int r = rem >> 3, c = rem & 7;
            const __half* src = (arr == 0 ? gK : gV) + (size_t)(t0 + r) * DKK + (c << 3);
            CP_ASYNC16(base + arr * ATT_BUF + r * ATT_RS + (c << 4), src);
        }
        CP_COMMIT();
    };

    float ctx[8][4];
    #pragma unroll
    for (int nt = 0; nt < 8; nt++)
        #pragma unroll
        for (int j = 0; j < 4; j++) ctx[nt][j] = 0.0f;
    float m0 = -1e30f, m1 = -1e30f, l0 = 0.0f, l1 = 0.0f;

    const uint32_t kAddr = (uint32_t)(((((lane >> 4) << 3) | (lane & 7)) * ATT_RS)
                                      + ((lane >> 3) & 1) * 16);
    const uint32_t vAddr = (uint32_t)((lane & 15) * ATT_RS + ((lane >> 4) << 4));

    load_kv(0, 0);
    #pragma unroll 1
    for (int t = 0; t < SS / 64; t++) {
        if (t + 1 < SS / 64) { load_kv((t + 1) * 64, (t + 1) & 1); CP_WAIT(1); }
        else                 { CP_WAIT(0); }
        __syncthreads();
        const uint32_t base = sbu + (t & 1) * ATT_STG;

        float sa[8][4];
        #pragma unroll
        for (int nt = 0; nt < 8; nt++)
            #pragma unroll
            for (int j = 0; j < 4; j++) sa[nt][j] = 0.0f;
        #pragma unroll
        for (int ks = 0; ks < 4; ks++) {
            #pragma unroll
            for (int np = 0; np < 4; np++) {
                uint32_t kb[4];
                ldm_x4(kb, base + kAddr + np * 16 * ATT_RS + ks * 32);
                mma_f16(sa[2 * np],     qf[ks], kb);
                mma_f16(sa[2 * np + 1], qf[ks], kb + 2);
            }
        }

        float rm0 = -1e30f, rm1 = -1e30f;
        #pragma unroll
        for (int nt = 0; nt < 8; nt++) {
            rm0 = fmaxf(rm0, fmaxf(sa[nt][0], sa[nt][1]));
            rm1 = fmaxf(rm1, fmaxf(sa[nt][2], sa[nt][3]));
        }
        rm0 = fmaxf(rm0, __shfl_xor_sync(0xFFFFFFFFu, rm0, 1));
        rm0 = fmaxf(rm0, __shfl_xor_sync(0xFFFFFFFFu, rm0, 2));
        rm1 = fmaxf(rm1, __shfl_xor_sync(0xFFFFFFFFu, rm1, 1));
        rm1 = fmaxf(rm1, __shfl_xor_sync(0xFFFFFFFFu, rm1, 2));
        const float nm0 = fmaxf(m0, rm0), nm1 = fmaxf(m1, rm1);
        const float c0 = ex2(m0 - nm0), c1 = ex2(m1 - nm1);
        l0 *= c0; l1 *= c1;
        #pragma unroll
        for (int nt = 0; nt < 8; nt++) {
            ctx[nt][0] *= c0; ctx[nt][1] *= c0;
            ctx[nt][2] *= c1; ctx[nt][3] *= c1;
        }
        float s0 = 0.0f, s1 = 0.0f;
        #pragma unroll
        for (int nt = 0; nt < 8; nt++) {
            float p0 = ex2(sa[nt][0] - nm0); sa[nt][0] = p0; s0 += p0;
            float p1 = ex2(sa[nt][1] - nm0); sa[nt][1] = p1; s0 += p1;
            float p2 = ex2(sa[nt][2] - nm1); sa[nt][2] = p2; s1 += p2;
            float p3 = ex2(sa[nt][3] - nm1); sa[nt][3] = p3; s1 += p3;
        }
        s0 += __shfl_xor_sync(0xFFFFFFFFu, s0, 1);
        s0 += __shfl_xor_sync(0xFFFFFFFFu, s0, 2);
        s1 += __shfl_xor_sync(0xFFFFFFFFu, s1, 1);
        s1 += __shfl_xor_sync(0xFFFFFFFFu, s1, 2);
        l0 += s0; l1 += s1; m0 = nm0; m1 = nm1;

        #pragma unroll
        for (int ks = 0; ks < 4; ks++) {
            uint32_t ph[4];
            ph[0] = pack_h2(sa[2 * ks][0],     sa[2 * ks][1]);
            ph[1] = pack_h2(sa[2 * ks][2],     sa[2 * ks][3]);
            ph[2] = pack_h2(sa[2 * ks + 1][0], sa[2 * ks + 1][1]);
            ph[3] = pack_h2(sa[2 * ks + 1][2], sa[2 * ks + 1][3]);
            const uint32_t vrow = vAddr + ks * 16 * ATT_RS;
            #pragma unroll
            for (int np = 0; np < 4; np++) {
                uint32_t vb[4];
                ldm_x4_t(vb, base + ATT_BUF + vrow + np * 32);
                mma_f16(ctx[2 * np],     ph, vb);
                mma_f16(ctx[2 * np + 1], ph, vb + 2);
            }
        }
        __syncthreads();
    }

    const float i0 = 1.0f / l0, i1 = 1.0f / l1;
    const int g = lane >> 2, tc2 = (lane & 3) << 1;
    const int r0 = qt * 128 + wid * 16 + g;
    const size_t base0 = ((size_t)b * SS + r0) * DD + h * DKK;
    #pragma unroll
    for (int nt = 0; nt < 8; nt++) {
        const int col = nt * 8 + tc2;
        *(uint32_t*)(Cs + base0 + col) = pack_h2(ctx[nt][0] * i0, ctx[nt][1] * i0);
        *(uint32_t*)(Cs + base0 + (size_t)8 * DD + col) = pack_h2(ctx[nt][2] * i1, ctx[nt][3] * i1);
    }
}

// ======================= LayerNorm over (sum of NP partials + res) =========
template<int NP, int WB>
__global__ __launch_bounds__(256)
void ln_k(const float* __restrict__ parts, const float* __restrict__ res,
          const float* __restrict__ w, const float* __restrict__ bsh,
          float* __restrict__ out, __half* __restrict__ oh)
{
    const size_t row = blockIdx.x;
    float xv[3];
    float s = 0.0f, s2 = 0.0f;
    #pragma unroll
    for (int it = 0; it < 3; it++) {
        int i = threadIdx.x + it * 256;
        float v = res[row * DD + i];
        #pragma unroll
        for (int p = 0; p < NP; p++)
            v += parts[(size_t)p * MROWS * DD + row * DD + i];
        xv[it] = v; s += v; s2 += v * v;
    }
    #pragma unroll
    for (int o = 16; o > 0; o >>= 1) {
        s  += __shfl_xor_sync(0xFFFFFFFFu, s,  o);
        s2 += __shfl_xor_sync(0xFFFFFFFFu, s2, o);
    }
    __shared__ float ws[8], ws2[8];
    const int wid = threadIdx.x >> 5, lane = threadIdx.x & 31;
    if (lane == 0) { ws[wid] = s; ws2[wid] = s2; }
    __syncthreads();
    float ts = 0.0f, ts2 = 0.0f;
    #pragma unroll
    for (int i = 0; i < 8; i++) { ts += ws[i]; ts2 += ws2[i]; }
    const float mu   = ts  * (1.0f / DD);
    const float var  = ts2 * (1.0f / DD) - mu * mu;
    const float rstd = rsqrtf(var + 1e-5f);
    #pragma unroll
    for (int it = 0; it < 3; it++) {
        int i = threadIdx.x + it * 256;
        float r = (xv[it] - mu) * rstd * w[i] + bsh[i];
        if (out) out[row * DD + i] = r;
        if (WB) oh[row * DD + i] = __float2half_rn(r);
    }
}

// ======================= launch ============================================
template<typename T>
static void* sym_addr(T& sym) {
    void* p = nullptr;
    cudaGetSymbolAddress(&p, sym);
    return p;
}

extern "C" void kernel_launch(void* const* d_in, const int* in_sizes, int n_in,
                              void* d_out, int out_size)
{
    const float* src  = (const float*)d_in[0];
    const float* Wq   = (const float*)d_in[1];
    const float* bq   = (const float*)d_in[2];
    const float* Wk   = (const float*)d_in[3];
    const float* bk   = (const float*)d_in[4];
    const float* Wv   = (const float*)d_in[5];
    const float* bv   = (const float*)d_in[6];
    const float* Wo   = (const float*)d_in[7];
    const float* bo   = (const float*)d_in[8];
    const float* ln1w = (const float*)d_in[9];
    const float* ln1b = (const float*)d_in[10];
    const float* W1   = (const float*)d_in[11];
    const float* b1   = (const float*)d_in[12];
    const float* W2   = (const float*)d_in[13];
    const float* b2   = (const float*)d_in[14];
    const float* ln2w = (const float*)d_in[15];
    const float* ln2b = (const float*)d_in[16];
    float* out = (float*)d_out;

    float* pp   = (float*)sym_addr(g_p);
    float* px   = (float*)sym_addr(g_x);

    __half* ctxh = (__half*)sym_addr(s_ctxh);
    __half* srch = (__half*)sym_addr(s_srch);
    __half* xh   = (__half*)sym_addr(s_xh);
    __half* ffh  = (__half*)sym_addr(s_ffh);
    __half* q1   = (__half*)sym_addr(a_q);
    __half* k1   = (__half*)sym_addr(a_k);
    __half* v1   = (__half*)sym_addr(a_v);
    __half* wqkv = (__half*)sym_addr(w_qkv);
    __half* wo   = (__half*)sym_addr(w_o);
    __half* w1   = (__half*)sym_addr(w_1);
    __half* w2   = (__half*)sym_addr(w_2);

    cudaFuncSetAttribute((const void*)gemm_mma<4,128,2>, cudaFuncAttributeMaxDynamicSharedMemorySize, GP<128>::SMEM);
    cudaFuncSetAttribute((const void*)gemm_mma<2,128,2>, cudaFuncAttributeMaxDynamicSharedMemorySize, GP<128>::SMEM);
    cudaFuncSetAttribute((const void*)gemm_mma<5,128,2>, cudaFuncAttributeMaxDynamicSharedMemorySize, GP<128>::SMEM);
    cudaFuncSetAttribute((const void*)attn_mma,          cudaFuncAttributeMaxDynamicSharedMemorySize, ATT_SMEM);

    // fused preprocessing (cvt + all weight repacks)
    preproc<<<PRE_GRID, 256>>>(src, Wq, Wk, Wv, Wo, W1, W2);

    // fused QKV projection (N=2304, occ 2)
    gemm_mma<4,128,2><<<dim3(3*DD/128, MROWS/128), 256, GP<128>::SMEM>>>(
        srch, wqkv, bq, bk, (float*)bv, nullptr, MROWS, 3*DD, DD);

    // flash attention -> ctx fp16 [B,S,H*DK]
    attn_mma<<<dim3(SS/128, HH, BB), 256, ATT_SMEM>>>(q1, k1, v1, ctxh);

    // out projection (BN=128, split-K 4) -> partials ; LN1(sum + src) -> x
    gemm_mma<5,128,2><<<dim3(DD/128, MROWS/128, 4), 256, GP<128>::SMEM>>>(
        ctxh, wo, bo, nullptr, pp, nullptr, MROWS, DD, DD);
    ln_k<4,1><<<MROWS, 256>>>(pp, src, ln1w, ln1b, px, xh);

    // FF1 (BN=128, relu -> fp16)
    gemm_mma<2,128,2><<<dim3(DFF/128, MROWS/128), 256, GP<128>::SMEM>>>(
        xh, w1, b1, nullptr, nullptr, ffh, MROWS, DFF, DD);

    // FF2 (BN=128, split-K 4) -> partials ; LN2(sum + x) -> out
    gemm_mma<5,128,2><<<dim3(DD/128, MROWS/128, 4), 256, GP<128>::SMEM>>>(
        ffh, w2, b2, nullptr, pp, nullptr, MROWS, DD, DFF);
    ln_k<4,0><<<MROWS, 256>>>(pp, px, ln2w, ln2b, out, nullptr);
}